// round 2
// baseline (speedup 1.0000x reference)
#include <cuda_runtime.h>
#include <math.h>
#include <stdint.h>

// ---------------- problem constants ----------------
#define T_    4
#define V_    8
#define TVC   32           // T*V cameras
#define HP    64
#define WP    64
#define C_    64           // feature channels
#define KSEL  4            // TOPK
#define HID   256
#define TE    32           // TIME_EMB
#define VE    16           // VIEW_EMB
#define MAXM  50000
#define MAXTOK (MAXM*KSEL)

// ---------------- scratch (static device globals; no runtime alloc) ----------------
__device__ float g_P[TVC*12];          // per-camera 3x4 projection  P = K @ w2c[:3,:4]
__device__ float g_scal[4];            // W_img, H_img, su=WP/max(1,W), sv=HP/max(1,H)
__device__ float g_temb[T_*TE];        // time embedding table
__device__ int   g_selcam[MAXTOK];
__device__ float g_selu[MAXTOK];
__device__ float g_selv[MAXTOK];
__device__ float g_selz[MAXTOK];
__device__ float g_xin [(size_t)MAXTOK*96];
__device__ float g_h   [(size_t)MAXTOK*256];
__device__ float g_qkv [(size_t)MAXTOK*768];
__device__ float g_o   [(size_t)MAXTOK*256];
__device__ float g_proj[(size_t)MAXTOK*256];
__device__ float g_ff  [(size_t)MAXTOK*512];
__device__ float g_mean[(size_t)MAXM*256];

// ---------------- setup: camera inverses, projection matrices, time embeddings ----------------
__global__ void setup_kernel(const float* __restrict__ poses,
                             const float* __restrict__ intr,
                             const int*   __restrict__ time_ids,
                             int T)
{
    int n = threadIdx.x;
    if (n < TVC) {
        // Gauss-Jordan 4x4 inverse in double (partial pivoting)
        double a[4][8];
        for (int r = 0; r < 4; r++)
            for (int c = 0; c < 4; c++) {
                a[r][c]   = (double)poses[n*16 + r*4 + c];
                a[r][4+c] = (r == c) ? 1.0 : 0.0;
            }
        for (int col = 0; col < 4; col++) {
            int piv = col;
            for (int r = col+1; r < 4; r++)
                if (fabs(a[r][col]) > fabs(a[piv][col])) piv = r;
            if (piv != col)
                for (int c = 0; c < 8; c++) { double t = a[col][c]; a[col][c] = a[piv][c]; a[piv][c] = t; }
            double dv = a[col][col];
            for (int c = 0; c < 8; c++) a[col][c] /= dv;
            for (int r = 0; r < 4; r++) if (r != col) {
                double f = a[r][col];
                for (int c = 0; c < 8; c++) a[r][c] -= f * a[col][c];
            }
        }
        double Km[9];
        for (int i = 0; i < 9; i++) Km[i] = (double)intr[n*9 + i];
        for (int r = 0; r < 3; r++)
            for (int c = 0; c < 4; c++) {
                double s = 0.0;
                for (int j = 0; j < 3; j++) s += Km[r*3 + j] * a[j][4 + c];
                g_P[n*12 + r*4 + c] = (float)s;
            }
    }
    if (n == 0) {
        float cx = intr[2], cy = intr[5];
        float W = 2.0f*cx, H = 2.0f*cy;
        g_scal[0] = W; g_scal[1] = H;
        g_scal[2] = (float)WP / fmaxf(1.0f, W);
        g_scal[3] = (float)HP / fmaxf(1.0f, H);
        int tmin = time_ids[0], tmax = time_ids[0];
        for (int t = 1; t < T; t++) {
            int v = time_ids[t];
            if (v < tmin) tmin = v;
            if (v > tmax) tmax = v;
        }
        if (tmax < tmin + 1) tmax = tmin + 1;
        for (int t = 0; t < T; t++) {
            double tn = (double)(time_ids[t] - tmin) / (double)(tmax - tmin);
            for (int i = 0; i < TE/2; i++) {
                double f  = exp(8.0 * (double)i / (double)(TE/2 - 1));
                double ph = tn * f;
                g_temb[t*TE + i]          = (float)sin(ph);
                g_temb[t*TE + TE/2 + i]   = (float)cos(ph);
            }
        }
    }
}

// ---------------- per-point projection + stable top-4 ----------------
__global__ __launch_bounds__(128)
void proj_topk_kernel(const float* __restrict__ xyz, int M)
{
    int m = blockIdx.x * blockDim.x + threadIdx.x;
    if (m >= M) return;
    float X = xyz[3*m+0], Y = xyz[3*m+1], Z = xyz[3*m+2];
    float W = g_scal[0], H = g_scal[1];

    float bs[KSEL] = {-1.f,-1.f,-1.f,-1.f};
    int   bi[KSEL] = {1000,1000,1000,1000};
    float bu[KSEL], bv[KSEL], bz[KSEL];
    #pragma unroll
    for (int q = 0; q < KSEL; q++) { bu[q]=0; bv[q]=0; bz[q]=0; }

    for (int cam = 0; cam < TVC; cam++) {
        const float* P = g_P + cam*12;
        float uw = P[0]*X + P[1]*Y + P[2] *Z + P[3];
        float vw = P[4]*X + P[5]*Y + P[6] *Z + P[7];
        float z  = P[8]*X + P[9]*Y + P[10]*Z + P[11];
        float wd = fmaxf(z, 1e-6f);
        float u = uw / wd, v = vw / wd;
        bool vis = (z > 1e-4f) && (u >= 0.f) && (u < W) && (v >= 0.f) && (v < H);
        float score = vis ? (1.0f / (fmaxf(z, 0.1f) + 1e-6f)) : 0.0f;
        // stable insertion: descending score, ties -> lower camera index first
        #pragma unroll
        for (int slot = 0; slot < KSEL; slot++) {
            bool better = (score > bs[slot]) || (score == bs[slot] && cam < bi[slot]);
            if (better) {
                for (int q = KSEL-1; q > slot; q--) {
                    bs[q]=bs[q-1]; bi[q]=bi[q-1]; bu[q]=bu[q-1]; bv[q]=bv[q-1]; bz[q]=bz[q-1];
                }
                bs[slot]=score; bi[slot]=cam; bu[slot]=u; bv[slot]=v; bz[slot]=z;
                break;
            }
        }
    }
    #pragma unroll
    for (int q = 0; q < KSEL; q++) {
        int t = m*KSEL + q;
        g_selcam[t] = bi[q];
        g_selu[t] = bu[q]; g_selv[t] = bv[q]; g_selz[t] = bz[q];
    }
}

// ---------------- bilinear gather + positional features -> xin[Ntok,96] ----------------
__global__ __launch_bounds__(256)
void gather_kernel(const float* __restrict__ feat,
                   const float* __restrict__ view_emb,
                   const float* __restrict__ pos_w,
                   const float* __restrict__ pos_b,
                   int Ntok)
{
    int wid  = (blockIdx.x * blockDim.x + threadIdx.x) >> 5;
    int lane = threadIdx.x & 31;
    if (wid >= Ntok) return;

    int   cam = g_selcam[wid];
    float u = g_selu[wid], v = g_selv[wid], z = g_selz[wid];
    float uf = u * g_scal[2], vf = v * g_scal[3];
    float x0f = floorf(uf), y0f = floorf(vf);
    float fx = uf - x0f, fy = vf - y0f;
    int x0 = (int)x0f, y0 = (int)y0f;
    float w00 = (1.f-fx)*(1.f-fy);
    float w01 = fx*(1.f-fy);
    float w10 = (1.f-fx)*fy;
    float w11 = fx*fy;
    float zm  = (z > 1e-4f) ? 1.0f : 0.0f;

    float s0 = 0.f, s1 = 0.f;
    #pragma unroll
    for (int dy = 0; dy < 2; dy++) {
        #pragma unroll
        for (int dx = 0; dx < 2; dx++) {
            int xi = x0 + dx, yi = y0 + dy;
            bool val = (xi >= 0) && (xi < WP) && (yi >= 0) && (yi < HP);
            int xc = min(max(xi, 0), WP-1);
            int yc = min(max(yi, 0), HP-1);
            size_t base = (((size_t)cam*HP + yc)*WP + xc) * C_;
            float w = dy ? (dx ? w11 : w10) : (dx ? w01 : w00);
            float f0 = feat[base + lane];
            float f1 = feat[base + lane + 32];
            if (!val) { f0 = 0.f; f1 = 0.f; }
            s0 += w * f0;
            s1 += w * f1;
        }
    }
    size_t xb = (size_t)wid * 96;
    g_xin[xb + lane]      = s0 * zm;
    g_xin[xb + 32 + lane] = s1 * zm;

    // pos32[lane] = pos_b + concat(t_emb, view_emb) @ pos_w
    int tdx = cam / V_;
    int vdx = cam % V_;
    int vmin = min(vdx, 63);
    float acc = pos_b[lane];
    #pragma unroll
    for (int i = 0; i < TE; i++)
        acc += g_temb[tdx*TE + i] * pos_w[i*32 + lane];
    #pragma unroll
    for (int i = 0; i < VE; i++)
        acc += view_emb[vmin*VE + i] * pos_w[(TE + i)*32 + lane];
    g_xin[xb + 64 + lane] = acc;
}

// ---------------- tiled fp32 GEMM: C[N,Nout] = A[N,Kd] @ B[Kd,Nout] + bias (opt relu) ----------------
// BM=BN=128, BK=16, 256 threads, 8x8 microtile. Kd must be a multiple of 16 (96/256/512 all are).
__global__ __launch_bounds__(256)
void gemm_bias_kernel(const float* __restrict__ A, const float* __restrict__ B,
                      const float* __restrict__ bias, float* __restrict__ C,
                      int N, int Kd, int Nout, int relu)
{
    __shared__ float As[16][128];
    __shared__ float Bs[16][128];
    int bm = blockIdx.y * 128;
    int bn = blockIdx.x * 128;
    int tid = threadIdx.x;
    int tx = tid & 15, ty = tid >> 4;

    float acc[8][8];
    #pragma unroll
    for (int i = 0; i < 8; i++)
        #pragma unroll
        for (int j = 0; j < 8; j++) acc[i][j] = 0.f;

    for (int k0 = 0; k0 < Kd; k0 += 16) {
        // load A tile 128x16 (transposed into As[k][m])
        #pragma unroll
        for (int i = 0; i < 2; i++) {
            int id  = tid + i*256;
            int row = id >> 2;
            int cg  = (id & 3) * 4;
            float4 a = make_float4(0.f,0.f,0.f,0.f);
            int gr = bm + row;
            if (gr < N) a = *(const float4*)(A + (size_t)gr*Kd + k0 + cg);
            As[cg+0][row] = a.x; As[cg+1][row] = a.y;
            As[cg+2][row] = a.z; As[cg+3][row] = a.w;
        }
        // load B tile 16x128
        #pragma unroll
        for (int i = 0; i < 2; i++) {
            int id = tid + i*256;
            int kr = id >> 5;
            int cg = (id & 31) * 4;
            int gc = bn + cg;
            float4 b = make_float4(0.f,0.f,0.f,0.f);
            if (gc < Nout) b = *(const float4*)(B + (size_t)(k0+kr)*Nout + gc);
            *(float4*)&Bs[kr][cg] = b;
        }
        __syncthreads();
        #pragma unroll
        for (int kk = 0; kk < 16; kk++) {
            float a[8], b[8];
            *(float4*)&a[0] = *(float4*)&As[kk][ty*8];
            *(float4*)&a[4] = *(float4*)&As[kk][ty*8+4];
            *(float4*)&b[0] = *(float4*)&Bs[kk][tx*8];
            *(float4*)&b[4] = *(float4*)&Bs[kk][tx*8+4];
            #pragma unroll
            for (int i = 0; i < 8; i++)
                #pragma unroll
                for (int j = 0; j < 8; j++)
                    acc[i][j] = fmaf(a[i], b[j], acc[i][j]);
        }
        __syncthreads();
    }
    // epilogue
    #pragma unroll
    for (int i = 0; i < 8; i++) {
        int gr = bm + ty*8 + i;
        if (gr >= N) continue;
        #pragma unroll
        for (int jg = 0; jg < 2; jg++) {
            int gc = bn + tx*8 + jg*4;
            if (gc >= Nout) continue;
            float4 o;
            o.x = acc[i][jg*4+0] + bias[gc+0];
            o.y = acc[i][jg*4+1] + bias[gc+1];
            o.z = acc[i][jg*4+2] + bias[gc+2];
            o.w = acc[i][jg*4+3] + bias[gc+3];
            if (relu) {
                o.x = fmaxf(o.x, 0.f); o.y = fmaxf(o.y, 0.f);
                o.z = fmaxf(o.z, 0.f); o.w = fmaxf(o.w, 0.f);
            }
            *(float4*)(C + (size_t)gr*Nout + gc) = o;
        }
    }
}

// ---------------- attention over 4 tokens, 8 heads, Dh=32: one block per point, one warp per head ----------------
__global__ __launch_bounds__(256)
void attn_kernel(int M)
{
    int m = blockIdx.x;
    if (m >= M) return;
    int h = threadIdx.x >> 5;
    int lane = threadIdx.x & 31;
    const float* qkv = g_qkv + (size_t)m * KSEL * 768;

    float q[4], k[4], v[4];
    #pragma unroll
    for (int j = 0; j < 4; j++) {
        q[j] = qkv[(size_t)j*768 +        h*32 + lane];
        k[j] = qkv[(size_t)j*768 + 256  + h*32 + lane];
        v[j] = qkv[(size_t)j*768 + 512  + h*32 + lane];
    }
    float s[16];
    #pragma unroll
    for (int i = 0; i < 4; i++)
        #pragma unroll
        for (int j = 0; j < 4; j++)
            s[i*4+j] = q[i] * k[j];
    #pragma unroll
    for (int off = 16; off > 0; off >>= 1)
        #pragma unroll
        for (int x = 0; x < 16; x++)
            s[x] += __shfl_xor_sync(0xFFFFFFFFu, s[x], off);

    const float scale = 0.17677669529663687f;  // 1/sqrt(32)
    float a[16];
    #pragma unroll
    for (int i = 0; i < 4; i++) {
        float s0 = s[i*4+0]*scale, s1 = s[i*4+1]*scale;
        float s2 = s[i*4+2]*scale, s3 = s[i*4+3]*scale;
        float mx = fmaxf(fmaxf(s0, s1), fmaxf(s2, s3));
        float e0 = expf(s0-mx), e1 = expf(s1-mx), e2 = expf(s2-mx), e3 = expf(s3-mx);
        float r = 1.0f / (e0+e1+e2+e3);
        a[i*4+0] = e0*r; a[i*4+1] = e1*r; a[i*4+2] = e2*r; a[i*4+3] = e3*r;
    }
    float* o = g_o + (size_t)m * KSEL * 256;
    #pragma unroll
    for (int i = 0; i < 4; i++) {
        float oi = a[i*4+0]*v[0] + a[i*4+1]*v[1] + a[i*4+2]*v[2] + a[i*4+3]*v[3];
        o[(size_t)i*256 + h*32 + lane] = oi;
    }
}

// ---------------- residual add + layernorm (in place on g_h) ----------------
__global__ __launch_bounds__(256)
void add_ln_kernel(float* __restrict__ h, const float* __restrict__ d,
                   const float* __restrict__ s, const float* __restrict__ b,
                   int Ntok)
{
    int row  = (blockIdx.x * blockDim.x + threadIdx.x) >> 5;
    int lane = threadIdx.x & 31;
    if (row >= Ntok) return;
    size_t base = (size_t)row*256 + lane*8;
    float x[8];
    float4 h0 = *(float4*)(h + base),     h1 = *(float4*)(h + base + 4);
    float4 d0 = *(const float4*)(d + base), d1 = *(const float4*)(d + base + 4);
    x[0]=h0.x+d0.x; x[1]=h0.y+d0.y; x[2]=h0.z+d0.z; x[3]=h0.w+d0.w;
    x[4]=h1.x+d1.x; x[5]=h1.y+d1.y; x[6]=h1.z+d1.z; x[7]=h1.w+d1.w;

    float sum = 0.f;
    #pragma unroll
    for (int j = 0; j < 8; j++) sum += x[j];
    #pragma unroll
    for (int off = 16; off > 0; off >>= 1) sum += __shfl_xor_sync(0xFFFFFFFFu, sum, off);
    float mu = sum * (1.0f/256.0f);

    float vs = 0.f;
    #pragma unroll
    for (int j = 0; j < 8; j++) { float t = x[j]-mu; vs += t*t; }
    #pragma unroll
    for (int off = 16; off > 0; off >>= 1) vs += __shfl_xor_sync(0xFFFFFFFFu, vs, off);
    float rinv = rsqrtf(vs * (1.0f/256.0f) + 1e-5f);

    float y[8];
    #pragma unroll
    for (int j = 0; j < 8; j++) {
        int c = lane*8 + j;
        y[j] = (x[j]-mu)*rinv*s[c] + b[c];
    }
    *(float4*)(h + base)     = make_float4(y[0],y[1],y[2],y[3]);
    *(float4*)(h + base + 4) = make_float4(y[4],y[5],y[6],y[7]);
}

// ---------------- mean over the 4 tokens ----------------
__global__ __launch_bounds__(256)
void mean_kernel(int M)
{
    int idx = blockIdx.x * blockDim.x + threadIdx.x;
    if (idx >= M*256) return;
    int m = idx >> 8, c = idx & 255;
    const float* hp = g_h + (size_t)m*4*256 + c;
    g_mean[idx] = 0.25f * (hp[0] + hp[256] + hp[512] + hp[768]);
}

// ---------------- host launch ----------------
extern "C" void kernel_launch(void* const* d_in, const int* in_sizes, int n_in,
                              void* d_out, int out_size)
{
    const float* xyz      = (const float*)d_in[0];
    const float* feat     = (const float*)d_in[1];
    const float* poses    = (const float*)d_in[2];
    const float* intr     = (const float*)d_in[3];
    const int*   time_ids = (const int*)  d_in[4];
    const float* view_emb = (const float*)d_in[5];
    const float* pos_w    = (const float*)d_in[6];
    const float* pos_b    = (const float*)d_in[7];
    const float* fp_w     = (const float*)d_in[8];
    const float* fp_b     = (const float*)d_in[9];
    const float* qkv_w    = (const float*)d_in[10];
    const float* qkv_b    = (const float*)d_in[11];
    const float* ao_w     = (const float*)d_in[12];
    const float* ao_b     = (const float*)d_in[13];
    const float* ln1_s    = (const float*)d_in[14];
    const float* ln1_b    = (const float*)d_in[15];
    const float* ff1_w    = (const float*)d_in[16];
    const float* ff1_b    = (const float*)d_in[17];
    const float* ff2_w    = (const float*)d_in[18];
    const float* ff2_b    = (const float*)d_in[19];
    const float* ln2_s    = (const float*)d_in[20];
    const float* ln2_b    = (const float*)d_in[21];
    const float* out_w    = (const float*)d_in[22];
    const float* out_b    = (const float*)d_in[23];

    int M    = in_sizes[0] / 3;
    int Ntok = M * KSEL;
    int T    = in_sizes[4];

    float *ph, *pqkv, *po, *pproj, *pff, *pxin, *pmean;
    cudaGetSymbolAddress((void**)&ph,    g_h);
    cudaGetSymbolAddress((void**)&pqkv,  g_qkv);
    cudaGetSymbolAddress((void**)&po,    g_o);
    cudaGetSymbolAddress((void**)&pproj, g_proj);
    cudaGetSymbolAddress((void**)&pff,   g_ff);
    cudaGetSymbolAddress((void**)&pxin,  g_xin);
    cudaGetSymbolAddress((void**)&pmean, g_mean);

    setup_kernel<<<1, 32>>>(poses, intr, time_ids, T);
    proj_topk_kernel<<<(M + 127)/128, 128>>>(xyz, M);
    gather_kernel<<<(Ntok*32 + 255)/256, 256>>>(feat, view_emb, pos_w, pos_b, Ntok);

    auto gemm = [&](const float* A, const float* B, const float* bias, float* C,
                    int N, int Kd, int Nout, int relu) {
        dim3 grid((Nout + 127)/128, (N + 127)/128);
        gemm_bias_kernel<<<grid, 256>>>(A, B, bias, C, N, Kd, Nout, relu);
    };

    // first projection: h = xin @ fp_w + fp_b
    gemm(pxin, fp_w, fp_b, ph, Ntok, 96, 256, 0);

    for (int l = 0; l < 2; l++) {
        gemm(ph, qkv_w + (size_t)l*256*768, qkv_b + l*768, pqkv, Ntok, 256, 768, 0);
        attn_kernel<<<M, 256>>>(M);
        gemm(po, ao_w + (size_t)l*256*256, ao_b + l*256, pproj, Ntok, 256, 256, 0);
        add_ln_kernel<<<(Ntok*32 + 255)/256, 256>>>(ph, pproj, ln1_s + l*256, ln1_b + l*256, Ntok);
        gemm(ph, ff1_w + (size_t)l*256*512, ff1_b + l*512, pff, Ntok, 256, 512, 1);
        gemm(pff, ff2_w + (size_t)l*512*256, ff2_b + l*256, pproj, Ntok, 512, 256, 0);
        add_ln_kernel<<<(Ntok*32 + 255)/256, 256>>>(ph, pproj, ln2_s + l*256, ln2_b + l*256, Ntok);
    }

    mean_kernel<<<(M*256 + 255)/256, 256>>>(M);
    gemm(pmean, out_w, out_b, (float*)d_out, M, 256, 64, 0);
}

// round 3
// speedup vs baseline: 1.3671x; 1.3671x over previous
#include <cuda_runtime.h>
#include <cuda_fp16.h>
#include <math.h>
#include <stdint.h>

// ---------------- problem constants ----------------
#define T_    4
#define V_    8
#define TVC   32           // T*V cameras
#define HP    64
#define WP    64
#define C_    64           // feature channels
#define KSEL  4            // TOPK
#define HID   256
#define TE    32           // TIME_EMB
#define VE    16           // VIEW_EMB
#define MAXM  50000
#define MAXTOK (MAXM*KSEL)

// ---------------- scratch (static device globals; no runtime alloc) ----------------
__device__ float g_P[TVC*12];          // per-camera 3x4 projection  P = K @ w2c[:3,:4]
__device__ float g_scal[4];            // W_img, H_img, su=WP/max(1,W), sv=HP/max(1,H)
__device__ float g_temb[T_*TE];        // time embedding table
__device__ int   g_selcam[MAXTOK];
__device__ float g_selu[MAXTOK];
__device__ float g_selv[MAXTOK];
__device__ float g_selz[MAXTOK];
__device__ float g_xin [(size_t)MAXTOK*96];
__device__ float g_h   [(size_t)MAXTOK*256];
__device__ float g_qkv [(size_t)MAXTOK*768];
__device__ float g_o   [(size_t)MAXTOK*256];
__device__ float g_proj[(size_t)MAXTOK*256];
__device__ float g_ff  [(size_t)MAXTOK*512];
__device__ float g_mean[(size_t)MAXM*256];

// ---------------- setup: camera inverses, projection matrices, time embeddings ----------------
__global__ void setup_kernel(const float* __restrict__ poses,
                             const float* __restrict__ intr,
                             const int*   __restrict__ time_ids,
                             int T)
{
    int n = threadIdx.x;
    if (n < TVC) {
        double a[4][8];
        for (int r = 0; r < 4; r++)
            for (int c = 0; c < 4; c++) {
                a[r][c]   = (double)poses[n*16 + r*4 + c];
                a[r][4+c] = (r == c) ? 1.0 : 0.0;
            }
        for (int col = 0; col < 4; col++) {
            int piv = col;
            for (int r = col+1; r < 4; r++)
                if (fabs(a[r][col]) > fabs(a[piv][col])) piv = r;
            if (piv != col)
                for (int c = 0; c < 8; c++) { double t = a[col][c]; a[col][c] = a[piv][c]; a[piv][c] = t; }
            double dv = a[col][col];
            for (int c = 0; c < 8; c++) a[col][c] /= dv;
            for (int r = 0; r < 4; r++) if (r != col) {
                double f = a[r][col];
                for (int c = 0; c < 8; c++) a[r][c] -= f * a[col][c];
            }
        }
        double Km[9];
        for (int i = 0; i < 9; i++) Km[i] = (double)intr[n*9 + i];
        for (int r = 0; r < 3; r++)
            for (int c = 0; c < 4; c++) {
                double s = 0.0;
                for (int j = 0; j < 3; j++) s += Km[r*3 + j] * a[j][4 + c];
                g_P[n*12 + r*4 + c] = (float)s;
            }
    }
    if (n == 0) {
        float cx = intr[2], cy = intr[5];
        float W = 2.0f*cx, H = 2.0f*cy;
        g_scal[0] = W; g_scal[1] = H;
        g_scal[2] = (float)WP / fmaxf(1.0f, W);
        g_scal[3] = (float)HP / fmaxf(1.0f, H);
        int tmin = time_ids[0], tmax = time_ids[0];
        for (int t = 1; t < T; t++) {
            int v = time_ids[t];
            if (v < tmin) tmin = v;
            if (v > tmax) tmax = v;
        }
        if (tmax < tmin + 1) tmax = tmin + 1;
        for (int t = 0; t < T; t++) {
            double tn = (double)(time_ids[t] - tmin) / (double)(tmax - tmin);
            for (int i = 0; i < TE/2; i++) {
                double f  = exp(8.0 * (double)i / (double)(TE/2 - 1));
                double ph = tn * f;
                g_temb[t*TE + i]          = (float)sin(ph);
                g_temb[t*TE + TE/2 + i]   = (float)cos(ph);
            }
        }
    }
}

// ---------------- per-point projection + stable top-4 ----------------
__global__ __launch_bounds__(128)
void proj_topk_kernel(const float* __restrict__ xyz, int M)
{
    int m = blockIdx.x * blockDim.x + threadIdx.x;
    if (m >= M) return;
    float X = xyz[3*m+0], Y = xyz[3*m+1], Z = xyz[3*m+2];
    float W = g_scal[0], H = g_scal[1];

    float bs[KSEL] = {-1.f,-1.f,-1.f,-1.f};
    int   bi[KSEL] = {1000,1000,1000,1000};
    float bu[KSEL], bv[KSEL], bz[KSEL];
    #pragma unroll
    for (int q = 0; q < KSEL; q++) { bu[q]=0; bv[q]=0; bz[q]=0; }

    for (int cam = 0; cam < TVC; cam++) {
        const float* P = g_P + cam*12;
        float uw = P[0]*X + P[1]*Y + P[2] *Z + P[3];
        float vw = P[4]*X + P[5]*Y + P[6] *Z + P[7];
        float z  = P[8]*X + P[9]*Y + P[10]*Z + P[11];
        float wd = fmaxf(z, 1e-6f);
        float u = uw / wd, v = vw / wd;
        bool vis = (z > 1e-4f) && (u >= 0.f) && (u < W) && (v >= 0.f) && (v < H);
        float score = vis ? (1.0f / (fmaxf(z, 0.1f) + 1e-6f)) : 0.0f;
        #pragma unroll
        for (int slot = 0; slot < KSEL; slot++) {
            bool better = (score > bs[slot]) || (score == bs[slot] && cam < bi[slot]);
            if (better) {
                for (int q = KSEL-1; q > slot; q--) {
                    bs[q]=bs[q-1]; bi[q]=bi[q-1]; bu[q]=bu[q-1]; bv[q]=bv[q-1]; bz[q]=bz[q-1];
                }
                bs[slot]=score; bi[slot]=cam; bu[slot]=u; bv[slot]=v; bz[slot]=z;
                break;
            }
        }
    }
    #pragma unroll
    for (int q = 0; q < KSEL; q++) {
        int t = m*KSEL + q;
        g_selcam[t] = bi[q];
        g_selu[t] = bu[q]; g_selv[t] = bv[q]; g_selz[t] = bz[q];
    }
}

// ---------------- bilinear gather + positional features -> xin[Ntok,96] ----------------
__global__ __launch_bounds__(256)
void gather_kernel(const float* __restrict__ feat,
                   const float* __restrict__ view_emb,
                   const float* __restrict__ pos_w,
                   const float* __restrict__ pos_b,
                   int Ntok)
{
    int wid  = (blockIdx.x * blockDim.x + threadIdx.x) >> 5;
    int lane = threadIdx.x & 31;
    if (wid >= Ntok) return;

    int   cam = g_selcam[wid];
    float u = g_selu[wid], v = g_selv[wid], z = g_selz[wid];
    float uf = u * g_scal[2], vf = v * g_scal[3];
    float x0f = floorf(uf), y0f = floorf(vf);
    float fx = uf - x0f, fy = vf - y0f;
    int x0 = (int)x0f, y0 = (int)y0f;
    float w00 = (1.f-fx)*(1.f-fy);
    float w01 = fx*(1.f-fy);
    float w10 = (1.f-fx)*fy;
    float w11 = fx*fy;
    float zm  = (z > 1e-4f) ? 1.0f : 0.0f;

    float s0 = 0.f, s1 = 0.f;
    #pragma unroll
    for (int dy = 0; dy < 2; dy++) {
        #pragma unroll
        for (int dx = 0; dx < 2; dx++) {
            int xi = x0 + dx, yi = y0 + dy;
            bool val = (xi >= 0) && (xi < WP) && (yi >= 0) && (yi < HP);
            int xc = min(max(xi, 0), WP-1);
            int yc = min(max(yi, 0), HP-1);
            size_t base = (((size_t)cam*HP + yc)*WP + xc) * C_;
            float w = dy ? (dx ? w11 : w10) : (dx ? w01 : w00);
            float f0 = feat[base + lane];
            float f1 = feat[base + lane + 32];
            if (!val) { f0 = 0.f; f1 = 0.f; }
            s0 += w * f0;
            s1 += w * f1;
        }
    }
    size_t xb = (size_t)wid * 96;
    g_xin[xb + lane]      = s0 * zm;
    g_xin[xb + 32 + lane] = s1 * zm;

    int tdx = cam / V_;
    int vdx = cam % V_;
    int vmin = min(vdx, 63);
    float acc = pos_b[lane];
    #pragma unroll
    for (int i = 0; i < TE; i++)
        acc += g_temb[tdx*TE + i] * pos_w[i*32 + lane];
    #pragma unroll
    for (int i = 0; i < VE; i++)
        acc += view_emb[vmin*VE + i] * pos_w[(TE + i)*32 + lane];
    g_xin[xb + 64 + lane] = acc;
}

// ---------------- tensor-core GEMM with fp16 hi/lo split (3-MMA compensation) ----------------
// C[N,Nout] = A[N,Kd] @ B[Kd,Nout] + bias (opt relu).  Kd % 32 == 0.
// BM=BN=128, BK=32, 256 threads = 8 warps (2x4), warp tile 64x32, mma m16n8k16.
#define SK 40   // padded halfs per smem row (20 words -> conflict-free frag loads)

__device__ __forceinline__ void mma16816(float* c, const uint32_t* a, uint32_t b0, uint32_t b1) {
    asm volatile(
        "mma.sync.aligned.m16n8k16.row.col.f32.f16.f16.f32 "
        "{%0,%1,%2,%3}, {%4,%5,%6,%7}, {%8,%9}, {%0,%1,%2,%3};\n"
        : "+f"(c[0]), "+f"(c[1]), "+f"(c[2]), "+f"(c[3])
        : "r"(a[0]), "r"(a[1]), "r"(a[2]), "r"(a[3]), "r"(b0), "r"(b1));
}

__global__ __launch_bounds__(256, 2)
void gemm_tc_kernel(const float* __restrict__ A, const float* __restrict__ B,
                    const float* __restrict__ bias, float* __restrict__ C,
                    int N, int Kd, int Nout, int relu)
{
    __shared__ __half As_hi[128*SK];
    __shared__ __half As_lo[128*SK];
    __shared__ __half Bs_hi[128*SK];
    __shared__ __half Bs_lo[128*SK];

    int bm = blockIdx.y * 128;
    int bn = blockIdx.x * 128;
    int tid = threadIdx.x;
    int wid = tid >> 5, lane = tid & 31;
    int g = lane >> 2, tc = lane & 3;
    int wm = (wid >> 2) * 64;       // warp m offset (0 or 64)
    int wn = (wid & 3) * 32;        // warp n offset (0,32,64,96)

    float acc[4][4][4];
    #pragma unroll
    for (int i = 0; i < 4; i++)
        #pragma unroll
        for (int j = 0; j < 4; j++)
            #pragma unroll
            for (int r = 0; r < 4; r++) acc[i][j][r] = 0.f;

    for (int k0 = 0; k0 < Kd; k0 += 32) {
        // ---- stage A tile 128x32 (fp32 -> hi/lo halves), layout As[m][k] ----
        #pragma unroll
        for (int r = 0; r < 4; r++) {
            int id = tid + r*256;            // 0..1023
            int m  = id >> 3;
            int kq = (id & 7) * 4;
            float4 a = make_float4(0.f,0.f,0.f,0.f);
            int gr = bm + m;
            if (gr < N) a = *(const float4*)(A + (size_t)gr*Kd + k0 + kq);
            float av[4] = {a.x, a.y, a.z, a.w};
            #pragma unroll
            for (int e = 0; e < 4; e++) {
                __half h = __float2half_rn(av[e]);
                As_hi[m*SK + kq + e] = h;
                As_lo[m*SK + kq + e] = __float2half_rn(av[e] - __half2float(h));
            }
        }
        // ---- stage B tile 32x128 transposed -> Bs[n][k] ----
        #pragma unroll
        for (int r = 0; r < 8; r++) {
            int id = tid + r*256;            // 0..2047 -> (kpair, n)
            int kp = id >> 7;                // 0..15
            int n  = id & 127;
            int gc = bn + n;
            float b0f = 0.f, b1f = 0.f;
            if (gc < Nout) {
                b0f = B[(size_t)(k0 + 2*kp    ) * Nout + gc];
                b1f = B[(size_t)(k0 + 2*kp + 1) * Nout + gc];
            }
            __half h0 = __float2half_rn(b0f);
            __half h1 = __float2half_rn(b1f);
            __half l0 = __float2half_rn(b0f - __half2float(h0));
            __half l1 = __float2half_rn(b1f - __half2float(h1));
            *(__half2*)&Bs_hi[n*SK + 2*kp] = __halves2half2(h0, h1);
            *(__half2*)&Bs_lo[n*SK + 2*kp] = __halves2half2(l0, l1);
        }
        __syncthreads();

        #pragma unroll
        for (int kb = 0; kb < 32; kb += 16) {
            uint32_t ah[4][4], al[4][4];
            #pragma unroll
            for (int i = 0; i < 4; i++) {
                int r0 = wm + i*16 + g;
                int c0 = kb + tc*2;
                ah[i][0] = *(const uint32_t*)&As_hi[(r0    )*SK + c0    ];
                ah[i][1] = *(const uint32_t*)&As_hi[(r0 + 8)*SK + c0    ];
                ah[i][2] = *(const uint32_t*)&As_hi[(r0    )*SK + c0 + 8];
                ah[i][3] = *(const uint32_t*)&As_hi[(r0 + 8)*SK + c0 + 8];
                al[i][0] = *(const uint32_t*)&As_lo[(r0    )*SK + c0    ];
                al[i][1] = *(const uint32_t*)&As_lo[(r0 + 8)*SK + c0    ];
                al[i][2] = *(const uint32_t*)&As_lo[(r0    )*SK + c0 + 8];
                al[i][3] = *(const uint32_t*)&As_lo[(r0 + 8)*SK + c0 + 8];
            }
            #pragma unroll
            for (int j = 0; j < 4; j++) {
                int n0 = wn + j*8 + g;
                int c0 = kb + tc*2;
                uint32_t bh0 = *(const uint32_t*)&Bs_hi[n0*SK + c0    ];
                uint32_t bh1 = *(const uint32_t*)&Bs_hi[n0*SK + c0 + 8];
                uint32_t bl0 = *(const uint32_t*)&Bs_lo[n0*SK + c0    ];
                uint32_t bl1 = *(const uint32_t*)&Bs_lo[n0*SK + c0 + 8];
                #pragma unroll
                for (int i = 0; i < 4; i++) {
                    mma16816(acc[i][j], ah[i], bh0, bh1);   // hi*hi
                    mma16816(acc[i][j], ah[i], bl0, bl1);   // hi*lo
                    mma16816(acc[i][j], al[i], bh0, bh1);   // lo*hi
                }
            }
        }
        __syncthreads();
    }

    // ---- epilogue: bias (+relu), guarded stores ----
    #pragma unroll
    for (int j = 0; j < 4; j++) {
        int col = bn + wn + j*8 + tc*2;
        if (col >= Nout) continue;
        float bx = bias[col], by = bias[col+1];
        #pragma unroll
        for (int i = 0; i < 4; i++) {
            int r0 = bm + wm + i*16 + g;
            int r1 = r0 + 8;
            float v0 = acc[i][j][0] + bx;
            float v1 = acc[i][j][1] + by;
            float v2 = acc[i][j][2] + bx;
            float v3 = acc[i][j][3] + by;
            if (relu) {
                v0 = fmaxf(v0, 0.f); v1 = fmaxf(v1, 0.f);
                v2 = fmaxf(v2, 0.f); v3 = fmaxf(v3, 0.f);
            }
            if (r0 < N) { C[(size_t)r0*Nout + col] = v0; C[(size_t)r0*Nout + col + 1] = v1; }
            if (r1 < N) { C[(size_t)r1*Nout + col] = v2; C[(size_t)r1*Nout + col + 1] = v3; }
        }
    }
}

// ---------------- attention over 4 tokens, 8 heads, Dh=32 ----------------
__global__ __launch_bounds__(256)
void attn_kernel(int M)
{
    int m = blockIdx.x;
    if (m >= M) return;
    int h = threadIdx.x >> 5;
    int lane = threadIdx.x & 31;
    const float* qkv = g_qkv + (size_t)m * KSEL * 768;

    float q[4], k[4], v[4];
    #pragma unroll
    for (int j = 0; j < 4; j++) {
        q[j] = qkv[(size_t)j*768 +        h*32 + lane];
        k[j] = qkv[(size_t)j*768 + 256  + h*32 + lane];
        v[j] = qkv[(size_t)j*768 + 512  + h*32 + lane];
    }
    float s[16];
    #pragma unroll
    for (int i = 0; i < 4; i++)
        #pragma unroll
        for (int j = 0; j < 4; j++)
            s[i*4+j] = q[i] * k[j];
    #pragma unroll
    for (int off = 16; off > 0; off >>= 1)
        #pragma unroll
        for (int x = 0; x < 16; x++)
            s[x] += __shfl_xor_sync(0xFFFFFFFFu, s[x], off);

    const float scale = 0.17677669529663687f;  // 1/sqrt(32)
    float a[16];
    #pragma unroll
    for (int i = 0; i < 4; i++) {
        float s0 = s[i*4+0]*scale, s1 = s[i*4+1]*scale;
        float s2 = s[i*4+2]*scale, s3 = s[i*4+3]*scale;
        float mx = fmaxf(fmaxf(s0, s1), fmaxf(s2, s3));
        float e0 = expf(s0-mx), e1 = expf(s1-mx), e2 = expf(s2-mx), e3 = expf(s3-mx);
        float r = 1.0f / (e0+e1+e2+e3);
        a[i*4+0] = e0*r; a[i*4+1] = e1*r; a[i*4+2] = e2*r; a[i*4+3] = e3*r;
    }
    float* o = g_o + (size_t)m * KSEL * 256;
    #pragma unroll
    for (int i = 0; i < 4; i++) {
        float oi = a[i*4+0]*v[0] + a[i*4+1]*v[1] + a[i*4+2]*v[2] + a[i*4+3]*v[3];
        o[(size_t)i*256 + h*32 + lane] = oi;
    }
}

// ---------------- residual add + layernorm (in place on g_h) ----------------
__global__ __launch_bounds__(256)
void add_ln_kernel(float* __restrict__ h, const float* __restrict__ d,
                   const float* __restrict__ s, const float* __restrict__ b,
                   int Ntok)
{
    int row  = (blockIdx.x * blockDim.x + threadIdx.x) >> 5;
    int lane = threadIdx.x & 31;
    if (row >= Ntok) return;
    size_t base = (size_t)row*256 + lane*8;
    float x[8];
    float4 h0 = *(float4*)(h + base),     h1 = *(float4*)(h + base + 4);
    float4 d0 = *(const float4*)(d + base), d1 = *(const float4*)(d + base + 4);
    x[0]=h0.x+d0.x; x[1]=h0.y+d0.y; x[2]=h0.z+d0.z; x[3]=h0.w+d0.w;
    x[4]=h1.x+d1.x; x[5]=h1.y+d1.y; x[6]=h1.z+d1.z; x[7]=h1.w+d1.w;

    float sum = 0.f;
    #pragma unroll
    for (int j = 0; j < 8; j++) sum += x[j];
    #pragma unroll
    for (int off = 16; off > 0; off >>= 1) sum += __shfl_xor_sync(0xFFFFFFFFu, sum, off);
    float mu = sum * (1.0f/256.0f);

    float vs = 0.f;
    #pragma unroll
    for (int j = 0; j < 8; j++) { float t = x[j]-mu; vs += t*t; }
    #pragma unroll
    for (int off = 16; off > 0; off >>= 1) vs += __shfl_xor_sync(0xFFFFFFFFu, vs, off);
    float rinv = rsqrtf(vs * (1.0f/256.0f) + 1e-5f);

    float y[8];
    #pragma unroll
    for (int j = 0; j < 8; j++) {
        int c = lane*8 + j;
        y[j] = (x[j]-mu)*rinv*s[c] + b[c];
    }
    *(float4*)(h + base)     = make_float4(y[0],y[1],y[2],y[3]);
    *(float4*)(h + base + 4) = make_float4(y[4],y[5],y[6],y[7]);
}

// ---------------- mean over the 4 tokens ----------------
__global__ __launch_bounds__(256)
void mean_kernel(int M)
{
    int idx = blockIdx.x * blockDim.x + threadIdx.x;
    if (idx >= M*256) return;
    int m = idx >> 8, c = idx & 255;
    const float* hp = g_h + (size_t)m*4*256 + c;
    g_mean[idx] = 0.25f * (hp[0] + hp[256] + hp[512] + hp[768]);
}

// ---------------- host launch ----------------
extern "C" void kernel_launch(void* const* d_in, const int* in_sizes, int n_in,
                              void* d_out, int out_size)
{
    const float* xyz      = (const float*)d_in[0];
    const float* feat     = (const float*)d_in[1];
    const float* poses    = (const float*)d_in[2];
    const float* intr     = (const float*)d_in[3];
    const int*   time_ids = (const int*)  d_in[4];
    const float* view_emb = (const float*)d_in[5];
    const float* pos_w    = (const float*)d_in[6];
    const float* pos_b    = (const float*)d_in[7];
    const float* fp_w     = (const float*)d_in[8];
    const float* fp_b     = (const float*)d_in[9];
    const float* qkv_w    = (const float*)d_in[10];
    const float* qkv_b    = (const float*)d_in[11];
    const float* ao_w     = (const float*)d_in[12];
    const float* ao_b     = (const float*)d_in[13];
    const float* ln1_s    = (const float*)d_in[14];
    const float* ln1_b    = (const float*)d_in[15];
    const float* ff1_w    = (const float*)d_in[16];
    const float* ff1_b    = (const float*)d_in[17];
    const float* ff2_w    = (const float*)d_in[18];
    const float* ff2_b    = (const float*)d_in[19];
    const float* ln2_s    = (const float*)d_in[20];
    const float* ln2_b    = (const float*)d_in[21];
    const float* out_w    = (const float*)d_in[22];
    const float* out_b    = (const float*)d_in[23];

    int M    = in_sizes[0] / 3;
    int Ntok = M * KSEL;
    int T    = in_sizes[4];

    float *ph, *pqkv, *po, *pproj, *pff, *pxin, *pmean;
    cudaGetSymbolAddress((void**)&ph,    g_h);
    cudaGetSymbolAddress((void**)&pqkv,  g_qkv);
    cudaGetSymbolAddress((void**)&po,    g_o);
    cudaGetSymbolAddress((void**)&pproj, g_proj);
    cudaGetSymbolAddress((void**)&pff,   g_ff);
    cudaGetSymbolAddress((void**)&pxin,  g_xin);
    cudaGetSymbolAddress((void**)&pmean, g_mean);

    setup_kernel<<<1, 32>>>(poses, intr, time_ids, T);
    proj_topk_kernel<<<(M + 127)/128, 128>>>(xyz, M);
    gather_kernel<<<(Ntok*32 + 255)/256, 256>>>(feat, view_emb, pos_w, pos_b, Ntok);

    auto gemm = [&](const float* A, const float* B, const float* bias, float* C,
                    int N, int Kd, int Nout, int relu) {
        dim3 grid((Nout + 127)/128, (N + 127)/128);
        gemm_tc_kernel<<<grid, 256>>>(A, B, bias, C, N, Kd, Nout, relu);
    };

    // first projection: h = xin @ fp_w + fp_b   (Kd=96, multiple of 32)
    gemm(pxin, fp_w, fp_b, ph, Ntok, 96, 256, 0);

    for (int l = 0; l < 2; l++) {
        gemm(ph, qkv_w + (size_t)l*256*768, qkv_b + l*768, pqkv, Ntok, 256, 768, 0);
        attn_kernel<<<M, 256>>>(M);
        gemm(po, ao_w + (size_t)l*256*256, ao_b + l*256, pproj, Ntok, 256, 256, 0);
        add_ln_kernel<<<(Ntok*32 + 255)/256, 256>>>(ph, pproj, ln1_s + l*256, ln1_b + l*256, Ntok);
        gemm(ph, ff1_w + (size_t)l*256*512, ff1_b + l*512, pff, Ntok, 256, 512, 1);
        gemm(pff, ff2_w + (size_t)l*512*256, ff2_b + l*256, pproj, Ntok, 512, 256, 0);
        add_ln_kernel<<<(Ntok*32 + 255)/256, 256>>>(ph, pproj, ln2_s + l*256, ln2_b + l*256, Ntok);
    }

    mean_kernel<<<(M*256 + 255)/256, 256>>>(M);
    gemm(pmean, out_w, out_b, (float*)d_out, M, 256, 64, 0);
}

// round 4
// speedup vs baseline: 1.8427x; 1.3479x over previous
#include <cuda_runtime.h>
#include <cuda_fp16.h>
#include <math.h>
#include <stdint.h>

// ---------------- problem constants ----------------
#define T_    4
#define V_    8
#define TVC   32
#define HP    64
#define WP    64
#define C_    64
#define KSEL  4
#define HID   256
#define TE    32
#define VE    16
#define MAXM  50000
#define MAXTOK (MAXM*KSEL)

// ---------------- scratch ----------------
__device__ float g_P[TVC*12];
__device__ float g_scal[4];
__device__ float g_temb[T_*TE];
__device__ int   g_selcam[MAXTOK];
__device__ float g_selu[MAXTOK];
__device__ float g_selv[MAXTOK];
__device__ float g_selz[MAXTOK];

// fp32 intermediates still needed
__device__ float g_h   [(size_t)MAXTOK*256];
__device__ float g_qkv [(size_t)MAXTOK*768];
__device__ float g_proj[(size_t)MAXTOK*256];

// half hi/lo activation buffers (GEMM A-operands)
__device__ __half g_xh[(size_t)MAXTOK*96],  g_xl[(size_t)MAXTOK*96];
__device__ __half g_hh[(size_t)MAXTOK*256], g_hl[(size_t)MAXTOK*256];
__device__ __half g_oh[(size_t)MAXTOK*256], g_ol[(size_t)MAXTOK*256];
__device__ __half g_fh[(size_t)MAXTOK*512], g_fl[(size_t)MAXTOK*512];
__device__ __half g_mh[(size_t)MAXM*256],   g_ml[(size_t)MAXM*256];

// preconverted transposed weights [Nout][Kd], hi/lo
#define WTOTAL 1089536
__device__ __half g_wh[WTOTAL], g_wl[WTOTAL];

// ---------------- setup ----------------
__global__ void setup_kernel(const float* __restrict__ poses,
                             const float* __restrict__ intr,
                             const int*   __restrict__ time_ids,
                             int T)
{
    int n = threadIdx.x;
    if (n < TVC) {
        double a[4][8];
        for (int r = 0; r < 4; r++)
            for (int c = 0; c < 4; c++) {
                a[r][c]   = (double)poses[n*16 + r*4 + c];
                a[r][4+c] = (r == c) ? 1.0 : 0.0;
            }
        for (int col = 0; col < 4; col++) {
            int piv = col;
            for (int r = col+1; r < 4; r++)
                if (fabs(a[r][col]) > fabs(a[piv][col])) piv = r;
            if (piv != col)
                for (int c = 0; c < 8; c++) { double t = a[col][c]; a[col][c] = a[piv][c]; a[piv][c] = t; }
            double dv = a[col][col];
            for (int c = 0; c < 8; c++) a[col][c] /= dv;
            for (int r = 0; r < 4; r++) if (r != col) {
                double f = a[r][col];
                for (int c = 0; c < 8; c++) a[r][c] -= f * a[col][c];
            }
        }
        double Km[9];
        for (int i = 0; i < 9; i++) Km[i] = (double)intr[n*9 + i];
        for (int r = 0; r < 3; r++)
            for (int c = 0; c < 4; c++) {
                double s = 0.0;
                for (int j = 0; j < 3; j++) s += Km[r*3 + j] * a[j][4 + c];
                g_P[n*12 + r*4 + c] = (float)s;
            }
    }
    if (n == 0) {
        float cx = intr[2], cy = intr[5];
        float W = 2.0f*cx, H = 2.0f*cy;
        g_scal[0] = W; g_scal[1] = H;
        g_scal[2] = (float)WP / fmaxf(1.0f, W);
        g_scal[3] = (float)HP / fmaxf(1.0f, H);
        int tmin = time_ids[0], tmax = time_ids[0];
        for (int t = 1; t < T; t++) {
            int v = time_ids[t];
            if (v < tmin) tmin = v;
            if (v > tmax) tmax = v;
        }
        if (tmax < tmin + 1) tmax = tmin + 1;
        for (int t = 0; t < T; t++) {
            double tn = (double)(time_ids[t] - tmin) / (double)(tmax - tmin);
            for (int i = 0; i < TE/2; i++) {
                double f  = exp(8.0 * (double)i / (double)(TE/2 - 1));
                double ph = tn * f;
                g_temb[t*TE + i]        = (float)sin(ph);
                g_temb[t*TE + TE/2 + i] = (float)cos(ph);
            }
        }
    }
}

// ---------------- weight convert + transpose: W[Kd][Nout] fp32 -> Wt[Nout][Kd] hi/lo ----------------
__global__ __launch_bounds__(256)
void wconv_kernel(const float* __restrict__ W, __half* __restrict__ Wh,
                  __half* __restrict__ Wl, int Kd, int Nout, int total)
{
    int i = blockIdx.x * blockDim.x + threadIdx.x;
    if (i >= total) return;
    int n = i / Kd, k = i - n*Kd;
    float w = W[(size_t)k*Nout + n];
    __half h = __float2half_rn(w);
    Wh[i] = h;
    Wl[i] = __float2half_rn(w - __half2float(h));
}

// ---------------- per-point projection + stable top-4 ----------------
__global__ __launch_bounds__(128)
void proj_topk_kernel(const float* __restrict__ xyz, int M)
{
    int m = blockIdx.x * blockDim.x + threadIdx.x;
    if (m >= M) return;
    float X = xyz[3*m+0], Y = xyz[3*m+1], Z = xyz[3*m+2];
    float W = g_scal[0], H = g_scal[1];

    float bs[KSEL] = {-1.f,-1.f,-1.f,-1.f};
    int   bi[KSEL] = {1000,1000,1000,1000};
    float bu[KSEL], bv[KSEL], bz[KSEL];
    #pragma unroll
    for (int q = 0; q < KSEL; q++) { bu[q]=0; bv[q]=0; bz[q]=0; }

    for (int cam = 0; cam < TVC; cam++) {
        const float* P = g_P + cam*12;
        float uw = P[0]*X + P[1]*Y + P[2] *Z + P[3];
        float vw = P[4]*X + P[5]*Y + P[6] *Z + P[7];
        float z  = P[8]*X + P[9]*Y + P[10]*Z + P[11];
        float wd = fmaxf(z, 1e-6f);
        float u = uw / wd, v = vw / wd;
        bool vis = (z > 1e-4f) && (u >= 0.f) && (u < W) && (v >= 0.f) && (v < H);
        float score = vis ? (1.0f / (fmaxf(z, 0.1f) + 1e-6f)) : 0.0f;
        #pragma unroll
        for (int slot = 0; slot < KSEL; slot++) {
            bool better = (score > bs[slot]) || (score == bs[slot] && cam < bi[slot]);
            if (better) {
                for (int q = KSEL-1; q > slot; q--) {
                    bs[q]=bs[q-1]; bi[q]=bi[q-1]; bu[q]=bu[q-1]; bv[q]=bv[q-1]; bz[q]=bz[q-1];
                }
                bs[slot]=score; bi[slot]=cam; bu[slot]=u; bv[slot]=v; bz[slot]=z;
                break;
            }
        }
    }
    #pragma unroll
    for (int q = 0; q < KSEL; q++) {
        int t = m*KSEL + q;
        g_selcam[t] = bi[q];
        g_selu[t] = bu[q]; g_selv[t] = bv[q]; g_selz[t] = bz[q];
    }
}

__device__ __forceinline__ void split_store(__half* hp, __half* lp, size_t idx, float v) {
    __half h = __float2half_rn(v);
    hp[idx] = h;
    lp[idx] = __float2half_rn(v - __half2float(h));
}

// ---------------- bilinear gather + pos feats -> xin hi/lo [Ntok,96] ----------------
__global__ __launch_bounds__(256)
void gather_kernel(const float* __restrict__ feat,
                   const float* __restrict__ view_emb,
                   const float* __restrict__ pos_w,
                   const float* __restrict__ pos_b,
                   int Ntok)
{
    int wid  = (blockIdx.x * blockDim.x + threadIdx.x) >> 5;
    int lane = threadIdx.x & 31;
    if (wid >= Ntok) return;

    int   cam = g_selcam[wid];
    float u = g_selu[wid], v = g_selv[wid], z = g_selz[wid];
    float uf = u * g_scal[2], vf = v * g_scal[3];
    float x0f = floorf(uf), y0f = floorf(vf);
    float fx = uf - x0f, fy = vf - y0f;
    int x0 = (int)x0f, y0 = (int)y0f;
    float w00 = (1.f-fx)*(1.f-fy);
    float w01 = fx*(1.f-fy);
    float w10 = (1.f-fx)*fy;
    float w11 = fx*fy;
    float zm  = (z > 1e-4f) ? 1.0f : 0.0f;

    float s0 = 0.f, s1 = 0.f;
    #pragma unroll
    for (int dy = 0; dy < 2; dy++) {
        #pragma unroll
        for (int dx = 0; dx < 2; dx++) {
            int xi = x0 + dx, yi = y0 + dy;
            bool val = (xi >= 0) && (xi < WP) && (yi >= 0) && (yi < HP);
            int xc = min(max(xi, 0), WP-1);
            int yc = min(max(yi, 0), HP-1);
            size_t base = (((size_t)cam*HP + yc)*WP + xc) * C_;
            float w = dy ? (dx ? w11 : w10) : (dx ? w01 : w00);
            float f0 = feat[base + lane];
            float f1 = feat[base + lane + 32];
            if (!val) { f0 = 0.f; f1 = 0.f; }
            s0 += w * f0;
            s1 += w * f1;
        }
    }
    size_t xb = (size_t)wid * 96;
    split_store(g_xh, g_xl, xb + lane,      s0 * zm);
    split_store(g_xh, g_xl, xb + 32 + lane, s1 * zm);

    int tdx = cam / V_;
    int vdx = cam % V_;
    int vmin = min(vdx, 63);
    float acc = pos_b[lane];
    #pragma unroll
    for (int i = 0; i < TE; i++)
        acc += g_temb[tdx*TE + i] * pos_w[i*32 + lane];
    #pragma unroll
    for (int i = 0; i < VE; i++)
        acc += view_emb[vmin*VE + i] * pos_w[(TE + i)*32 + lane];
    split_store(g_xh, g_xl, xb + 64 + lane, acc);
}

// ---------------- pipelined tensor-core GEMM, pure-half inputs, 3-MMA hi/lo ----------------
// A: [N][Kd] half hi/lo; B: [Nout][Kd] half hi/lo (pre-transposed weights).
// BM=BN=128, BK=32, 256 threads, 2-stage cp.async pipeline. mode: 1=relu, 2=fp32 out, 4=half out.
#define SK 40                              // padded halfs per smem row
#define STG_H (4*128*SK)                   // halves per stage (4 arrays)
#define ARR_B (128*SK*2)                   // bytes per array (10240)

__device__ __forceinline__ void mma16816(float* c, const uint32_t* a, uint32_t b0, uint32_t b1) {
    asm volatile(
        "mma.sync.aligned.m16n8k16.row.col.f32.f16.f16.f32 "
        "{%0,%1,%2,%3}, {%4,%5,%6,%7}, {%8,%9}, {%0,%1,%2,%3};\n"
        : "+f"(c[0]), "+f"(c[1]), "+f"(c[2]), "+f"(c[3])
        : "r"(a[0]), "r"(a[1]), "r"(a[2]), "r"(a[3]), "r"(b0), "r"(b1));
}
__device__ __forceinline__ void cpa16(uint32_t dst, const void* src, int sz) {
    asm volatile("cp.async.cg.shared.global [%0], [%1], 16, %2;\n" :: "r"(dst), "l"(src), "r"(sz));
}
__device__ __forceinline__ void cp_commit() { asm volatile("cp.async.commit_group;\n"); }
template<int NW> __device__ __forceinline__ void cp_wait() { asm volatile("cp.async.wait_group %0;\n" :: "n"(NW)); }

extern __shared__ __half s_dyn[];

__global__ __launch_bounds__(256, 2)
void gemm_tc2(const __half* __restrict__ Ah, const __half* __restrict__ Al,
              const __half* __restrict__ Bh, const __half* __restrict__ Bl,
              const float* __restrict__ bias, float* __restrict__ C,
              __half* __restrict__ Ch, __half* __restrict__ Cl,
              int N, int Kd, int Nout, int mode)
{
    int bm = blockIdx.y * 128;
    int bn = blockIdx.x * 128;
    int tid = threadIdx.x;
    int wid = tid >> 5, lane = tid & 31;
    int g = lane >> 2, tc = lane & 3;
    int wm = (wid >> 2) * 64;
    int wn = (wid & 3) * 32;
    uint32_t sb = (uint32_t)__cvta_generic_to_shared(s_dyn);

    float acc[4][4][4];
    #pragma unroll
    for (int i = 0; i < 4; i++)
        #pragma unroll
        for (int j = 0; j < 4; j++)
            #pragma unroll
            for (int r = 0; r < 4; r++) acc[i][j][r] = 0.f;

    const int NT = Kd >> 5;

    auto load_stage = [&](int st, int k0) {
        #pragma unroll
        for (int r = 0; r < 2; r++) {
            int id  = tid + r*256;           // 0..511
            int row = id >> 2;
            int seg = id & 3;
            uint32_t d = sb + st*(2*ARR_B*2) + row*(SK*2) + seg*16;
            int gr = bm + row;
            bool va = gr < N;
            size_t goA = (size_t)(va ? gr : 0) * Kd + k0 + seg*8;
            cpa16(d,             Ah + goA, va ? 16 : 0);
            cpa16(d + ARR_B,     Al + goA, va ? 16 : 0);
            int gn = bn + row;
            bool vb = gn < Nout;
            size_t goB = (size_t)(vb ? gn : 0) * Kd + k0 + seg*8;
            cpa16(d + 2*ARR_B,   Bh + goB, vb ? 16 : 0);
            cpa16(d + 3*ARR_B,   Bl + goB, vb ? 16 : 0);
        }
        cp_commit();
    };

    load_stage(0, 0);

    for (int t = 0; t < NT; t++) {
        int cur = t & 1;
        if (t + 1 < NT) { load_stage((t+1) & 1, (t+1)*32); cp_wait<1>(); }
        else            { cp_wait<0>(); }
        __syncthreads();

        const __half* sA_hi = s_dyn + cur*STG_H;
        const __half* sA_lo = sA_hi + 128*SK;
        const __half* sB_hi = sA_lo + 128*SK;
        const __half* sB_lo = sB_hi + 128*SK;

        #pragma unroll
        for (int kb = 0; kb < 32; kb += 16) {
            uint32_t ah[4][4], al[4][4];
            int c0 = kb + tc*2;
            #pragma unroll
            for (int i = 0; i < 4; i++) {
                int r0 = wm + i*16 + g;
                ah[i][0] = *(const uint32_t*)&sA_hi[(r0    )*SK + c0    ];
                ah[i][1] = *(const uint32_t*)&sA_hi[(r0 + 8)*SK + c0    ];
                ah[i][2] = *(const uint32_t*)&sA_hi[(r0    )*SK + c0 + 8];
                ah[i][3] = *(const uint32_t*)&sA_hi[(r0 + 8)*SK + c0 + 8];
                al[i][0] = *(const uint32_t*)&sA_lo[(r0    )*SK + c0    ];
                al[i][1] = *(const uint32_t*)&sA_lo[(r0 + 8)*SK + c0    ];
                al[i][2] = *(const uint32_t*)&sA_lo[(r0    )*SK + c0 + 8];
                al[i][3] = *(const uint32_t*)&sA_lo[(r0 + 8)*SK + c0 + 8];
            }
            #pragma unroll
            for (int j = 0; j < 4; j++) {
                int n0 = wn + j*8 + g;
                uint32_t bh0 = *(const uint32_t*)&sB_hi[n0*SK + c0    ];
                uint32_t bh1 = *(const uint32_t*)&sB_hi[n0*SK + c0 + 8];
                uint32_t bl0 = *(const uint32_t*)&sB_lo[n0*SK + c0    ];
                uint32_t bl1 = *(const uint32_t*)&sB_lo[n0*SK + c0 + 8];
                #pragma unroll
                for (int i = 0; i < 4; i++) {
                    mma16816(acc[i][j], ah[i], bh0, bh1);
                    mma16816(acc[i][j], ah[i], bl0, bl1);
                    mma16816(acc[i][j], al[i], bh0, bh1);
                }
            }
        }
        __syncthreads();
    }

    // epilogue
    bool relu  = mode & 1;
    bool wfp   = mode & 2;
    bool whalf = mode & 4;
    #pragma unroll
    for (int j = 0; j < 4; j++) {
        int col = bn + wn + j*8 + tc*2;
        if (col >= Nout) continue;
        float bx = bias[col], by = bias[col+1];
        #pragma unroll
        for (int i = 0; i < 4; i++) {
            int r0 = bm + wm + i*16 + g;
            int r1 = r0 + 8;
            float v0 = acc[i][j][0] + bx;
            float v1 = acc[i][j][1] + by;
            float v2 = acc[i][j][2] + bx;
            float v3 = acc[i][j][3] + by;
            if (relu) {
                v0 = fmaxf(v0, 0.f); v1 = fmaxf(v1, 0.f);
                v2 = fmaxf(v2, 0.f); v3 = fmaxf(v3, 0.f);
            }
            if (r0 < N) {
                size_t o = (size_t)r0*Nout + col;
                if (wfp) { C[o] = v0; C[o+1] = v1; }
                if (whalf) {
                    __half h0 = __float2half_rn(v0), h1 = __float2half_rn(v1);
                    *(__half2*)(Ch + o) = __halves2half2(h0, h1);
                    *(__half2*)(Cl + o) = __halves2half2(
                        __float2half_rn(v0 - __half2float(h0)),
                        __float2half_rn(v1 - __half2float(h1)));
                }
            }
            if (r1 < N) {
                size_t o = (size_t)r1*Nout + col;
                if (wfp) { C[o] = v2; C[o+1] = v3; }
                if (whalf) {
                    __half h2 = __float2half_rn(v2), h3 = __float2half_rn(v3);
                    *(__half2*)(Ch + o) = __halves2half2(h2, h3);
                    *(__half2*)(Cl + o) = __halves2half2(
                        __float2half_rn(v2 - __half2float(h2)),
                        __float2half_rn(v3 - __half2float(h3)));
                }
            }
        }
    }
}

// ---------------- attention over 4 tokens, 8 heads, Dh=32 -> o hi/lo ----------------
__global__ __launch_bounds__(256)
void attn_kernel(int M)
{
    int m = blockIdx.x;
    if (m >= M) return;
    int h = threadIdx.x >> 5;
    int lane = threadIdx.x & 31;
    const float* qkv = g_qkv + (size_t)m * KSEL * 768;

    float q[4], k[4], v[4];
    #pragma unroll
    for (int j = 0; j < 4; j++) {
        q[j] = qkv[(size_t)j*768 +        h*32 + lane];
        k[j] = qkv[(size_t)j*768 + 256  + h*32 + lane];
        v[j] = qkv[(size_t)j*768 + 512  + h*32 + lane];
    }
    float s[16];
    #pragma unroll
    for (int i = 0; i < 4; i++)
        #pragma unroll
        for (int j = 0; j < 4; j++)
            s[i*4+j] = q[i] * k[j];
    #pragma unroll
    for (int off = 16; off > 0; off >>= 1)
        #pragma unroll
        for (int x = 0; x < 16; x++)
            s[x] += __shfl_xor_sync(0xFFFFFFFFu, s[x], off);

    const float scale = 0.17677669529663687f;
    float a[16];
    #pragma unroll
    for (int i = 0; i < 4; i++) {
        float s0 = s[i*4+0]*scale, s1 = s[i*4+1]*scale;
        float s2 = s[i*4+2]*scale, s3 = s[i*4+3]*scale;
        float mx = fmaxf(fmaxf(s0, s1), fmaxf(s2, s3));
        float e0 = expf(s0-mx), e1 = expf(s1-mx), e2 = expf(s2-mx), e3 = expf(s3-mx);
        float r = 1.0f / (e0+e1+e2+e3);
        a[i*4+0] = e0*r; a[i*4+1] = e1*r; a[i*4+2] = e2*r; a[i*4+3] = e3*r;
    }
    size_t ob = (size_t)m * KSEL * 256;
    #pragma unroll
    for (int i = 0; i < 4; i++) {
        float oi = a[i*4+0]*v[0] + a[i*4+1]*v[1] + a[i*4+2]*v[2] + a[i*4+3]*v[3];
        split_store(g_oh, g_ol, ob + (size_t)i*256 + h*32 + lane, oi);
    }
}

// ---------------- residual add + layernorm (in place on g_h, also emits hi/lo) ----------------
__global__ __launch_bounds__(256)
void add_ln_kernel(float* __restrict__ h, const float* __restrict__ d,
                   const float* __restrict__ s, const float* __restrict__ b,
                   int Ntok)
{
    int row  = (blockIdx.x * blockDim.x + threadIdx.x) >> 5;
    int lane = threadIdx.x & 31;
    if (row >= Ntok) return;
    size_t base = (size_t)row*256 + lane*8;
    float x[8];
    float4 h0 = *(float4*)(h + base),       h1 = *(float4*)(h + base + 4);
    float4 d0 = *(const float4*)(d + base), d1 = *(const float4*)(d + base + 4);
    x[0]=h0.x+d0.x; x[1]=h0.y+d0.y; x[2]=h0.z+d0.z; x[3]=h0.w+d0.w;
    x[4]=h1.x+d1.x; x[5]=h1.y+d1.y; x[6]=h1.z+d1.z; x[7]=h1.w+d1.w;

    float sum = 0.f;
    #pragma unroll
    for (int j = 0; j < 8; j++) sum += x[j];
    #pragma unroll
    for (int off = 16; off > 0; off >>= 1) sum += __shfl_xor_sync(0xFFFFFFFFu, sum, off);
    float mu = sum * (1.0f/256.0f);

    float vs = 0.f;
    #pragma unroll
    for (int j = 0; j < 8; j++) { float t = x[j]-mu; vs += t*t; }
    #pragma unroll
    for (int off = 16; off > 0; off >>= 1) vs += __shfl_xor_sync(0xFFFFFFFFu, vs, off);
    float rinv = rsqrtf(vs * (1.0f/256.0f) + 1e-5f);

    float y[8];
    #pragma unroll
    for (int j = 0; j < 8; j++) {
        int c = lane*8 + j;
        y[j] = (x[j]-mu)*rinv*s[c] + b[c];
    }
    *(float4*)(h + base)     = make_float4(y[0],y[1],y[2],y[3]);
    *(float4*)(h + base + 4) = make_float4(y[4],y[5],y[6],y[7]);
    #pragma unroll
    for (int j = 0; j < 8; j++) split_store(g_hh, g_hl, base + j, y[j]);
}

// ---------------- mean over the 4 tokens -> hi/lo ----------------
__global__ __launch_bounds__(256)
void mean_kernel(int M)
{
    int idx = blockIdx.x * blockDim.x + threadIdx.x;
    if (idx >= M*256) return;
    int m = idx >> 8, c = idx & 255;
    const float* hp = g_h + (size_t)m*4*256 + c;
    split_store(g_mh, g_ml, idx, 0.25f * (hp[0] + hp[256] + hp[512] + hp[768]));
}

// ---------------- host launch ----------------
extern "C" void kernel_launch(void* const* d_in, const int* in_sizes, int n_in,
                              void* d_out, int out_size)
{
    const float* xyz      = (const float*)d_in[0];
    const float* feat     = (const float*)d_in[1];
    const float* poses    = (const float*)d_in[2];
    const float* intr     = (const float*)d_in[3];
    const int*   time_ids = (const int*)  d_in[4];
    const float* view_emb = (const float*)d_in[5];
    const float* pos_w    = (const float*)d_in[6];
    const float* pos_b    = (const float*)d_in[7];
    const float* fp_w     = (const float*)d_in[8];
    const float* fp_b     = (const float*)d_in[9];
    const float* qkv_w    = (const float*)d_in[10];
    const float* qkv_b    = (const float*)d_in[11];
    const float* ao_w     = (const float*)d_in[12];
    const float* ao_b     = (const float*)d_in[13];
    const float* ln1_s    = (const float*)d_in[14];
    const float* ln1_b    = (const float*)d_in[15];
    const float* ff1_w    = (const float*)d_in[16];
    const float* ff1_b    = (const float*)d_in[17];
    const float* ff2_w    = (const float*)d_in[18];
    const float* ff2_b    = (const float*)d_in[19];
    const float* ln2_s    = (const float*)d_in[20];
    const float* ln2_b    = (const float*)d_in[21];
    const float* out_w    = (const float*)d_in[22];
    const float* out_b    = (const float*)d_in[23];

    int M    = in_sizes[0] / 3;
    int Ntok = M * KSEL;
    int T    = in_sizes[4];

    float *ph, *pqkv, *pproj;
    __half *pxh,*pxl,*phh,*phl,*poh,*pol,*pfh,*pfl,*pmh,*pml,*pwh,*pwl;
    cudaGetSymbolAddress((void**)&ph,    g_h);
    cudaGetSymbolAddress((void**)&pqkv,  g_qkv);
    cudaGetSymbolAddress((void**)&pproj, g_proj);
    cudaGetSymbolAddress((void**)&pxh, g_xh); cudaGetSymbolAddress((void**)&pxl, g_xl);
    cudaGetSymbolAddress((void**)&phh, g_hh); cudaGetSymbolAddress((void**)&phl, g_hl);
    cudaGetSymbolAddress((void**)&poh, g_oh); cudaGetSymbolAddress((void**)&pol, g_ol);
    cudaGetSymbolAddress((void**)&pfh, g_fh); cudaGetSymbolAddress((void**)&pfl, g_fl);
    cudaGetSymbolAddress((void**)&pmh, g_mh); cudaGetSymbolAddress((void**)&pml, g_ml);
    cudaGetSymbolAddress((void**)&pwh, g_wh); cudaGetSymbolAddress((void**)&pwl, g_wl);

    cudaFuncSetAttribute(gemm_tc2, cudaFuncAttributeMaxDynamicSharedMemorySize, 81920);

    // weight offsets in transposed hi/lo buffer
    const size_t off_fp   = 0;                         // 256x96
    const size_t off_qkv0 = off_fp   + 24576;          // 768x256
    const size_t off_qkv1 = off_qkv0 + 196608;
    const size_t off_ao0  = off_qkv1 + 196608;         // 256x256
    const size_t off_ao1  = off_ao0  + 65536;
    const size_t off_ff10 = off_ao1  + 65536;          // 512x256
    const size_t off_ff11 = off_ff10 + 131072;
    const size_t off_ff20 = off_ff11 + 131072;         // 256x512
    const size_t off_ff21 = off_ff20 + 131072;
    const size_t off_out  = off_ff21 + 131072;         // 64x256

    auto wconv = [&](const float* W, size_t off, int Kd, int Nout) {
        int total = Kd * Nout;
        wconv_kernel<<<(total + 255)/256, 256>>>(W, pwh + off, pwl + off, Kd, Nout, total);
    };
    wconv(fp_w, off_fp, 96, 256);
    wconv(qkv_w,               off_qkv0, 256, 768);
    wconv(qkv_w + 256*768,     off_qkv1, 256, 768);
    wconv(ao_w,                off_ao0,  256, 256);
    wconv(ao_w + 256*256,      off_ao1,  256, 256);
    wconv(ff1_w,               off_ff10, 256, 512);
    wconv(ff1_w + 256*512,     off_ff11, 256, 512);
    wconv(ff2_w,               off_ff20, 512, 256);
    wconv(ff2_w + 512*256,     off_ff21, 512, 256);
    wconv(out_w, off_out, 256, 64);

    setup_kernel<<<1, 32>>>(poses, intr, time_ids, T);
    proj_topk_kernel<<<(M + 127)/128, 128>>>(xyz, M);
    gather_kernel<<<(Ntok*32 + 255)/256, 256>>>(feat, view_emb, pos_w, pos_b, Ntok);

    auto gemm = [&](const __half* Ah, const __half* Al, size_t woff,
                    const float* bias, float* C, __half* Ch, __half* Cl,
                    int N, int Kd, int Nout, int mode) {
        dim3 grid((Nout + 127)/128, (N + 127)/128);
        gemm_tc2<<<grid, 256, 81920>>>(Ah, Al, pwh + woff, pwl + woff,
                                       bias, C, Ch, Cl, N, Kd, Nout, mode);
    };

    // fp: xin -> h (fp32 + halves)
    gemm(pxh, pxl, off_fp, fp_b, ph, phh, phl, Ntok, 96, 256, 2|4);

    const size_t qoff[2] = {off_qkv0, off_qkv1};
    const size_t aoff[2] = {off_ao0,  off_ao1};
    const size_t f1off[2] = {off_ff10, off_ff11};
    const size_t f2off[2] = {off_ff20, off_ff21};
    for (int l = 0; l < 2; l++) {
        gemm(phh, phl, qoff[l], qkv_b + l*768, pqkv, nullptr, nullptr, Ntok, 256, 768, 2);
        attn_kernel<<<M, 256>>>(M);
        gemm(poh, pol, aoff[l], ao_b + l*256, pproj, nullptr, nullptr, Ntok, 256, 256, 2);
        add_ln_kernel<<<(Ntok*32 + 255)/256, 256>>>(ph, pproj, ln1_s + l*256, ln1_b + l*256, Ntok);
        gemm(phh, phl, f1off[l], ff1_b + l*512, nullptr, pfh, pfl, Ntok, 256, 512, 4|1);
        gemm(pfh, pfl, f2off[l], ff2_b + l*256, pproj, nullptr, nullptr, Ntok, 512, 256, 2);
        add_ln_kernel<<<(Ntok*32 + 255)/256, 256>>>(ph, pproj, ln2_s + l*256, ln2_b + l*256, Ntok);
    }

    mean_kernel<<<(M*256 + 255)/256, 256>>>(M);
    gemm(pmh, pml, off_out, out_b, (float*)d_out, nullptr, nullptr, M, 256, 64, 2);
}

// round 5
// speedup vs baseline: 1.9356x; 1.0504x over previous
#include <cuda_runtime.h>
#include <cuda_fp16.h>
#include <math.h>
#include <stdint.h>

// ---------------- problem constants ----------------
#define T_    4
#define V_    8
#define TVC   32
#define HP    64
#define WP    64
#define C_    64
#define KSEL  4
#define HID   256
#define TE    32
#define VE    16
#define MAXM  50000
#define MAXTOK (MAXM*KSEL)

// ---------------- scratch ----------------
__device__ float g_P[TVC*12];
__device__ float g_scal[4];
__device__ float g_temb[T_*TE];
__device__ int   g_selcam[MAXTOK];
__device__ float g_selu[MAXTOK];
__device__ float g_selv[MAXTOK];
__device__ float g_selz[MAXTOK];

// fp32 intermediates
__device__ float g_h   [(size_t)MAXTOK*256];
__device__ float g_qkv [(size_t)MAXTOK*768];
__device__ float g_proj[(size_t)MAXTOK*256];

// half hi/lo activation buffers (GEMM A-operands)
__device__ __half g_xh[(size_t)MAXTOK*96],  g_xl[(size_t)MAXTOK*96];
__device__ __half g_hh[(size_t)MAXTOK*256], g_hl[(size_t)MAXTOK*256];
__device__ __half g_oh[(size_t)MAXTOK*256], g_ol[(size_t)MAXTOK*256];
__device__ __half g_fh[(size_t)MAXTOK*512], g_fl[(size_t)MAXTOK*512];
__device__ __half g_mh[(size_t)MAXM*256],   g_ml[(size_t)MAXM*256];

// preconverted transposed weights [Nout][Kd], hi/lo
#define WTOTAL 1089536
__device__ __half g_wh[WTOTAL], g_wl[WTOTAL];

// ---------------- setup ----------------
__global__ void setup_kernel(const float* __restrict__ poses,
                             const float* __restrict__ intr,
                             const int*   __restrict__ time_ids,
                             int T)
{
    int n = threadIdx.x;
    if (n < TVC) {
        double a[4][8];
        for (int r = 0; r < 4; r++)
            for (int c = 0; c < 4; c++) {
                a[r][c]   = (double)poses[n*16 + r*4 + c];
                a[r][4+c] = (r == c) ? 1.0 : 0.0;
            }
        for (int col = 0; col < 4; col++) {
            int piv = col;
            for (int r = col+1; r < 4; r++)
                if (fabs(a[r][col]) > fabs(a[piv][col])) piv = r;
            if (piv != col)
                for (int c = 0; c < 8; c++) { double t = a[col][c]; a[col][c] = a[piv][c]; a[piv][c] = t; }
            double dv = a[col][col];
            for (int c = 0; c < 8; c++) a[col][c] /= dv;
            for (int r = 0; r < 4; r++) if (r != col) {
                double f = a[r][col];
                for (int c = 0; c < 8; c++) a[r][c] -= f * a[col][c];
            }
        }
        double Km[9];
        for (int i = 0; i < 9; i++) Km[i] = (double)intr[n*9 + i];
        for (int r = 0; r < 3; r++)
            for (int c = 0; c < 4; c++) {
                double s = 0.0;
                for (int j = 0; j < 3; j++) s += Km[r*3 + j] * a[j][4 + c];
                g_P[n*12 + r*4 + c] = (float)s;
            }
    }
    if (n == 0) {
        float cx = intr[2], cy = intr[5];
        float W = 2.0f*cx, H = 2.0f*cy;
        g_scal[0] = W; g_scal[1] = H;
        g_scal[2] = (float)WP / fmaxf(1.0f, W);
        g_scal[3] = (float)HP / fmaxf(1.0f, H);
        int tmin = time_ids[0], tmax = time_ids[0];
        for (int t = 1; t < T; t++) {
            int v = time_ids[t];
            if (v < tmin) tmin = v;
            if (v > tmax) tmax = v;
        }
        if (tmax < tmin + 1) tmax = tmin + 1;
        for (int t = 0; t < T; t++) {
            double tn = (double)(time_ids[t] - tmin) / (double)(tmax - tmin);
            for (int i = 0; i < TE/2; i++) {
                double f  = exp(8.0 * (double)i / (double)(TE/2 - 1));
                double ph = tn * f;
                g_temb[t*TE + i]        = (float)sin(ph);
                g_temb[t*TE + TE/2 + i] = (float)cos(ph);
            }
        }
    }
}

// ---------------- weight convert + transpose ----------------
__global__ __launch_bounds__(256)
void wconv_kernel(const float* __restrict__ W, __half* __restrict__ Wh,
                  __half* __restrict__ Wl, int Kd, int Nout, int total)
{
    int i = blockIdx.x * blockDim.x + threadIdx.x;
    if (i >= total) return;
    int n = i / Kd, k = i - n*Kd;
    float w = W[(size_t)k*Nout + n];
    __half h = __float2half_rn(w);
    Wh[i] = h;
    Wl[i] = __float2half_rn(w - __half2float(h));
}

// ---------------- per-point projection + stable top-4 ----------------
__global__ __launch_bounds__(128)
void proj_topk_kernel(const float* __restrict__ xyz, int M)
{
    int m = blockIdx.x * blockDim.x + threadIdx.x;
    if (m >= M) return;
    float X = xyz[3*m+0], Y = xyz[3*m+1], Z = xyz[3*m+2];
    float W = g_scal[0], H = g_scal[1];

    float bs[KSEL] = {-1.f,-1.f,-1.f,-1.f};
    int   bi[KSEL] = {1000,1000,1000,1000};
    float bu[KSEL], bv[KSEL], bz[KSEL];
    #pragma unroll
    for (int q = 0; q < KSEL; q++) { bu[q]=0; bv[q]=0; bz[q]=0; }

    for (int cam = 0; cam < TVC; cam++) {
        const float* P = g_P + cam*12;
        float uw = P[0]*X + P[1]*Y + P[2] *Z + P[3];
        float vw = P[4]*X + P[5]*Y + P[6] *Z + P[7];
        float z  = P[8]*X + P[9]*Y + P[10]*Z + P[11];
        float wd = fmaxf(z, 1e-6f);
        float u = uw / wd, v = vw / wd;
        bool vis = (z > 1e-4f) && (u >= 0.f) && (u < W) && (v >= 0.f) && (v < H);
        float score = vis ? (1.0f / (fmaxf(z, 0.1f) + 1e-6f)) : 0.0f;
        #pragma unroll
        for (int slot = 0; slot < KSEL; slot++) {
            bool better = (score > bs[slot]) || (score == bs[slot] && cam < bi[slot]);
            if (better) {
                for (int q = KSEL-1; q > slot; q--) {
                    bs[q]=bs[q-1]; bi[q]=bi[q-1]; bu[q]=bu[q-1]; bv[q]=bv[q-1]; bz[q]=bz[q-1];
                }
                bs[slot]=score; bi[slot]=cam; bu[slot]=u; bv[slot]=v; bz[slot]=z;
                break;
            }
        }
    }
    #pragma unroll
    for (int q = 0; q < KSEL; q++) {
        int t = m*KSEL + q;
        g_selcam[t] = bi[q];
        g_selu[t] = bu[q]; g_selv[t] = bv[q]; g_selz[t] = bz[q];
    }
}

__device__ __forceinline__ void split_store(__half* hp, __half* lp, size_t idx, float v) {
    __half h = __float2half_rn(v);
    hp[idx] = h;
    lp[idx] = __float2half_rn(v - __half2float(h));
}

// ---------------- bilinear gather + pos feats -> xin hi/lo [Ntok,96] ----------------
__global__ __launch_bounds__(256)
void gather_kernel(const float* __restrict__ feat,
                   const float* __restrict__ view_emb,
                   const float* __restrict__ pos_w,
                   const float* __restrict__ pos_b,
                   int Ntok)
{
    int wid  = (blockIdx.x * blockDim.x + threadIdx.x) >> 5;
    int lane = threadIdx.x & 31;
    if (wid >= Ntok) return;

    int   cam = g_selcam[wid];
    float u = g_selu[wid], v = g_selv[wid], z = g_selz[wid];
    float uf = u * g_scal[2], vf = v * g_scal[3];
    float x0f = floorf(uf), y0f = floorf(vf);
    float fx = uf - x0f, fy = vf - y0f;
    int x0 = (int)x0f, y0 = (int)y0f;
    float w00 = (1.f-fx)*(1.f-fy);
    float w01 = fx*(1.f-fy);
    float w10 = (1.f-fx)*fy;
    float w11 = fx*fy;
    float zm  = (z > 1e-4f) ? 1.0f : 0.0f;

    float s0 = 0.f, s1 = 0.f;
    #pragma unroll
    for (int dy = 0; dy < 2; dy++) {
        #pragma unroll
        for (int dx = 0; dx < 2; dx++) {
            int xi = x0 + dx, yi = y0 + dy;
            bool val = (xi >= 0) && (xi < WP) && (yi >= 0) && (yi < HP);
            int xc = min(max(xi, 0), WP-1);
            int yc = min(max(yi, 0), HP-1);
            size_t base = (((size_t)cam*HP + yc)*WP + xc) * C_;
            float w = dy ? (dx ? w11 : w10) : (dx ? w01 : w00);
            float f0 = feat[base + lane];
            float f1 = feat[base + lane + 32];
            if (!val) { f0 = 0.f; f1 = 0.f; }
            s0 += w * f0;
            s1 += w * f1;
        }
    }
    size_t xb = (size_t)wid * 96;
    split_store(g_xh, g_xl, xb + lane,      s0 * zm);
    split_store(g_xh, g_xl, xb + 32 + lane, s1 * zm);

    int tdx = cam / V_;
    int vdx = cam % V_;
    int vmin = min(vdx, 63);
    float acc = pos_b[lane];
    #pragma unroll
    for (int i = 0; i < TE; i++)
        acc += g_temb[tdx*TE + i] * pos_w[i*32 + lane];
    #pragma unroll
    for (int i = 0; i < VE; i++)
        acc += view_emb[vmin*VE + i] * pos_w[(TE + i)*32 + lane];
    split_store(g_xh, g_xl, xb + 64 + lane, acc);
}

// ---------------- pipelined tensor-core GEMM, LDSM fragments, 3-MMA hi/lo ----------------
// A: [N][Kd] half hi/lo; B: [Nout][Kd] half hi/lo. BM=BN=128, BK=32, 256 thr, 2-stage cp.async.
// mode: 1=relu, 2=fp32 out, 4=half out.
#define SK 40                              // padded halfs per smem row
#define STG_H (4*128*SK)                   // halves per stage
#define ARR_B (128*SK*2)                   // bytes per array (10240)
#define STG_B (4*ARR_B)                    // bytes per stage (40960)

__device__ __forceinline__ void mma16816(float* c, const uint32_t* a, uint32_t b0, uint32_t b1) {
    asm volatile(
        "mma.sync.aligned.m16n8k16.row.col.f32.f16.f16.f32 "
        "{%0,%1,%2,%3}, {%4,%5,%6,%7}, {%8,%9}, {%0,%1,%2,%3};\n"
        : "+f"(c[0]), "+f"(c[1]), "+f"(c[2]), "+f"(c[3])
        : "r"(a[0]), "r"(a[1]), "r"(a[2]), "r"(a[3]), "r"(b0), "r"(b1));
}
__device__ __forceinline__ void ldsm4(uint32_t* r, uint32_t addr) {
    asm volatile("ldmatrix.sync.aligned.m8n8.x4.shared.b16 {%0,%1,%2,%3}, [%4];"
        : "=r"(r[0]), "=r"(r[1]), "=r"(r[2]), "=r"(r[3]) : "r"(addr));
}
__device__ __forceinline__ void cpa16(uint32_t dst, const void* src, int sz) {
    asm volatile("cp.async.cg.shared.global [%0], [%1], 16, %2;\n" :: "r"(dst), "l"(src), "r"(sz));
}
__device__ __forceinline__ void cp_commit() { asm volatile("cp.async.commit_group;\n"); }
template<int NW> __device__ __forceinline__ void cp_wait() { asm volatile("cp.async.wait_group %0;\n" :: "n"(NW)); }

extern __shared__ __half s_dyn[];

__global__ __launch_bounds__(256, 2)
void gemm_tc2(const __half* __restrict__ Ah, const __half* __restrict__ Al,
              const __half* __restrict__ Bh, const __half* __restrict__ Bl,
              const float* __restrict__ bias, float* __restrict__ C,
              __half* __restrict__ Ch, __half* __restrict__ Cl,
              int N, int Kd, int Nout, int mode)
{
    int bm = blockIdx.y * 128;
    int bn = blockIdx.x * 128;
    int tid = threadIdx.x;
    int wid = tid >> 5, lane = tid & 31;
    int g = lane >> 2, tc = lane & 3;
    int wm = (wid >> 2) * 64;
    int wn = (wid & 3) * 32;
    uint32_t sb = (uint32_t)__cvta_generic_to_shared(s_dyn);

    // ldmatrix per-lane byte offsets within a stage
    // A i-tile: row = wm + i*16 + (lane&15), col halfs = (lane>>4)*8
    uint32_t a_off[4];
    #pragma unroll
    for (int i = 0; i < 4; i++)
        a_off[i] = (uint32_t)(((wm + i*16 + (lane & 15)) * SK + ((lane >> 4) << 3)) * 2);
    // B jp-pair: row n = wn + jp*16 + (lane&7) + ((lane>>4)<<3), col halfs = ((lane>>3)&1)<<3
    uint32_t b_off[2];
    #pragma unroll
    for (int jp = 0; jp < 2; jp++)
        b_off[jp] = (uint32_t)(((wn + jp*16 + (lane & 7) + ((lane >> 4) << 3)) * SK
                                + (((lane >> 3) & 1) << 3)) * 2);

    float acc[4][4][4];
    #pragma unroll
    for (int i = 0; i < 4; i++)
        #pragma unroll
        for (int j = 0; j < 4; j++)
            #pragma unroll
            for (int r = 0; r < 4; r++) acc[i][j][r] = 0.f;

    const int NT = Kd >> 5;

    auto load_stage = [&](int st, int k0) {
        #pragma unroll
        for (int r = 0; r < 2; r++) {
            int id  = tid + r*256;           // 0..511
            int row = id >> 2;
            int seg = id & 3;
            uint32_t d = sb + st*STG_B + row*(SK*2) + seg*16;
            int gr = bm + row;
            bool va = gr < N;
            size_t goA = (size_t)(va ? gr : 0) * Kd + k0 + seg*8;
            cpa16(d,             Ah + goA, va ? 16 : 0);
            cpa16(d + ARR_B,     Al + goA, va ? 16 : 0);
            int gn = bn + row;
            bool vb = gn < Nout;
            size_t goB = (size_t)(vb ? gn : 0) * Kd + k0 + seg*8;
            cpa16(d + 2*ARR_B,   Bh + goB, vb ? 16 : 0);
            cpa16(d + 3*ARR_B,   Bl + goB, vb ? 16 : 0);
        }
        cp_commit();
    };

    load_stage(0, 0);

    for (int t = 0; t < NT; t++) {
        cp_wait<0>();
        __syncthreads();
        if (t + 1 < NT) load_stage((t+1) & 1, (t+1)*32);

        uint32_t sa = sb + (t & 1)*STG_B;          // A_hi base of current stage
        uint32_t sbb = sa + 2*ARR_B;               // B_hi base

        #pragma unroll
        for (int kb = 0; kb < 32; kb += 16) {
            uint32_t kbB = kb * 2;
            uint32_t ah[4][4], al[4][4];
            #pragma unroll
            for (int i = 0; i < 4; i++) {
                ldsm4(ah[i], sa + a_off[i] + kbB);
                ldsm4(al[i], sa + ARR_B + a_off[i] + kbB);
            }
            #pragma unroll
            for (int jp = 0; jp < 2; jp++) {
                uint32_t bh[4], bl[4];
                ldsm4(bh, sbb + b_off[jp] + kbB);
                ldsm4(bl, sbb + ARR_B + b_off[jp] + kbB);
                #pragma unroll
                for (int jj = 0; jj < 2; jj++) {
                    int j = jp*2 + jj;
                    uint32_t bh0 = bh[jj*2], bh1 = bh[jj*2+1];
                    uint32_t bl0 = bl[jj*2], bl1 = bl[jj*2+1];
                    #pragma unroll
                    for (int i = 0; i < 4; i++) {
                        mma16816(acc[i][j], ah[i], bh0, bh1);
                        mma16816(acc[i][j], ah[i], bl0, bl1);
                        mma16816(acc[i][j], al[i], bh0, bh1);
                    }
                }
            }
        }
    }

    // epilogue
    bool relu  = mode & 1;
    bool wfp   = mode & 2;
    bool whalf = mode & 4;
    #pragma unroll
    for (int j = 0; j < 4; j++) {
        int col = bn + wn + j*8 + tc*2;
        if (col >= Nout) continue;
        float bx = bias[col], by = bias[col+1];
        #pragma unroll
        for (int i = 0; i < 4; i++) {
            int r0 = bm + wm + i*16 + g;
            int r1 = r0 + 8;
            float v0 = acc[i][j][0] + bx;
            float v1 = acc[i][j][1] + by;
            float v2 = acc[i][j][2] + bx;
            float v3 = acc[i][j][3] + by;
            if (relu) {
                v0 = fmaxf(v0, 0.f); v1 = fmaxf(v1, 0.f);
                v2 = fmaxf(v2, 0.f); v3 = fmaxf(v3, 0.f);
            }
            if (r0 < N) {
                size_t o = (size_t)r0*Nout + col;
                if (wfp) { C[o] = v0; C[o+1] = v1; }
                if (whalf) {
                    __half h0 = __float2half_rn(v0), h1 = __float2half_rn(v1);
                    *(__half2*)(Ch + o) = __halves2half2(h0, h1);
                    *(__half2*)(Cl + o) = __halves2half2(
                        __float2half_rn(v0 - __half2float(h0)),
                        __float2half_rn(v1 - __half2float(h1)));
                }
            }
            if (r1 < N) {
                size_t o = (size_t)r1*Nout + col;
                if (wfp) { C[o] = v2; C[o+1] = v3; }
                if (whalf) {
                    __half h2 = __float2half_rn(v2), h3 = __float2half_rn(v3);
                    *(__half2*)(Ch + o) = __halves2half2(h2, h3);
                    *(__half2*)(Cl + o) = __halves2half2(
                        __float2half_rn(v2 - __half2float(h2)),
                        __float2half_rn(v3 - __half2float(h3)));
                }
            }
        }
    }
}

// ---------------- attention over 4 tokens, 8 heads, Dh=32 -> o hi/lo ----------------
__global__ __launch_bounds__(256)
void attn_kernel(int M)
{
    int m = blockIdx.x;
    if (m >= M) return;
    int h = threadIdx.x >> 5;
    int lane = threadIdx.x & 31;
    const float* qkv = g_qkv + (size_t)m * KSEL * 768;

    float q[4], k[4], v[4];
    #pragma unroll
    for (int j = 0; j < 4; j++) {
        q[j] = qkv[(size_t)j*768 +        h*32 + lane];
        k[j] = qkv[(size_t)j*768 + 256  + h*32 + lane];
        v[j] = qkv[(size_t)j*768 + 512  + h*32 + lane];
    }
    float s[16];
    #pragma unroll
    for (int i = 0; i < 4; i++)
        #pragma unroll
        for (int j = 0; j < 4; j++)
            s[i*4+j] = q[i] * k[j];
    #pragma unroll
    for (int off = 16; off > 0; off >>= 1)
        #pragma unroll
        for (int x = 0; x < 16; x++)
            s[x] += __shfl_xor_sync(0xFFFFFFFFu, s[x], off);

    const float scale = 0.17677669529663687f;
    float a[16];
    #pragma unroll
    for (int i = 0; i < 4; i++) {
        float s0 = s[i*4+0]*scale, s1 = s[i*4+1]*scale;
        float s2 = s[i*4+2]*scale, s3 = s[i*4+3]*scale;
        float mx = fmaxf(fmaxf(s0, s1), fmaxf(s2, s3));
        float e0 = expf(s0-mx), e1 = expf(s1-mx), e2 = expf(s2-mx), e3 = expf(s3-mx);
        float r = 1.0f / (e0+e1+e2+e3);
        a[i*4+0] = e0*r; a[i*4+1] = e1*r; a[i*4+2] = e2*r; a[i*4+3] = e3*r;
    }
    size_t ob = (size_t)m * KSEL * 256;
    #pragma unroll
    for (int i = 0; i < 4; i++) {
        float oi = a[i*4+0]*v[0] + a[i*4+1]*v[1] + a[i*4+2]*v[2] + a[i*4+3]*v[3];
        split_store(g_oh, g_ol, ob + (size_t)i*256 + h*32 + lane, oi);
    }
}

// ---------------- residual add + layernorm ----------------
__global__ __launch_bounds__(256)
void add_ln_kernel(float* __restrict__ h, const float* __restrict__ d,
                   const float* __restrict__ s, const float* __restrict__ b,
                   int Ntok)
{
    int row  = (blockIdx.x * blockDim.x + threadIdx.x) >> 5;
    int lane = threadIdx.x & 31;
    if (row >= Ntok) return;
    size_t base = (size_t)row*256 + lane*8;
    float x[8];
    float4 h0 = *(float4*)(h + base),       h1 = *(float4*)(h + base + 4);
    float4 d0 = *(const float4*)(d + base), d1 = *(const float4*)(d + base + 4);
    x[0]=h0.x+d0.x; x[1]=h0.y+d0.y; x[2]=h0.z+d0.z; x[3]=h0.w+d0.w;
    x[4]=h1.x+d1.x; x[5]=h1.y+d1.y; x[6]=h1.z+d1.z; x[7]=h1.w+d1.w;

    float sum = 0.f;
    #pragma unroll
    for (int j = 0; j < 8; j++) sum += x[j];
    #pragma unroll
    for (int off = 16; off > 0; off >>= 1) sum += __shfl_xor_sync(0xFFFFFFFFu, sum, off);
    float mu = sum * (1.0f/256.0f);

    float vs = 0.f;
    #pragma unroll
    for (int j = 0; j < 8; j++) { float t = x[j]-mu; vs += t*t; }
    #pragma unroll
    for (int off = 16; off > 0; off >>= 1) vs += __shfl_xor_sync(0xFFFFFFFFu, vs, off);
    float rinv = rsqrtf(vs * (1.0f/256.0f) + 1e-5f);

    float y[8];
    #pragma unroll
    for (int j = 0; j < 8; j++) {
        int c = lane*8 + j;
        y[j] = (x[j]-mu)*rinv*s[c] + b[c];
    }
    *(float4*)(h + base)     = make_float4(y[0],y[1],y[2],y[3]);
    *(float4*)(h + base + 4) = make_float4(y[4],y[5],y[6],y[7]);
    #pragma unroll
    for (int j = 0; j < 8; j++) split_store(g_hh, g_hl, base + j, y[j]);
}

// ---------------- mean over the 4 tokens -> hi/lo ----------------
__global__ __launch_bounds__(256)
void mean_kernel(int M)
{
    int idx = blockIdx.x * blockDim.x + threadIdx.x;
    if (idx >= M*256) return;
    int m = idx >> 8, c = idx & 255;
    const float* hp = g_h + (size_t)m*4*256 + c;
    split_store(g_mh, g_ml, idx, 0.25f * (hp[0] + hp[256] + hp[512] + hp[768]));
}

// ---------------- host launch ----------------
extern "C" void kernel_launch(void* const* d_in, const int* in_sizes, int n_in,
                              void* d_out, int out_size)
{
    const float* xyz      = (const float*)d_in[0];
    const float* feat     = (const float*)d_in[1];
    const float* poses    = (const float*)d_in[2];
    const float* intr     = (const float*)d_in[3];
    const int*   time_ids = (const int*)  d_in[4];
    const float* view_emb = (const float*)d_in[5];
    const float* pos_w    = (const float*)d_in[6];
    const float* pos_b    = (const float*)d_in[7];
    const float* fp_w     = (const float*)d_in[8];
    const float* fp_b     = (const float*)d_in[9];
    const float* qkv_w    = (const float*)d_in[10];
    const float* qkv_b    = (const float*)d_in[11];
    const float* ao_w     = (const float*)d_in[12];
    const float* ao_b     = (const float*)d_in[13];
    const float* ln1_s    = (const float*)d_in[14];
    const float* ln1_b    = (const float*)d_in[15];
    const float* ff1_w    = (const float*)d_in[16];
    const float* ff1_b    = (const float*)d_in[17];
    const float* ff2_w    = (const float*)d_in[18];
    const float* ff2_b    = (const float*)d_in[19];
    const float* ln2_s    = (const float*)d_in[20];
    const float* ln2_b    = (const float*)d_in[21];
    const float* out_w    = (const float*)d_in[22];
    const float* out_b    = (const float*)d_in[23];

    int M    = in_sizes[0] / 3;
    int Ntok = M * KSEL;
    int T    = in_sizes[4];

    float *ph, *pqkv, *pproj;
    __half *pxh,*pxl,*phh,*phl,*poh,*pol,*pfh,*pfl,*pmh,*pml,*pwh,*pwl;
    cudaGetSymbolAddress((void**)&ph,    g_h);
    cudaGetSymbolAddress((void**)&pqkv,  g_qkv);
    cudaGetSymbolAddress((void**)&pproj, g_proj);
    cudaGetSymbolAddress((void**)&pxh, g_xh); cudaGetSymbolAddress((void**)&pxl, g_xl);
    cudaGetSymbolAddress((void**)&phh, g_hh); cudaGetSymbolAddress((void**)&phl, g_hl);
    cudaGetSymbolAddress((void**)&poh, g_oh); cudaGetSymbolAddress((void**)&pol, g_ol);
    cudaGetSymbolAddress((void**)&pfh, g_fh); cudaGetSymbolAddress((void**)&pfl, g_fl);
    cudaGetSymbolAddress((void**)&pmh, g_mh); cudaGetSymbolAddress((void**)&pml, g_ml);
    cudaGetSymbolAddress((void**)&pwh, g_wh); cudaGetSymbolAddress((void**)&pwl, g_wl);

    cudaFuncSetAttribute(gemm_tc2, cudaFuncAttributeMaxDynamicSharedMemorySize, 81920);

    const size_t off_fp   = 0;
    const size_t off_qkv0 = off_fp   + 24576;
    const size_t off_qkv1 = off_qkv0 + 196608;
    const size_t off_ao0  = off_qkv1 + 196608;
    const size_t off_ao1  = off_ao0  + 65536;
    const size_t off_ff10 = off_ao1  + 65536;
    const size_t off_ff11 = off_ff10 + 131072;
    const size_t off_ff20 = off_ff11 + 131072;
    const size_t off_ff21 = off_ff20 + 131072;
    const size_t off_out  = off_ff21 + 131072;

    auto wconv = [&](const float* W, size_t off, int Kd, int Nout) {
        int total = Kd * Nout;
        wconv_kernel<<<(total + 255)/256, 256>>>(W, pwh + off, pwl + off, Kd, Nout, total);
    };
    wconv(fp_w, off_fp, 96, 256);
    wconv(qkv_w,               off_qkv0, 256, 768);
    wconv(qkv_w + 256*768,     off_qkv1, 256, 768);
    wconv(ao_w,                off_ao0,  256, 256);
    wconv(ao_w + 256*256,      off_ao1,  256, 256);
    wconv(ff1_w,               off_ff10, 256, 512);
    wconv(ff1_w + 256*512,     off_ff11, 256, 512);
    wconv(ff2_w,               off_ff20, 512, 256);
    wconv(ff2_w + 512*256,     off_ff21, 512, 256);
    wconv(out_w, off_out, 256, 64);

    setup_kernel<<<1, 32>>>(poses, intr, time_ids, T);
    proj_topk_kernel<<<(M + 127)/128, 128>>>(xyz, M);
    gather_kernel<<<(Ntok*32 + 255)/256, 256>>>(feat, view_emb, pos_w, pos_b, Ntok);

    auto gemm = [&](const __half* Ah, const __half* Al, size_t woff,
                    const float* bias, float* C, __half* Ch, __half* Cl,
                    int N, int Kd, int Nout, int mode) {
        dim3 grid((Nout + 127)/128, (N + 127)/128);
        gemm_tc2<<<grid, 256, 81920>>>(Ah, Al, pwh + woff, pwl + woff,
                                       bias, C, Ch, Cl, N, Kd, Nout, mode);
    };

    // fp: xin -> h (fp32 + halves)
    gemm(pxh, pxl, off_fp, fp_b, ph, phh, phl, Ntok, 96, 256, 2|4);

    const size_t qoff[2] = {off_qkv0, off_qkv1};
    const size_t aoff[2] = {off_ao0,  off_ao1};
    const size_t f1off[2] = {off_ff10, off_ff11};
    const size_t f2off[2] = {off_ff20, off_ff21};
    for (int l = 0; l < 2; l++) {
        gemm(phh, phl, qoff[l], qkv_b + l*768, pqkv, nullptr, nullptr, Ntok, 256, 768, 2);
        attn_kernel<<<M, 256>>>(M);
        gemm(poh, pol, aoff[l], ao_b + l*256, pproj, nullptr, nullptr, Ntok, 256, 256, 2);
        add_ln_kernel<<<(Ntok*32 + 255)/256, 256>>>(ph, pproj, ln1_s + l*256, ln1_b + l*256, Ntok);
        gemm(phh, phl, f1off[l], ff1_b + l*512, nullptr, pfh, pfl, Ntok, 256, 512, 4|1);
        gemm(pfh, pfl, f2off[l], ff2_b + l*256, pproj, nullptr, nullptr, Ntok, 512, 256, 2);
        add_ln_kernel<<<(Ntok*32 + 255)/256, 256>>>(ph, pproj, ln2_s + l*256, ln2_b + l*256, Ntok);
    }

    mean_kernel<<<(M*256 + 255)/256, 256>>>(M);
    gemm(pmh, pml, off_out, out_b, (float*)d_out, nullptr, nullptr, M, 256, 64, 2);
}

// round 9
// speedup vs baseline: 2.2595x; 1.1674x over previous
#include <cuda_runtime.h>
#include <cuda_fp16.h>
#include <math.h>
#include <stdint.h>

// ---------------- problem constants ----------------
#define T_    4
#define V_    8
#define TVC   32
#define HP    64
#define WP    64
#define C_    64
#define KSEL  4
#define HID   256
#define TE    32
#define VE    16
#define MAXM  50000
#define MAXTOK (MAXM*KSEL)

// ---------------- scratch ----------------
__device__ float g_P[TVC*12];
__device__ float g_scal[4];
__device__ float g_temb[T_*TE];
__device__ int   g_selcam[MAXTOK];
__device__ float g_selu[MAXTOK];
__device__ float g_selv[MAXTOK];
__device__ float g_selz[MAXTOK];

// fp32 intermediates
__device__ float g_h   [(size_t)MAXTOK*256];
__device__ float g_qkv [(size_t)MAXTOK*768];

// half hi/lo activation buffers (GEMM A-operands)
__device__ __half g_xh[(size_t)MAXTOK*96],  g_xl[(size_t)MAXTOK*96];
__device__ __half g_hh[(size_t)MAXTOK*256], g_hl[(size_t)MAXTOK*256];
__device__ __half g_oh[(size_t)MAXTOK*256], g_ol[(size_t)MAXTOK*256];
__device__ __half g_fh[(size_t)MAXTOK*512], g_fl[(size_t)MAXTOK*512];
__device__ __half g_mh[(size_t)MAXM*256],   g_ml[(size_t)MAXM*256];

// preconverted transposed weights [Nout][Kd], hi/lo
#define WTOTAL 1089536
__device__ __half g_wh[WTOTAL], g_wl[WTOTAL];

// ---------------- setup ----------------
__global__ void setup_kernel(const float* __restrict__ poses,
                             const float* __restrict__ intr,
                             const int*   __restrict__ time_ids,
                             int T)
{
    int n = threadIdx.x;
    if (n < TVC) {
        double a[4][8];
        for (int r = 0; r < 4; r++)
            for (int c = 0; c < 4; c++) {
                a[r][c]   = (double)poses[n*16 + r*4 + c];
                a[r][4+c] = (r == c) ? 1.0 : 0.0;
            }
        for (int col = 0; col < 4; col++) {
            int piv = col;
            for (int r = col+1; r < 4; r++)
                if (fabs(a[r][col]) > fabs(a[piv][col])) piv = r;
            if (piv != col)
                for (int c = 0; c < 8; c++) { double t = a[col][c]; a[col][c] = a[piv][c]; a[piv][c] = t; }
            double dv = a[col][col];
            for (int c = 0; c < 8; c++) a[col][c] /= dv;
            for (int r = 0; r < 4; r++) if (r != col) {
                double f = a[r][col];
                for (int c = 0; c < 8; c++) a[r][c] -= f * a[col][c];
            }
        }
        double Km[9];
        for (int i = 0; i < 9; i++) Km[i] = (double)intr[n*9 + i];
        for (int r = 0; r < 3; r++)
            for (int c = 0; c < 4; c++) {
                double s = 0.0;
                for (int j = 0; j < 3; j++) s += Km[r*3 + j] * a[j][4 + c];
                g_P[n*12 + r*4 + c] = (float)s;
            }
    }
    if (n == 0) {
        float cx = intr[2], cy = intr[5];
        float W = 2.0f*cx, H = 2.0f*cy;
        g_scal[0] = W; g_scal[1] = H;
        g_scal[2] = (float)WP / fmaxf(1.0f, W);
        g_scal[3] = (float)HP / fmaxf(1.0f, H);
        int tmin = time_ids[0], tmax = time_ids[0];
        for (int t = 1; t < T; t++) {
            int v = time_ids[t];
            if (v < tmin) tmin = v;
            if (v > tmax) tmax = v;
        }
        if (tmax < tmin + 1) tmax = tmin + 1;
        for (int t = 0; t < T; t++) {
            double tn = (double)(time_ids[t] - tmin) / (double)(tmax - tmin);
            for (int i = 0; i < TE/2; i++) {
                double f  = exp(8.0 * (double)i / (double)(TE/2 - 1));
                double ph = tn * f;
                g_temb[t*TE + i]        = (float)sin(ph);
                g_temb[t*TE + TE/2 + i] = (float)cos(ph);
            }
        }
    }
}

// ---------------- single-launch weight convert + transpose ----------------
struct WTab {
    const float* src[10];
    long long    off[10];
    int          kd[10];
    int          nout[10];
};
__global__ __launch_bounds__(256)
void wconv_all(WTab tab, __half* __restrict__ Wh, __half* __restrict__ Wl)
{
    int mi  = blockIdx.y;
    int idx = blockIdx.x * blockDim.x + threadIdx.x;
    int Kd = tab.kd[mi], Nout = tab.nout[mi];
    if (idx >= Kd * Nout) return;
    int n = idx / Kd, k = idx - n*Kd;
    float w = tab.src[mi][(size_t)k*Nout + n];
    __half h = __float2half_rn(w);
    size_t o = (size_t)tab.off[mi] + idx;
    Wh[o] = h;
    Wl[o] = __float2half_rn(w - __half2float(h));
}

// ---------------- per-point projection + stable top-4 ----------------
__global__ __launch_bounds__(128)
void proj_topk_kernel(const float* __restrict__ xyz, int M)
{
    int m = blockIdx.x * blockDim.x + threadIdx.x;
    if (m >= M) return;
    float X = xyz[3*m+0], Y = xyz[3*m+1], Z = xyz[3*m+2];
    float W = g_scal[0], H = g_scal[1];

    float bs[KSEL] = {-1.f,-1.f,-1.f,-1.f};
    int   bi[KSEL] = {1000,1000,1000,1000};
    float bu[KSEL], bv[KSEL], bz[KSEL];
    #pragma unroll
    for (int q = 0; q < KSEL; q++) { bu[q]=0; bv[q]=0; bz[q]=0; }

    for (int cam = 0; cam < TVC; cam++) {
        const float* P = g_P + cam*12;
        float uw = P[0]*X + P[1]*Y + P[2] *Z + P[3];
        float vw = P[4]*X + P[5]*Y + P[6] *Z + P[7];
        float z  = P[8]*X + P[9]*Y + P[10]*Z + P[11];
        float wd = fmaxf(z, 1e-6f);
        float u = uw / wd, v = vw / wd;
        bool vis = (z > 1e-4f) && (u >= 0.f) && (u < W) && (v >= 0.f) && (v < H);
        float score = vis ? (1.0f / (fmaxf(z, 0.1f) + 1e-6f)) : 0.0f;
        #pragma unroll
        for (int slot = 0; slot < KSEL; slot++) {
            bool better = (score > bs[slot]) || (score == bs[slot] && cam < bi[slot]);
            if (better) {
                for (int q = KSEL-1; q > slot; q--) {
                    bs[q]=bs[q-1]; bi[q]=bi[q-1]; bu[q]=bu[q-1]; bv[q]=bv[q-1]; bz[q]=bz[q-1];
                }
                bs[slot]=score; bi[slot]=cam; bu[slot]=u; bv[slot]=v; bz[slot]=z;
                break;
            }
        }
    }
    #pragma unroll
    for (int q = 0; q < KSEL; q++) {
        int t = m*KSEL + q;
        g_selcam[t] = bi[q];
        g_selu[t] = bu[q]; g_selv[t] = bv[q]; g_selz[t] = bz[q];
    }
}

__device__ __forceinline__ void split_store(__half* hp, __half* lp, size_t idx, float v) {
    __half h = __float2half_rn(v);
    hp[idx] = h;
    lp[idx] = __float2half_rn(v - __half2float(h));
}

// ---------------- bilinear gather + pos feats -> xin hi/lo [Ntok,96] ----------------
__global__ __launch_bounds__(256)
void gather_kernel(const float* __restrict__ feat,
                   const float* __restrict__ view_emb,
                   const float* __restrict__ pos_w,
                   const float* __restrict__ pos_b,
                   int Ntok)
{
    int wid  = (blockIdx.x * blockDim.x + threadIdx.x) >> 5;
    int lane = threadIdx.x & 31;
    if (wid >= Ntok) return;

    int   cam = g_selcam[wid];
    float u = g_selu[wid], v = g_selv[wid], z = g_selz[wid];
    float uf = u * g_scal[2], vf = v * g_scal[3];
    float x0f = floorf(uf), y0f = floorf(vf);
    float fx = uf - x0f, fy = vf - y0f;
    int x0 = (int)x0f, y0 = (int)y0f;
    float w00 = (1.f-fx)*(1.f-fy);
    float w01 = fx*(1.f-fy);
    float w10 = (1.f-fx)*fy;
    float w11 = fx*fy;
    float zm  = (z > 1e-4f) ? 1.0f : 0.0f;

    float s0 = 0.f, s1 = 0.f;
    #pragma unroll
    for (int dy = 0; dy < 2; dy++) {
        #pragma unroll
        for (int dx = 0; dx < 2; dx++) {
            int xi = x0 + dx, yi = y0 + dy;
            bool val = (xi >= 0) && (xi < WP) && (yi >= 0) && (yi < HP);
            int xc = min(max(xi, 0), WP-1);
            int yc = min(max(yi, 0), HP-1);
            size_t base = (((size_t)cam*HP + yc)*WP + xc) * C_;
            float w = dy ? (dx ? w11 : w10) : (dx ? w01 : w00);
            float f0 = feat[base + lane];
            float f1 = feat[base + lane + 32];
            if (!val) { f0 = 0.f; f1 = 0.f; }
            s0 += w * f0;
            s1 += w * f1;
        }
    }
    size_t xb = (size_t)wid * 96;
    split_store(g_xh, g_xl, xb + lane,      s0 * zm);
    split_store(g_xh, g_xl, xb + 32 + lane, s1 * zm);

    int tdx = cam / V_;
    int vdx = cam % V_;
    int vmin = min(vdx, 63);
    float acc = pos_b[lane];
    #pragma unroll
    for (int i = 0; i < TE; i++)
        acc += g_temb[tdx*TE + i] * pos_w[i*32 + lane];
    #pragma unroll
    for (int i = 0; i < VE; i++)
        acc += view_emb[vmin*VE + i] * pos_w[(TE + i)*32 + lane];
    split_store(g_xh, g_xl, xb + 64 + lane, acc);
}

// ---------------- shared helpers for tensor-core GEMMs ----------------
__device__ __forceinline__ void mma16816(float* c, const uint32_t* a, uint32_t b0, uint32_t b1) {
    asm volatile(
        "mma.sync.aligned.m16n8k16.row.col.f32.f16.f16.f32 "
        "{%0,%1,%2,%3}, {%4,%5,%6,%7}, {%8,%9}, {%0,%1,%2,%3};\n"
        : "+f"(c[0]), "+f"(c[1]), "+f"(c[2]), "+f"(c[3])
        : "r"(a[0]), "r"(a[1]), "r"(a[2]), "r"(a[3]), "r"(b0), "r"(b1));
}
__device__ __forceinline__ void ldsm4(uint32_t* r, uint32_t addr) {
    asm volatile("ldmatrix.sync.aligned.m8n8.x4.shared.b16 {%0,%1,%2,%3}, [%4];"
        : "=r"(r[0]), "=r"(r[1]), "=r"(r[2]), "=r"(r[3]) : "r"(addr));
}
__device__ __forceinline__ void cpa16(uint32_t dst, const void* src, int sz) {
    asm volatile("cp.async.cg.shared.global [%0], [%1], 16, %2;\n" :: "r"(dst), "l"(src), "r"(sz));
}
__device__ __forceinline__ void cp_commit() { asm volatile("cp.async.commit_group;\n"); }
__device__ __forceinline__ void cp_wait0()  { asm volatile("cp.async.wait_group 0;\n"); }

extern __shared__ __half s_dyn[];

// ---------------- main GEMM: BM=BN=128, BK=32, 2-stage cp.async, LDSM, 3-MMA hi/lo ----------------
// mode: 1=relu, 2=fp32 out, 4=half out.
#define SK 40
#define ARR_B (128*SK*2)                   // 10240
#define STG_B (4*ARR_B)                    // 40960

__global__ __launch_bounds__(256, 2)
void gemm_tc2(const __half* __restrict__ Ah, const __half* __restrict__ Al,
              const __half* __restrict__ Bh, const __half* __restrict__ Bl,
              const float* __restrict__ bias, float* __restrict__ C,
              __half* __restrict__ Ch, __half* __restrict__ Cl,
              int N, int Kd, int Nout, int mode)
{
    int bm = blockIdx.y * 128;
    int bn = blockIdx.x * 128;
    int tid = threadIdx.x;
    int wid = tid >> 5, lane = tid & 31;
    int g = lane >> 2, tc = lane & 3;
    int wm = (wid >> 2) * 64;
    int wn = (wid & 3) * 32;
    uint32_t sb = (uint32_t)__cvta_generic_to_shared(s_dyn);

    uint32_t a_off[4];
    #pragma unroll
    for (int i = 0; i < 4; i++)
        a_off[i] = (uint32_t)(((wm + i*16 + (lane & 15)) * SK + ((lane >> 4) << 3)) * 2);
    uint32_t b_off[2];
    #pragma unroll
    for (int jp = 0; jp < 2; jp++)
        b_off[jp] = (uint32_t)(((wn + jp*16 + (lane & 7) + ((lane >> 4) << 3)) * SK
                                + (((lane >> 3) & 1) << 3)) * 2);

    float acc[4][4][4];
    #pragma unroll
    for (int i = 0; i < 4; i++)
        #pragma unroll
        for (int j = 0; j < 4; j++)
            #pragma unroll
            for (int r = 0; r < 4; r++) acc[i][j][r] = 0.f;

    const int NT = Kd >> 5;

    auto load_stage = [&](int st, int k0) {
        #pragma unroll
        for (int r = 0; r < 2; r++) {
            int id  = tid + r*256;
            int row = id >> 2;
            int seg = id & 3;
            uint32_t d = sb + st*STG_B + row*(SK*2) + seg*16;
            int gr = bm + row;
            bool va = gr < N;
            size_t goA = (size_t)(va ? gr : 0) * Kd + k0 + seg*8;
            cpa16(d,             Ah + goA, va ? 16 : 0);
            cpa16(d + ARR_B,     Al + goA, va ? 16 : 0);
            int gn = bn + row;
            bool vb = gn < Nout;
            size_t goB = (size_t)(vb ? gn : 0) * Kd + k0 + seg*8;
            cpa16(d + 2*ARR_B,   Bh + goB, vb ? 16 : 0);
            cpa16(d + 3*ARR_B,   Bl + goB, vb ? 16 : 0);
        }
        cp_commit();
    };

    load_stage(0, 0);

    for (int t = 0; t < NT; t++) {
        cp_wait0();
        __syncthreads();
        if (t + 1 < NT) load_stage((t+1) & 1, (t+1)*32);

        uint32_t sa  = sb + (t & 1)*STG_B;
        uint32_t sbb = sa + 2*ARR_B;

        #pragma unroll
        for (int kb = 0; kb < 32; kb += 16) {
            uint32_t kbB = kb * 2;
            uint32_t ah[4][4], al[4][4];
            #pragma unroll
            for (int i = 0; i < 4; i++) {
                ldsm4(ah[i], sa + a_off[i] + kbB);
                ldsm4(al[i], sa + ARR_B + a_off[i] + kbB);
            }
            #pragma unroll
            for (int jp = 0; jp < 2; jp++) {
                uint32_t bh[4], bl[4];
                ldsm4(bh, sbb + b_off[jp] + kbB);
                ldsm4(bl, sbb + ARR_B + b_off[jp] + kbB);
                #pragma unroll
                for (int jj = 0; jj < 2; jj++) {
                    int j = jp*2 + jj;
                    uint32_t bh0 = bh[jj*2], bh1 = bh[jj*2+1];
                    uint32_t bl0 = bl[jj*2], bl1 = bl[jj*2+1];
                    #pragma unroll
                    for (int i = 0; i < 4; i++) {
                        mma16816(acc[i][j], ah[i], bh0, bh1);
                        mma16816(acc[i][j], ah[i], bl0, bl1);
                        mma16816(acc[i][j], al[i], bh0, bh1);
                    }
                }
            }
        }
    }

    bool relu  = mode & 1;
    bool wfp   = mode & 2;
    bool whalf = mode & 4;
    #pragma unroll
    for (int j = 0; j < 4; j++) {
        int col = bn + wn + j*8 + tc*2;
        if (col >= Nout) continue;
        float bx = bias[col], by = bias[col+1];
        #pragma unroll
        for (int i = 0; i < 4; i++) {
            int r0 = bm + wm + i*16 + g;
            int r1 = r0 + 8;
            float v0 = acc[i][j][0] + bx;
            float v1 = acc[i][j][1] + by;
            float v2 = acc[i][j][2] + bx;
            float v3 = acc[i][j][3] + by;
            if (relu) {
                v0 = fmaxf(v0, 0.f); v1 = fmaxf(v1, 0.f);
                v2 = fmaxf(v2, 0.f); v3 = fmaxf(v3, 0.f);
            }
            if (r0 < N) {
                size_t o = (size_t)r0*Nout + col;
                if (wfp) { C[o] = v0; C[o+1] = v1; }
                if (whalf) {
                    __half h0 = __float2half_rn(v0), h1 = __float2half_rn(v1);
                    *(__half2*)(Ch + o) = __halves2half2(h0, h1);
                    *(__half2*)(Cl + o) = __halves2half2(
                        __float2half_rn(v0 - __half2float(h0)),
                        __float2half_rn(v1 - __half2float(h1)));
                }
            }
            if (r1 < N) {
                size_t o = (size_t)r1*Nout + col;
                if (wfp) { C[o] = v2; C[o+1] = v3; }
                if (whalf) {
                    __half h2 = __float2half_rn(v2), h3 = __float2half_rn(v3);
                    *(__half2*)(Ch + o) = __halves2half2(h2, h3);
                    *(__half2*)(Cl + o) = __halves2half2(
                        __float2half_rn(v2 - __half2float(h2)),
                        __float2half_rn(v3 - __half2float(h3)));
                }
            }
        }
    }
}

// ---------------- fused GEMM + residual + LayerNorm (Nout=256 fixed) ----------------
// BM=64, BN=256, 8 warps (2x4), warp tile 32x64. Writes h fp32 + half hi/lo.
// SKF=40 -> 80-byte row stride: cp.async dst 16B-aligned, LDSM conflict-free.
#define SKF   40
#define FA_B  (64*SKF*2)                   // 5120
#define FB_B  (256*SKF*2)                  // 20480
#define FSTG  (2*FA_B + 2*FB_B)            // 51200
#define FRED  (2*FSTG)                     // 102400
#define FTOT  (FRED + 64*4*8)              // 104448

__global__ __launch_bounds__(256, 2)
void gemm_ln(const __half* __restrict__ Ah, const __half* __restrict__ Al,
             const __half* __restrict__ Bh, const __half* __restrict__ Bl,
             const float* __restrict__ bias,
             const float* __restrict__ lns, const float* __restrict__ lnb,
             float* __restrict__ Hres, __half* __restrict__ Ch, __half* __restrict__ Cl,
             int N, int Kd)
{
    int bm = blockIdx.x * 64;
    int tid = threadIdx.x;
    int wid = tid >> 5, lane = tid & 31;
    int g = lane >> 2, tc = lane & 3;
    int wr = wid >> 2;            // 0..1 -> rows wr*32
    int wc = wid & 3;             // 0..3 -> cols wc*64
    uint32_t sb = (uint32_t)__cvta_generic_to_shared(s_dyn);
    float2* red = (float2*)((char*)s_dyn + FRED);

    uint32_t a_off[2];
    #pragma unroll
    for (int i = 0; i < 2; i++)
        a_off[i] = (uint32_t)(((wr*32 + i*16 + (lane & 15)) * SKF + ((lane >> 4) << 3)) * 2);
    uint32_t b_off[4];
    #pragma unroll
    for (int jp = 0; jp < 4; jp++)
        b_off[jp] = (uint32_t)(((wc*64 + jp*16 + (lane & 7) + ((lane >> 4) << 3)) * SKF
                                + (((lane >> 3) & 1) << 3)) * 2);

    float acc[2][8][4];
    #pragma unroll
    for (int i = 0; i < 2; i++)
        #pragma unroll
        for (int j = 0; j < 8; j++)
            #pragma unroll
            for (int r = 0; r < 4; r++) acc[i][j][r] = 0.f;

    const int NT = Kd >> 5;

    auto load_stage = [&](int st, int k0) {
        // A: 64 rows x 32 halfs, 1 chunk/thread/array
        {
            int row = tid >> 2, seg = tid & 3;
            uint32_t d = sb + st*FSTG + row*(SKF*2) + seg*16;
            int gr = bm + row;
            bool va = gr < N;
            size_t go = (size_t)(va ? gr : 0) * Kd + k0 + seg*8;
            cpa16(d,         Ah + go, va ? 16 : 0);
            cpa16(d + FA_B,  Al + go, va ? 16 : 0);
        }
        // B: 256 rows x 32 halfs, 4 chunks/thread/array
        #pragma unroll
        for (int r = 0; r < 4; r++) {
            int id = tid + r*256;
            int row = id >> 2, seg = id & 3;
            uint32_t d = sb + st*FSTG + 2*FA_B + row*(SKF*2) + seg*16;
            size_t go = (size_t)row * Kd + k0 + seg*8;
            cpa16(d,         Bh + go, 16);
            cpa16(d + FB_B,  Bl + go, 16);
        }
        cp_commit();
    };

    load_stage(0, 0);

    for (int t = 0; t < NT; t++) {
        cp_wait0();
        __syncthreads();
        if (t + 1 < NT) load_stage((t+1) & 1, (t+1)*32);

        uint32_t sa  = sb + (t & 1)*FSTG;
        uint32_t sbb = sa + 2*FA_B;

        #pragma unroll
        for (int kb = 0; kb < 32; kb += 16) {
            uint32_t kbB = kb * 2;
            uint32_t ah[2][4], al[2][4];
            #pragma unroll
            for (int i = 0; i < 2; i++) {
                ldsm4(ah[i], sa + a_off[i] + kbB);
                ldsm4(al[i], sa + FA_B + a_off[i] + kbB);
            }
            #pragma unroll
            for (int jp = 0; jp < 4; jp++) {
                uint32_t bh[4], bl[4];
                ldsm4(bh, sbb + b_off[jp] + kbB);
                ldsm4(bl, sbb + FB_B + b_off[jp] + kbB);
                #pragma unroll
                for (int jj = 0; jj < 2; jj++) {
                    int j = jp*2 + jj;
                    uint32_t bh0 = bh[jj*2], bh1 = bh[jj*2+1];
                    uint32_t bl0 = bl[jj*2], bl1 = bl[jj*2+1];
                    #pragma unroll
                    for (int i = 0; i < 2; i++) {
                        mma16816(acc[i][j], ah[i], bh0, bh1);
                        mma16816(acc[i][j], ah[i], bl0, bl1);
                        mma16816(acc[i][j], al[i], bh0, bh1);
                    }
                }
            }
        }
    }
    __syncthreads();   // k-loop done; smem now reusable as reduction buffer

    // ---- epilogue: x = h_old + (acc + bias); per-row LN over 256 cols ----
    int colw = wc*64;
    #pragma unroll
    for (int i = 0; i < 2; i++) {
        int rbase = wr*32 + i*16 + g;
        #pragma unroll
        for (int hhf = 0; hhf < 2; hhf++) {
            int rl = rbase + hhf*8;
            int grow = bm + rl;
            bool rv = grow < N;
            const float* hrow = Hres + (size_t)grow*256;
            float s1 = 0.f, s2 = 0.f;
            #pragma unroll
            for (int j = 0; j < 8; j++) {
                int col = colw + j*8 + tc*2;
                float2 hv = rv ? *(const float2*)(hrow + col) : make_float2(0.f, 0.f);
                float x0 = acc[i][j][hhf*2+0] + bias[col]   + hv.x;
                float x1 = acc[i][j][hhf*2+1] + bias[col+1] + hv.y;
                acc[i][j][hhf*2+0] = x0;
                acc[i][j][hhf*2+1] = x1;
                s1 += x0 + x1;
                s2 += x0*x0 + x1*x1;
            }
            s1 += __shfl_xor_sync(0xFFFFFFFFu, s1, 1);
            s1 += __shfl_xor_sync(0xFFFFFFFFu, s1, 2);
            s2 += __shfl_xor_sync(0xFFFFFFFFu, s2, 1);
            s2 += __shfl_xor_sync(0xFFFFFFFFu, s2, 2);
            if (tc == 0) red[(rl << 2) + wc] = make_float2(s1, s2);
        }
    }
    __syncthreads();
    #pragma unroll
    for (int i = 0; i < 2; i++) {
        int rbase = wr*32 + i*16 + g;
        #pragma unroll
        for (int hhf = 0; hhf < 2; hhf++) {
            int rl = rbase + hhf*8;
            int grow = bm + rl;
            if (grow >= N) continue;
            float2 t0 = red[(rl<<2)+0], t1 = red[(rl<<2)+1];
            float2 t2 = red[(rl<<2)+2], t3 = red[(rl<<2)+3];
            float tS  = t0.x + t1.x + t2.x + t3.x;
            float tS2 = t0.y + t1.y + t2.y + t3.y;
            float mu  = tS * (1.0f/256.0f);
            float var = tS2 * (1.0f/256.0f) - mu*mu;
            float rinv = rsqrtf(var + 1e-5f);
            float* hrow = Hres + (size_t)grow*256;
            size_t ob = (size_t)grow*256;
            #pragma unroll
            for (int j = 0; j < 8; j++) {
                int col = colw + j*8 + tc*2;
                float y0 = (acc[i][j][hhf*2+0] - mu)*rinv*lns[col]   + lnb[col];
                float y1 = (acc[i][j][hhf*2+1] - mu)*rinv*lns[col+1] + lnb[col+1];
                *(float2*)(hrow + col) = make_float2(y0, y1);
                __half h0 = __float2half_rn(y0), h1 = __float2half_rn(y1);
                *(__half2*)(Ch + ob + col) = __halves2half2(h0, h1);
                *(__half2*)(Cl + ob + col) = __halves2half2(
                    __float2half_rn(y0 - __half2float(h0)),
                    __float2half_rn(y1 - __half2float(h1)));
            }
        }
    }
}

// ---------------- attention over 4 tokens, 8 heads, Dh=32 -> o hi/lo ----------------
__global__ __launch_bounds__(256)
void attn_kernel(int M)
{
    int m = blockIdx.x;
    if (m >= M) return;
    int h = threadIdx.x >> 5;
    int lane = threadIdx.x & 31;
    const float* qkv = g_qkv + (size_t)m * KSEL * 768;

    float q[4], k[4], v[4];
    #pragma unroll
    for (int j = 0; j < 4; j++) {
        q[j] = qkv[(size_t)j*768 +        h*32 + lane];
        k[j] = qkv[(size_t)j*768 + 256  + h*32 + lane];
        v[j] = qkv[(size_t)j*768 + 512  + h*32 + lane];
    }
    float s[16];
    #pragma unroll
    for (int i = 0; i < 4; i++)
        #pragma unroll
        for (int j = 0; j < 4; j++)
            s[i*4+j] = q[i] * k[j];
    #pragma unroll
    for (int off = 16; off > 0; off >>= 1)
        #pragma unroll
        for (int x = 0; x < 16; x++)
            s[x] += __shfl_xor_sync(0xFFFFFFFFu, s[x], off);

    const float scale = 0.17677669529663687f;
    float a[16];
    #pragma unroll
    for (int i = 0; i < 4; i++) {
        float s0 = s[i*4+0]*scale, s1 = s[i*4+1]*scale;
        float s2 = s[i*4+2]*scale, s3 = s[i*4+3]*scale;
        float mx = fmaxf(fmaxf(s0, s1), fmaxf(s2, s3));
        float e0 = expf(s0-mx), e1 = expf(s1-mx), e2 = expf(s2-mx), e3 = expf(s3-mx);
        float r = 1.0f / (e0+e1+e2+e3);
        a[i*4+0] = e0*r; a[i*4+1] = e1*r; a[i*4+2] = e2*r; a[i*4+3] = e3*r;
    }
    size_t ob = (size_t)m * KSEL * 256;
    #pragma unroll
    for (int i = 0; i < 4; i++) {
        float oi = a[i*4+0]*v[0] + a[i*4+1]*v[1] + a[i*4+2]*v[2] + a[i*4+3]*v[3];
        split_store(g_oh, g_ol, ob + (size_t)i*256 + h*32 + lane, oi);
    }
}

// ---------------- mean over the 4 tokens -> hi/lo ----------------
__global__ __launch_bounds__(256)
void mean_kernel(int M)
{
    int idx = blockIdx.x * blockDim.x + threadIdx.x;
    if (idx >= M*256) return;
    int m = idx >> 8, c = idx & 255;
    const float* hp = g_h + (size_t)m*4*256 + c;
    split_store(g_mh, g_ml, idx, 0.25f * (hp[0] + hp[256] + hp[512] + hp[768]));
}

// ---------------- host launch ----------------
extern "C" void kernel_launch(void* const* d_in, const int* in_sizes, int n_in,
                              void* d_out, int out_size)
{
    const float* xyz      = (const float*)d_in[0];
    const float* feat     = (const float*)d_in[1];
    const float* poses    = (const float*)d_in[2];
    const float* intr     = (const float*)d_in[3];
    const int*   time_ids = (const int*)  d_in[4];
    const float* view_emb = (const float*)d_in[5];
    const float* pos_w    = (const float*)d_in[6];
    const float* pos_b    = (const float*)d_in[7];
    const float* fp_w     = (const float*)d_in[8];
    const float* fp_b     = (const float*)d_in[9];
    const float* qkv_w    = (const float*)d_in[10];
    const float* qkv_b    = (const float*)d_in[11];
    const float* ao_w     = (const float*)d_in[12];
    const float* ao_b     = (const float*)d_in[13];
    const float* ln1_s    = (const float*)d_in[14];
    const float* ln1_b    = (const float*)d_in[15];
    const float* ff1_w    = (const float*)d_in[16];
    const float* ff1_b    = (const float*)d_in[17];
    const float* ff2_w    = (const float*)d_in[18];
    const float* ff2_b    = (const float*)d_in[19];
    const float* ln2_s    = (const float*)d_in[20];
    const float* ln2_b    = (const float*)d_in[21];
    const float* out_w    = (const float*)d_in[22];
    const float* out_b    = (const float*)d_in[23];

    int M    = in_sizes[0] / 3;
    int Ntok = M * KSEL;
    int T    = in_sizes[4];

    float *ph, *pqkv;
    __half *pxh,*pxl,*phh,*phl,*poh,*pol,*pfh,*pfl,*pmh,*pml,*pwh,*pwl;
    cudaGetSymbolAddress((void**)&ph,    g_h);
    cudaGetSymbolAddress((void**)&pqkv,  g_qkv);
    cudaGetSymbolAddress((void**)&pxh, g_xh); cudaGetSymbolAddress((void**)&pxl, g_xl);
    cudaGetSymbolAddress((void**)&phh, g_hh); cudaGetSymbolAddress((void**)&phl, g_hl);
    cudaGetSymbolAddress((void**)&poh, g_oh); cudaGetSymbolAddress((void**)&pol, g_ol);
    cudaGetSymbolAddress((void**)&pfh, g_fh); cudaGetSymbolAddress((void**)&pfl, g_fl);
    cudaGetSymbolAddress((void**)&pmh, g_mh); cudaGetSymbolAddress((void**)&pml, g_ml);
    cudaGetSymbolAddress((void**)&pwh, g_wh); cudaGetSymbolAddress((void**)&pwl, g_wl);

    cudaFuncSetAttribute(gemm_tc2, cudaFuncAttributeMaxDynamicSharedMemorySize, 2*STG_B);
    cudaFuncSetAttribute(gemm_ln,  cudaFuncAttributeMaxDynamicSharedMemorySize, FTOT);

    const long long off_fp   = 0;
    const long long off_qkv0 = off_fp   + 24576;
    const long long off_qkv1 = off_qkv0 + 196608;
    const long long off_ao0  = off_qkv1 + 196608;
    const long long off_ao1  = off_ao0  + 65536;
    const long long off_ff10 = off_ao1  + 65536;
    const long long off_ff11 = off_ff10 + 131072;
    const long long off_ff20 = off_ff11 + 131072;
    const long long off_ff21 = off_ff20 + 131072;
    const long long off_out  = off_ff21 + 131072;

    WTab tab;
    tab.src[0]=fp_w;            tab.off[0]=off_fp;   tab.kd[0]=96;  tab.nout[0]=256;
    tab.src[1]=qkv_w;           tab.off[1]=off_qkv0; tab.kd[1]=256; tab.nout[1]=768;
    tab.src[2]=qkv_w+256*768;   tab.off[2]=off_qkv1; tab.kd[2]=256; tab.nout[2]=768;
    tab.src[3]=ao_w;            tab.off[3]=off_ao0;  tab.kd[3]=256; tab.nout[3]=256;
    tab.src[4]=ao_w+256*256;    tab.off[4]=off_ao1;  tab.kd[4]=256; tab.nout[4]=256;
    tab.src[5]=ff1_w;           tab.off[5]=off_ff10; tab.kd[5]=256; tab.nout[5]=512;
    tab.src[6]=ff1_w+256*512;   tab.off[6]=off_ff11; tab.kd[6]=256; tab.nout[6]=512;
    tab.src[7]=ff2_w;           tab.off[7]=off_ff20; tab.kd[7]=512; tab.nout[7]=256;
    tab.src[8]=ff2_w+512*256;   tab.off[8]=off_ff21; tab.kd[8]=512; tab.nout[8]=256;
    tab.src[9]=out_w;           tab.off[9]=off_out;  tab.kd[9]=256; tab.nout[9]=64;
    wconv_all<<<dim3(768, 10), 256>>>(tab, pwh, pwl);

    setup_kernel<<<1, 32>>>(poses, intr, time_ids, T);
    proj_topk_kernel<<<(M + 127)/128, 128>>>(xyz, M);
    gather_kernel<<<(Ntok*32 + 255)/256, 256>>>(feat, view_emb, pos_w, pos_b, Ntok);

    auto gemm = [&](const __half* Ah, const __half* Al, long long woff,
                    const float* bias, float* C, __half* Ch, __half* Cl,
                    int N, int Kd, int Nout, int mode) {
        dim3 grid((Nout + 127)/128, (N + 127)/128);
        gemm_tc2<<<grid, 256, 2*STG_B>>>(Ah, Al, pwh + woff, pwl + woff,
                                         bias, C, Ch, Cl, N, Kd, Nout, mode);
    };

    // fp: xin -> h (fp32 + halves)
    gemm(pxh, pxl, off_fp, fp_b, ph, phh, phl, Ntok, 96, 256, 2|4);

    const long long qoff[2]  = {off_qkv0, off_qkv1};
    const long long aoff[2]  = {off_ao0,  off_ao1};
    const long long f1off[2] = {off_ff10, off_ff11};
    const long long f2off[2] = {off_ff20, off_ff21};
    int gln = (Ntok + 63)/64;
    for (int l = 0; l < 2; l++) {
        gemm(phh, phl, qoff[l], qkv_b + l*768, pqkv, nullptr, nullptr, Ntok, 256, 768, 2);
        attn_kernel<<<M, 256>>>(M);
        gemm_ln<<<gln, 256, FTOT>>>(poh, pol, pwh + aoff[l], pwl + aoff[l],
                                    ao_b + l*256, ln1_s + l*256, ln1_b + l*256,
                                    ph, phh, phl, Ntok, 256);
        gemm(phh, phl, f1off[l], ff1_b + l*512, nullptr, pfh, pfl, Ntok, 256, 512, 4|1);
        gemm_ln<<<gln, 256, FTOT>>>(pfh, pfl, pwh + f2off[l], pwl + f2off[l],
                                    ff2_b + l*256, ln2_s + l*256, ln2_b + l*256,
                                    ph, phh, phl, Ntok, 512);
    }

    mean_kernel<<<(M*256 + 255)/256, 256>>>(M);
    gemm(pmh, pml, off_out, out_b, (float*)d_out, nullptr, nullptr, M, 256, 64, 2);
}

// round 12
// speedup vs baseline: 2.4608x; 1.0891x over previous
// v12: 2-MMA compensated GEMM pipeline (resubmit of v10/v11; broker flaked twice)
#include <cuda_runtime.h>
#include <cuda_fp16.h>
#include <math.h>
#include <stdint.h>

// ---------------- problem constants ----------------
#define T_    4
#define V_    8
#define TVC   32
#define HP    64
#define WP    64
#define C_    64
#define KSEL  4
#define HID   256
#define TE    32
#define VE    16
#define MAXM  50000
#define MAXTOK (MAXM*KSEL)

// ---------------- scratch ----------------
__device__ float g_P[TVC*12];
__device__ float g_scal[4];
__device__ float g_temb[T_*TE];
__device__ int   g_selcam[MAXTOK];
__device__ float g_selu[MAXTOK];
__device__ float g_selv[MAXTOK];
__device__ float g_selz[MAXTOK];

// fp32 intermediates
__device__ float g_h   [(size_t)MAXTOK*256];
__device__ float g_qkv [(size_t)MAXTOK*768];

// half (h, m/8) activation buffers (GEMM A-operands)
__device__ __half g_xh[(size_t)MAXTOK*96],  g_xl[(size_t)MAXTOK*96];
__device__ __half g_hh[(size_t)MAXTOK*256], g_hl[(size_t)MAXTOK*256];
__device__ __half g_oh[(size_t)MAXTOK*256], g_ol[(size_t)MAXTOK*256];
__device__ __half g_fh[(size_t)MAXTOK*512], g_fl[(size_t)MAXTOK*512];
__device__ __half g_mh[(size_t)MAXM*256],   g_ml[(size_t)MAXM*256];

// preconverted transposed weights [Nout][Kd], (h, m/4)
#define WTOTAL 1089536
__device__ __half g_wh[WTOTAL], g_wl[WTOTAL];

// ---------------- setup ----------------
__global__ void setup_kernel(const float* __restrict__ poses,
                             const float* __restrict__ intr,
                             const int*   __restrict__ time_ids,
                             int T)
{
    int n = threadIdx.x;
    if (n < TVC) {
        double a[4][8];
        for (int r = 0; r < 4; r++)
            for (int c = 0; c < 4; c++) {
                a[r][c]   = (double)poses[n*16 + r*4 + c];
                a[r][4+c] = (r == c) ? 1.0 : 0.0;
            }
        for (int col = 0; col < 4; col++) {
            int piv = col;
            for (int r = col+1; r < 4; r++)
                if (fabs(a[r][col]) > fabs(a[piv][col])) piv = r;
            if (piv != col)
                for (int c = 0; c < 8; c++) { double t = a[col][c]; a[col][c] = a[piv][c]; a[piv][c] = t; }
            double dv = a[col][col];
            for (int c = 0; c < 8; c++) a[col][c] /= dv;
            for (int r = 0; r < 4; r++) if (r != col) {
                double f = a[r][col];
                for (int c = 0; c < 8; c++) a[r][c] -= f * a[col][c];
            }
        }
        double Km[9];
        for (int i = 0; i < 9; i++) Km[i] = (double)intr[n*9 + i];
        for (int r = 0; r < 3; r++)
            for (int c = 0; c < 4; c++) {
                double s = 0.0;
                for (int j = 0; j < 3; j++) s += Km[r*3 + j] * a[j][4 + c];
                g_P[n*12 + r*4 + c] = (float)s;
            }
    }
    if (n == 0) {
        float cx = intr[2], cy = intr[5];
        float W = 2.0f*cx, H = 2.0f*cy;
        g_scal[0] = W; g_scal[1] = H;
        g_scal[2] = (float)WP / fmaxf(1.0f, W);
        g_scal[3] = (float)HP / fmaxf(1.0f, H);
        int tmin = time_ids[0], tmax = time_ids[0];
        for (int t = 1; t < T; t++) {
            int v = time_ids[t];
            if (v < tmin) tmin = v;
            if (v > tmax) tmax = v;
        }
        if (tmax < tmin + 1) tmax = tmin + 1;
        for (int t = 0; t < T; t++) {
            double tn = (double)(time_ids[t] - tmin) / (double)(tmax - tmin);
            for (int i = 0; i < TE/2; i++) {
                double f  = exp(8.0 * (double)i / (double)(TE/2 - 1));
                double ph = tn * f;
                g_temb[t*TE + i]        = (float)sin(ph);
                g_temb[t*TE + TE/2 + i] = (float)cos(ph);
            }
        }
    }
}

// ---------------- single-launch weight convert + transpose ----------------
// Emits Wh = RN(w) and Wm4 = RN(h/4 + 8*(w-h))  (merged term pre-scaled by 1/4)
struct WTab {
    const float* src[10];
    long long    off[10];
    int          kd[10];
    int          nout[10];
};
__global__ __launch_bounds__(256)
void wconv_all(WTab tab, __half* __restrict__ Wh, __half* __restrict__ Wl)
{
    int mi  = blockIdx.y;
    int idx = blockIdx.x * blockDim.x + threadIdx.x;
    int Kd = tab.kd[mi], Nout = tab.nout[mi];
    if (idx >= Kd * Nout) return;
    int n = idx / Kd, k = idx - n*Kd;
    float w = tab.src[mi][(size_t)k*Nout + n];
    __half h = __float2half_rn(w);
    float hf = __half2float(h);
    float l  = w - hf;
    size_t o = (size_t)tab.off[mi] + idx;
    Wh[o] = h;
    Wl[o] = __float2half_rn(hf*0.25f + 8.0f*l);
}

// ---------------- per-point projection + stable top-4 ----------------
__global__ __launch_bounds__(128)
void proj_topk_kernel(const float* __restrict__ xyz, int M)
{
    int m = blockIdx.x * blockDim.x + threadIdx.x;
    if (m >= M) return;
    float X = xyz[3*m+0], Y = xyz[3*m+1], Z = xyz[3*m+2];
    float W = g_scal[0], H = g_scal[1];

    float bs[KSEL] = {-1.f,-1.f,-1.f,-1.f};
    int   bi[KSEL] = {1000,1000,1000,1000};
    float bu[KSEL], bv[KSEL], bz[KSEL];
    #pragma unroll
    for (int q = 0; q < KSEL; q++) { bu[q]=0; bv[q]=0; bz[q]=0; }

    for (int cam = 0; cam < TVC; cam++) {
        const float* P = g_P + cam*12;
        float uw = P[0]*X + P[1]*Y + P[2] *Z + P[3];
        float vw = P[4]*X + P[5]*Y + P[6] *Z + P[7];
        float z  = P[8]*X + P[9]*Y + P[10]*Z + P[11];
        float wd = fmaxf(z, 1e-6f);
        float u = uw / wd, v = vw / wd;
        bool vis = (z > 1e-4f) && (u >= 0.f) && (u < W) && (v >= 0.f) && (v < H);
        float score = vis ? (1.0f / (fmaxf(z, 0.1f) + 1e-6f)) : 0.0f;
        #pragma unroll
        for (int slot = 0; slot < KSEL; slot++) {
            bool better = (score > bs[slot]) || (score == bs[slot] && cam < bi[slot]);
            if (better) {
                for (int q = KSEL-1; q > slot; q--) {
                    bs[q]=bs[q-1]; bi[q]=bi[q-1]; bu[q]=bu[q-1]; bv[q]=bv[q-1]; bz[q]=bz[q-1];
                }
                bs[slot]=score; bi[slot]=cam; bu[slot]=u; bv[slot]=v; bz[slot]=z;
                break;
            }
        }
    }
    #pragma unroll
    for (int q = 0; q < KSEL; q++) {
        int t = m*KSEL + q;
        g_selcam[t] = bi[q];
        g_selu[t] = bu[q]; g_selv[t] = bv[q]; g_selz[t] = bz[q];
    }
}

// Activation split: h = RN(v), m8 = RN(h/8 + 4*(v-h))  (merged term pre-scaled by 1/8)
__device__ __forceinline__ void split_store(__half* hp, __half* mp, size_t idx, float v) {
    __half h = __float2half_rn(v);
    float hf = __half2float(h);
    float l  = v - hf;
    hp[idx] = h;
    mp[idx] = __float2half_rn(hf*0.125f + 4.0f*l);
}

// ---------------- bilinear gather + pos feats -> xin h/m8 [Ntok,96] ----------------
__global__ __launch_bounds__(256)
void gather_kernel(const float* __restrict__ feat,
                   const float* __restrict__ view_emb,
                   const float* __restrict__ pos_w,
                   const float* __restrict__ pos_b,
                   int Ntok)
{
    int wid  = (blockIdx.x * blockDim.x + threadIdx.x) >> 5;
    int lane = threadIdx.x & 31;
    if (wid >= Ntok) return;

    int   cam = g_selcam[wid];
    float u = g_selu[wid], v = g_selv[wid], z = g_selz[wid];
    float uf = u * g_scal[2], vf = v * g_scal[3];
    float x0f = floorf(uf), y0f = floorf(vf);
    float fx = uf - x0f, fy = vf - y0f;
    int x0 = (int)x0f, y0 = (int)y0f;
    float w00 = (1.f-fx)*(1.f-fy);
    float w01 = fx*(1.f-fy);
    float w10 = (1.f-fx)*fy;
    float w11 = fx*fy;
    float zm  = (z > 1e-4f) ? 1.0f : 0.0f;

    float s0 = 0.f, s1 = 0.f;
    #pragma unroll
    for (int dy = 0; dy < 2; dy++) {
        #pragma unroll
        for (int dx = 0; dx < 2; dx++) {
            int xi = x0 + dx, yi = y0 + dy;
            bool val = (xi >= 0) && (xi < WP) && (yi >= 0) && (yi < HP);
            int xc = min(max(xi, 0), WP-1);
            int yc = min(max(yi, 0), HP-1);
            size_t base = (((size_t)cam*HP + yc)*WP + xc) * C_;
            float w = dy ? (dx ? w11 : w10) : (dx ? w01 : w00);
            float f0 = feat[base + lane];
            float f1 = feat[base + lane + 32];
            if (!val) { f0 = 0.f; f1 = 0.f; }
            s0 += w * f0;
            s1 += w * f1;
        }
    }
    size_t xb = (size_t)wid * 96;
    split_store(g_xh, g_xl, xb + lane,      s0 * zm);
    split_store(g_xh, g_xl, xb + 32 + lane, s1 * zm);

    int tdx = cam / V_;
    int vdx = cam % V_;
    int vmin = min(vdx, 63);
    float acc = pos_b[lane];
    #pragma unroll
    for (int i = 0; i < TE; i++)
        acc += g_temb[tdx*TE + i] * pos_w[i*32 + lane];
    #pragma unroll
    for (int i = 0; i < VE; i++)
        acc += view_emb[vmin*VE + i] * pos_w[(TE + i)*32 + lane];
    split_store(g_xh, g_xl, xb + 64 + lane, acc);
}

// ---------------- shared helpers for tensor-core GEMMs ----------------
__device__ __forceinline__ void mma16816(float* c, const uint32_t* a, uint32_t b0, uint32_t b1) {
    asm volatile(
        "mma.sync.aligned.m16n8k16.row.col.f32.f16.f16.f32 "
        "{%0,%1,%2,%3}, {%4,%5,%6,%7}, {%8,%9}, {%0,%1,%2,%3};\n"
        : "+f"(c[0]), "+f"(c[1]), "+f"(c[2]), "+f"(c[3])
        : "r"(a[0]), "r"(a[1]), "r"(a[2]), "r"(a[3]), "r"(b0), "r"(b1));
}
__device__ __forceinline__ void ldsm4(uint32_t* r, uint32_t addr) {
    asm volatile("ldmatrix.sync.aligned.m8n8.x4.shared.b16 {%0,%1,%2,%3}, [%4];"
        : "=r"(r[0]), "=r"(r[1]), "=r"(r[2]), "=r"(r[3]) : "r"(addr));
}
__device__ __forceinline__ void cpa16(uint32_t dst, const void* src, int sz) {
    asm volatile("cp.async.cg.shared.global [%0], [%1], 16, %2;\n" :: "r"(dst), "l"(src), "r"(sz));
}
__device__ __forceinline__ void cp_commit() { asm volatile("cp.async.commit_group;\n"); }
__device__ __forceinline__ void cp_wait0()  { asm volatile("cp.async.wait_group 0;\n"); }

extern __shared__ __half s_dyn[];

// ---- 2-MMA compensated GEMM: D = (31/32)*sum(Ah*Bh) + sum(Am8*Bm4) ----
// main GEMM: BM=BN=128, BK=32, 2-stage cp.async, LDSM, two k-passes.
// mode: 1=relu, 2=fp32 out, 4=half out.
#define SK 40
#define ARR_B (128*SK*2)                   // 10240
#define STG2_B (2*ARR_B)                   // 20480 (A+B per stage)

__global__ __launch_bounds__(256, 2)
void gemm_tc2(const __half* __restrict__ Ah, const __half* __restrict__ Am,
              const __half* __restrict__ Bh, const __half* __restrict__ Bm,
              const float* __restrict__ bias, float* __restrict__ C,
              __half* __restrict__ Ch, __half* __restrict__ Cm,
              int N, int Kd, int Nout, int mode)
{
    int bm = blockIdx.y * 128;
    int bn = blockIdx.x * 128;
    int tid = threadIdx.x;
    int wid = tid >> 5, lane = tid & 31;
    int g = lane >> 2, tc = lane & 3;
    int wm = (wid >> 2) * 64;
    int wn = (wid & 3) * 32;
    uint32_t sb = (uint32_t)__cvta_generic_to_shared(s_dyn);

    uint32_t a_off[4];
    #pragma unroll
    for (int i = 0; i < 4; i++)
        a_off[i] = (uint32_t)(((wm + i*16 + (lane & 15)) * SK + ((lane >> 4) << 3)) * 2);
    uint32_t b_off[2];
    #pragma unroll
    for (int jp = 0; jp < 2; jp++)
        b_off[jp] = (uint32_t)(((wn + jp*16 + (lane & 7) + ((lane >> 4) << 3)) * SK
                                + (((lane >> 3) & 1) << 3)) * 2);

    float acc[4][4][4];
    #pragma unroll
    for (int i = 0; i < 4; i++)
        #pragma unroll
        for (int j = 0; j < 4; j++)
            #pragma unroll
            for (int r = 0; r < 4; r++) acc[i][j][r] = 0.f;

    const int NT = Kd >> 5;

    auto load_stage = [&](int st, int k0, const __half* Ap, const __half* Bp) {
        #pragma unroll
        for (int r = 0; r < 2; r++) {
            int id  = tid + r*256;
            int row = id >> 2;
            int seg = id & 3;
            uint32_t d = sb + st*STG2_B + row*(SK*2) + seg*16;
            int gr = bm + row;
            bool va = gr < N;
            cpa16(d, Ap + (size_t)(va ? gr : 0) * Kd + k0 + seg*8, va ? 16 : 0);
            int gn = bn + row;
            bool vb = gn < Nout;
            cpa16(d + ARR_B, Bp + (size_t)(vb ? gn : 0) * Kd + k0 + seg*8, vb ? 16 : 0);
        }
        cp_commit();
    };

    auto kpass = [&](const __half* Ap, const __half* Bp) {
        load_stage(0, 0, Ap, Bp);
        for (int t = 0; t < NT; t++) {
            cp_wait0();
            __syncthreads();
            if (t + 1 < NT) load_stage((t+1) & 1, (t+1)*32, Ap, Bp);

            uint32_t sa  = sb + (t & 1)*STG2_B;
            uint32_t sbb = sa + ARR_B;

            #pragma unroll
            for (int kb = 0; kb < 32; kb += 16) {
                uint32_t kbB = kb * 2;
                uint32_t ah[4][4];
                #pragma unroll
                for (int i = 0; i < 4; i++)
                    ldsm4(ah[i], sa + a_off[i] + kbB);
                #pragma unroll
                for (int jp = 0; jp < 2; jp++) {
                    uint32_t bh[4];
                    ldsm4(bh, sbb + b_off[jp] + kbB);
                    #pragma unroll
                    for (int jj = 0; jj < 2; jj++) {
                        int j = jp*2 + jj;
                        #pragma unroll
                        for (int i = 0; i < 4; i++)
                            mma16816(acc[i][j], ah[i], bh[jj*2], bh[jj*2+1]);
                    }
                }
            }
        }
        __syncthreads();   // all reads done before next pass reloads buffers
    };

    kpass(Ah, Bh);
    #pragma unroll
    for (int i = 0; i < 4; i++)
        #pragma unroll
        for (int j = 0; j < 4; j++)
            #pragma unroll
            for (int r = 0; r < 4; r++) acc[i][j][r] *= (31.0f/32.0f);
    kpass(Am, Bm);

    bool relu  = mode & 1;
    bool wfp   = mode & 2;
    bool whalf = mode & 4;
    #pragma unroll
    for (int j = 0; j < 4; j++) {
        int col = bn + wn + j*8 + tc*2;
        if (col >= Nout) continue;
        float bx = bias[col], by = bias[col+1];
        #pragma unroll
        for (int i = 0; i < 4; i++) {
            int r0 = bm + wm + i*16 + g;
            int r1 = r0 + 8;
            float v0 = acc[i][j][0] + bx;
            float v1 = acc[i][j][1] + by;
            float v2 = acc[i][j][2] + bx;
            float v3 = acc[i][j][3] + by;
            if (relu) {
                v0 = fmaxf(v0, 0.f); v1 = fmaxf(v1, 0.f);
                v2 = fmaxf(v2, 0.f); v3 = fmaxf(v3, 0.f);
            }
            if (r0 < N) {
                size_t o = (size_t)r0*Nout + col;
                if (wfp) { C[o] = v0; C[o+1] = v1; }
                if (whalf) {
                    __half h0 = __float2half_rn(v0), h1 = __float2half_rn(v1);
                    float f0 = __half2float(h0), f1 = __half2float(h1);
                    *(__half2*)(Ch + o) = __halves2half2(h0, h1);
                    *(__half2*)(Cm + o) = __halves2half2(
                        __float2half_rn(f0*0.125f + 4.0f*(v0 - f0)),
                        __float2half_rn(f1*0.125f + 4.0f*(v1 - f1)));
                }
            }
            if (r1 < N) {
                size_t o = (size_t)r1*Nout + col;
                if (wfp) { C[o] = v2; C[o+1] = v3; }
                if (whalf) {
                    __half h2 = __float2half_rn(v2), h3 = __float2half_rn(v3);
                    float f2 = __half2float(h2), f3 = __half2float(h3);
                    *(__half2*)(Ch + o) = __halves2half2(h2, h3);
                    *(__half2*)(Cm + o) = __halves2half2(
                        __float2half_rn(f2*0.125f + 4.0f*(v2 - f2)),
                        __float2half_rn(f3*0.125f + 4.0f*(v3 - f3)));
                }
            }
        }
    }
}

// ---------------- fused GEMM + residual + LayerNorm (Nout=256 fixed), 2-MMA scheme ----------------
// BM=64, BN=256, 8 warps (2x4), warp tile 32x64. Writes h fp32 + half h/m8.
#define SKF   40
#define FA_B  (64*SKF*2)                   // 5120
#define FB_B  (256*SKF*2)                  // 20480
#define FSTG  (FA_B + FB_B)                // 25600 per stage
#define FRED  (2*FSTG)                     // 51200
#define FTOT  (FRED + 64*4*8)              // 53248

__global__ __launch_bounds__(256, 2)
void gemm_ln(const __half* __restrict__ Ah, const __half* __restrict__ Am,
             const __half* __restrict__ Bh, const __half* __restrict__ Bm,
             const float* __restrict__ bias,
             const float* __restrict__ lns, const float* __restrict__ lnb,
             float* __restrict__ Hres, __half* __restrict__ Ch, __half* __restrict__ Cm,
             int N, int Kd)
{
    int bm = blockIdx.x * 64;
    int tid = threadIdx.x;
    int wid = tid >> 5, lane = tid & 31;
    int g = lane >> 2, tc = lane & 3;
    int wr = wid >> 2;
    int wc = wid & 3;
    uint32_t sb = (uint32_t)__cvta_generic_to_shared(s_dyn);
    float2* red = (float2*)((char*)s_dyn + FRED);

    uint32_t a_off[2];
    #pragma unroll
    for (int i = 0; i < 2; i++)
        a_off[i] = (uint32_t)(((wr*32 + i*16 + (lane & 15)) * SKF + ((lane >> 4) << 3)) * 2);
    uint32_t b_off[4];
    #pragma unroll
    for (int jp = 0; jp < 4; jp++)
        b_off[jp] = (uint32_t)(((wc*64 + jp*16 + (lane & 7) + ((lane >> 4) << 3)) * SKF
                                + (((lane >> 3) & 1) << 3)) * 2);

    float acc[2][8][4];
    #pragma unroll
    for (int i = 0; i < 2; i++)
        #pragma unroll
        for (int j = 0; j < 8; j++)
            #pragma unroll
            for (int r = 0; r < 4; r++) acc[i][j][r] = 0.f;

    const int NT = Kd >> 5;

    auto load_stage = [&](int st, int k0, const __half* Ap, const __half* Bp) {
        {
            int row = tid >> 2, seg = tid & 3;
            uint32_t d = sb + st*FSTG + row*(SKF*2) + seg*16;
            int gr = bm + row;
            bool va = gr < N;
            cpa16(d, Ap + (size_t)(va ? gr : 0) * Kd + k0 + seg*8, va ? 16 : 0);
        }
        #pragma unroll
        for (int r = 0; r < 4; r++) {
            int id = tid + r*256;
            int row = id >> 2, seg = id & 3;
            uint32_t d = sb + st*FSTG + FA_B + row*(SKF*2) + seg*16;
            cpa16(d, Bp + (size_t)row * Kd + k0 + seg*8, 16);
        }
        cp_commit();
    };

    auto kpass = [&](const __half* Ap, const __half* Bp) {
        load_stage(0, 0, Ap, Bp);
        for (int t = 0; t < NT; t++) {
            cp_wait0();
            __syncthreads();
            if (t + 1 < NT) load_stage((t+1) & 1, (t+1)*32, Ap, Bp);

            uint32_t sa  = sb + (t & 1)*FSTG;
            uint32_t sbb = sa + FA_B;

            #pragma unroll
            for (int kb = 0; kb < 32; kb += 16) {
                uint32_t kbB = kb * 2;
                uint32_t ah[2][4];
                #pragma unroll
                for (int i = 0; i < 2; i++)
                    ldsm4(ah[i], sa + a_off[i] + kbB);
                #pragma unroll
                for (int jp = 0; jp < 4; jp++) {
                    uint32_t bh[4];
                    ldsm4(bh, sbb + b_off[jp] + kbB);
                    #pragma unroll
                    for (int jj = 0; jj < 2; jj++) {
                        int j = jp*2 + jj;
                        #pragma unroll
                        for (int i = 0; i < 2; i++)
                            mma16816(acc[i][j], ah[i], bh[jj*2], bh[jj*2+1]);
                    }
                }
            }
        }
        __syncthreads();
    };

    kpass(Ah, Bh);
    #pragma unroll
    for (int i = 0; i < 2; i++)
        #pragma unroll
        for (int j = 0; j < 8; j++)
            #pragma unroll
            for (int r = 0; r < 4; r++) acc[i][j][r] *= (31.0f/32.0f);
    kpass(Am, Bm);

    // ---- epilogue: x = h_old + (acc + bias); per-row LN over 256 cols ----
    int colw = wc*64;
    #pragma unroll
    for (int i = 0; i < 2; i++) {
        int rbase = wr*32 + i*16 + g;
        #pragma unroll
        for (int hhf = 0; hhf < 2; hhf++) {
            int rl = rbase + hhf*8;
            int grow = bm + rl;
            bool rv = grow < N;
            const float* hrow = Hres + (size_t)grow*256;
            float s1 = 0.f, s2 = 0.f;
            #pragma unroll
            for (int j = 0; j < 8; j++) {
                int col = colw + j*8 + tc*2;
                float2 hv = rv ? *(const float2*)(hrow + col) : make_float2(0.f, 0.f);
                float x0 = acc[i][j][hhf*2+0] + bias[col]   + hv.x;
                float x1 = acc[i][j][hhf*2+1] + bias[col+1] + hv.y;
                acc[i][j][hhf*2+0] = x0;
                acc[i][j][hhf*2+1] = x1;
                s1 += x0 + x1;
                s2 += x0*x0 + x1*x1;
            }
            s1 += __shfl_xor_sync(0xFFFFFFFFu, s1, 1);
            s1 += __shfl_xor_sync(0xFFFFFFFFu, s1, 2);
            s2 += __shfl_xor_sync(0xFFFFFFFFu, s2, 1);
            s2 += __shfl_xor_sync(0xFFFFFFFFu, s2, 2);
            if (tc == 0) red[(rl << 2) + wc] = make_float2(s1, s2);
        }
    }
    __syncthreads();
    #pragma unroll
    for (int i = 0; i < 2; i++) {
        int rbase = wr*32 + i*16 + g;
        #pragma unroll
        for (int hhf = 0; hhf < 2; hhf++) {
            int rl = rbase + hhf*8;
            int grow = bm + rl;
            if (grow >= N) continue;
            float2 t0 = red[(rl<<2)+0], t1 = red[(rl<<2)+1];
            float2 t2 = red[(rl<<2)+2], t3 = red[(rl<<2)+3];
            float tS  = t0.x + t1.x + t2.x + t3.x;
            float tS2 = t0.y + t1.y + t2.y + t3.y;
            float mu  = tS * (1.0f/256.0f);
            float var = tS2 * (1.0f/256.0f) - mu*mu;
            float rinv = rsqrtf(var + 1e-5f);
            float* hrow = Hres + (size_t)grow*256;
            size_t ob = (size_t)grow*256;
            #pragma unroll
            for (int j = 0; j < 8; j++) {
                int col = colw + j*8 + tc*2;
                float y0 = (acc[i][j][hhf*2+0] - mu)*rinv*lns[col]   + lnb[col];
                float y1 = (acc[i][j][hhf*2+1] - mu)*rinv*lns[col+1] + lnb[col+1];
                *(float2*)(hrow + col) = make_float2(y0, y1);
                __half h0 = __float2half_rn(y0), h1 = __float2half_rn(y1);
                float f0 = __half2float(h0), f1 = __half2float(h1);
                *(__half2*)(Ch + ob + col) = __halves2half2(h0, h1);
                *(__half2*)(Cm + ob + col) = __halves2half2(
                    __float2half_rn(f0*0.125f + 4.0f*(y0 - f0)),
                    __float2half_rn(f1*0.125f + 4.0f*(y1 - f1)));
            }
        }
    }
}

// ---------------- attention over 4 tokens, 8 heads, Dh=32 -> o h/m8 ----------------
__global__ __launch_bounds__(256)
void attn_kernel(int M)
{
    int m = blockIdx.x;
    if (m >= M) return;
    int h = threadIdx.x >> 5;
    int lane = threadIdx.x & 31;
    const float* qkv = g_qkv + (size_t)m * KSEL * 768;

    float q[4], k[4], v[4];
    #pragma unroll
    for (int j = 0; j < 4; j++) {
        q[j] = qkv[(size_t)j*768 +        h*32 + lane];
        k[j] = qkv[(size_t)j*768 + 256  + h*32 + lane];
        v[j] = qkv[(size_t)j*768 + 512  + h*32 + lane];
    }
    float s[16];
    #pragma unroll
    for (int i = 0; i < 4; i++)
        #pragma unroll
        for (int j = 0; j < 4; j++)
            s[i*4+j] = q[i] * k[j];
    #pragma unroll
    for (int off = 16; off > 0; off >>= 1)
        #pragma unroll
        for (int x = 0; x < 16; x++)
            s[x] += __shfl_xor_sync(0xFFFFFFFFu, s[x], off);

    const float scale = 0.17677669529663687f;
    float a[16];
    #pragma unroll
    for (int i = 0; i < 4; i++) {
        float s0 = s[i*4+0]*scale, s1 = s[i*4+1]*scale;
        float s2 = s[i*4+2]*scale, s3 = s[i*4+3]*scale;
        float mx = fmaxf(fmaxf(s0, s1), fmaxf(s2, s3));
        float e0 = expf(s0-mx), e1 = expf(s1-mx), e2 = expf(s2-mx), e3 = expf(s3-mx);
        float r = 1.0f / (e0+e1+e2+e3);
        a[i*4+0] = e0*r; a[i*4+1] = e1*r; a[i*4+2] = e2*r; a[i*4+3] = e3*r;
    }
    size_t ob = (size_t)m * KSEL * 256;
    #pragma unroll
    for (int i = 0; i < 4; i++) {
        float oi = a[i*4+0]*v[0] + a[i*4+1]*v[1] + a[i*4+2]*v[2] + a[i*4+3]*v[3];
        split_store(g_oh, g_ol, ob + (size_t)i*256 + h*32 + lane, oi);
    }
}

// ---------------- mean over the 4 tokens -> h/m8 ----------------
__global__ __launch_bounds__(256)
void mean_kernel(int M)
{
    int idx = blockIdx.x * blockDim.x + threadIdx.x;
    if (idx >= M*256) return;
    int m = idx >> 8, c = idx & 255;
    const float* hp = g_h + (size_t)m*4*256 + c;
    split_store(g_mh, g_ml, idx, 0.25f * (hp[0] + hp[256] + hp[512] + hp[768]));
}

// ---------------- host launch ----------------
extern "C" void kernel_launch(void* const* d_in, const int* in_sizes, int n_in,
                              void* d_out, int out_size)
{
    const float* xyz      = (const float*)d_in[0];
    const float* feat     = (const float*)d_in[1];
    const float* poses    = (const float*)d_in[2];
    const float* intr     = (const float*)d_in[3];
    const int*   time_ids = (const int*)  d_in[4];
    const float* view_emb = (const float*)d_in[5];
    const float* pos_w    = (const float*)d_in[6];
    const float* pos_b    = (const float*)d_in[7];
    const float* fp_w     = (const float*)d_in[8];
    const float* fp_b     = (const float*)d_in[9];
    const float* qkv_w    = (const float*)d_in[10];
    const float* qkv_b    = (const float*)d_in[11];
    const float* ao_w     = (const float*)d_in[12];
    const float* ao_b     = (const float*)d_in[13];
    const float* ln1_s    = (const float*)d_in[14];
    const float* ln1_b    = (const float*)d_in[15];
    const float* ff1_w    = (const float*)d_in[16];
    const float* ff1_b    = (const float*)d_in[17];
    const float* ff2_w    = (const float*)d_in[18];
    const float* ff2_b    = (const float*)d_in[19];
    const float* ln2_s    = (const float*)d_in[20];
    const float* ln2_b    = (const float*)d_in[21];
    const float* out_w    = (const float*)d_in[22];
    const float* out_b    = (const float*)d_in[23];

    int M    = in_sizes[0] / 3;
    int Ntok = M * KSEL;
    int T    = in_sizes[4];

    float *ph, *pqkv;
    __half *pxh,*pxl,*phh,*phl,*poh,*pol,*pfh,*pfl,*pmh,*pml,*pwh,*pwl;
    cudaGetSymbolAddress((void**)&ph,    g_h);
    cudaGetSymbolAddress((void**)&pqkv,  g_qkv);
    cudaGetSymbolAddress((void**)&pxh, g_xh); cudaGetSymbolAddress((void**)&pxl, g_xl);
    cudaGetSymbolAddress((void**)&phh, g_hh); cudaGetSymbolAddress((void**)&phl, g_hl);
    cudaGetSymbolAddress((void**)&poh, g_oh); cudaGetSymbolAddress((void**)&pol, g_ol);
    cudaGetSymbolAddress((void**)&pfh, g_fh); cudaGetSymbolAddress((void**)&pfl, g_fl);
    cudaGetSymbolAddress((void**)&pmh, g_mh); cudaGetSymbolAddress((void**)&pml, g_ml);
    cudaGetSymbolAddress((void**)&pwh, g_wh); cudaGetSymbolAddress((void**)&pwl, g_wl);

    cudaFuncSetAttribute(gemm_tc2, cudaFuncAttributeMaxDynamicSharedMemorySize, 2*STG2_B);
    cudaFuncSetAttribute(gemm_ln,  cudaFuncAttributeMaxDynamicSharedMemorySize, FTOT);

    const long long off_fp   = 0;
    const long long off_qkv0 = off_fp   + 24576;
    const long long off_qkv1 = off_qkv0 + 196608;
    const long long off_ao0  = off_qkv1 + 196608;
    const long long off_ao1  = off_ao0  + 65536;
    const long long off_ff10 = off_ao1  + 65536;
    const long long off_ff11 = off_ff10 + 131072;
    const long long off_ff20 = off_ff11 + 131072;
    const long long off_ff21 = off_ff20 + 131072;
    const long long off_out  = off_ff21 + 131072;

    WTab tab;
    tab.src[0]=fp_w;            tab.off[0]=off_fp;   tab.kd[0]=96;  tab.nout[0]=256;
    tab.src[1]=qkv_w;           tab.off[1]=off_qkv0; tab.kd[1]=256; tab.nout[1]=768;
    tab.src[2]=qkv_w+256*768;   tab.off[2]=off_qkv1; tab.kd[2]=256; tab.nout[2]=768;
    tab.src[3]=ao_w;            tab.off[3]=off_ao0;  tab.kd[3]=256; tab.nout[3]=256;
    tab.src[4]=ao_w+256*256;    tab.off[4]=off_ao1;  tab.kd[4]=256; tab.nout[4]=256;
    tab.src[5]=ff1_w;           tab.off[5]=off_ff10; tab.kd[5]=256; tab.nout[5]=512;
    tab.src[6]=ff1_w+256*512;   tab.off[6]=off_ff11; tab.kd[6]=256; tab.nout[6]=512;
    tab.src[7]=ff2_w;           tab.off[7]=off_ff20; tab.kd[7]=512; tab.nout[7]=256;
    tab.src[8]=ff2_w+512*256;   tab.off[8]=off_ff21; tab.kd[8]=512; tab.nout[8]=256;
    tab.src[9]=out_w;           tab.off[9]=off_out;  tab.kd[9]=256; tab.nout[9]=64;
    wconv_all<<<dim3(768, 10), 256>>>(tab, pwh, pwl);

    setup_kernel<<<1, 32>>>(poses, intr, time_ids, T);
    proj_topk_kernel<<<(M + 127)/128, 128>>>(xyz, M);
    gather_kernel<<<(Ntok*32 + 255)/256, 256>>>(feat, view_emb, pos_w, pos_b, Ntok);

    auto gemm = [&](const __half* Ahp, const __half* Amp, long long woff,
                    const float* bias, float* C, __half* Ch, __half* Cm,
                    int N, int Kd, int Nout, int mode) {
        dim3 grid((Nout + 127)/128, (N + 127)/128);
        gemm_tc2<<<grid, 256, 2*STG2_B>>>(Ahp, Amp, pwh + woff, pwl + woff,
                                          bias, C, Ch, Cm, N, Kd, Nout, mode);
    };

    // fp: xin -> h (fp32 + halves)
    gemm(pxh, pxl, off_fp, fp_b, ph, phh, phl, Ntok, 96, 256, 2|4);

    const long long qoff[2]  = {off_qkv0, off_qkv1};
    const long long aoff[2]  = {off_ao0,  off_ao1};
    const long long f1off[2] = {off_ff10, off_ff11};
    const long long f2off[2] = {off_ff20, off_ff21};
    int gln = (Ntok + 63)/64;
    for (int l = 0; l < 2; l++) {
        gemm(phh, phl, qoff[l], qkv_b + l*768, pqkv, nullptr, nullptr, Ntok, 256, 768, 2);
        attn_kernel<<<M, 256>>>(M);
        gemm_ln<<<gln, 256, FTOT>>>(poh, pol, pwh + aoff[l], pwl + aoff[l],
                                    ao_b + l*256, ln1_s + l*256, ln1_b + l*256,
                                    ph, phh, phl, Ntok, 256);
        gemm(phh, phl, f1off[l], ff1_b + l*512, nullptr, pfh, pfl, Ntok, 256, 512, 4|1);
        gemm_ln<<<gln, 256, FTOT>>>(pfh, pfl, pwh + f2off[l], pwl + f2off[l],
                                    ff2_b + l*256, ln2_s + l*256, ln2_b + l*256,
                                    ph, phh, phl, Ntok, 512);
    }

    mean_kernel<<<(M*256 + 255)/256, 256>>>(M);
    gemm(pmh, pml, off_out, out_b, (float*)d_out, nullptr, nullptr, M, 256, 64, 2);
}

// round 13
// speedup vs baseline: 2.6831x; 1.0904x over previous
// v13: 2-MMA compensated GEMM, unified h/m loop + BK=64
#include <cuda_runtime.h>
#include <cuda_fp16.h>
#include <math.h>
#include <stdint.h>

// ---------------- problem constants ----------------
#define T_    4
#define V_    8
#define TVC   32
#define HP    64
#define WP    64
#define C_    64
#define KSEL  4
#define HID   256
#define TE    32
#define VE    16
#define MAXM  50000
#define MAXTOK (MAXM*KSEL)

// ---------------- scratch ----------------
__device__ float g_P[TVC*12];
__device__ float g_scal[4];
__device__ float g_temb[T_*TE];
__device__ int   g_selcam[MAXTOK];
__device__ float g_selu[MAXTOK];
__device__ float g_selv[MAXTOK];
__device__ float g_selz[MAXTOK];

// fp32 intermediates
__device__ float g_h   [(size_t)MAXTOK*256];
__device__ float g_qkv [(size_t)MAXTOK*768];

// half (h, m/8) activation buffers
__device__ __half g_xh[(size_t)MAXTOK*96],  g_xl[(size_t)MAXTOK*96];
__device__ __half g_hh[(size_t)MAXTOK*256], g_hl[(size_t)MAXTOK*256];
__device__ __half g_oh[(size_t)MAXTOK*256], g_ol[(size_t)MAXTOK*256];
__device__ __half g_fh[(size_t)MAXTOK*512], g_fl[(size_t)MAXTOK*512];
__device__ __half g_mh[(size_t)MAXM*256],   g_ml[(size_t)MAXM*256];

// preconverted transposed weights [Nout][Kd], (h, m/4)
#define WTOTAL 1089536
__device__ __half g_wh[WTOTAL], g_wl[WTOTAL];

// ---------------- setup ----------------
__global__ void setup_kernel(const float* __restrict__ poses,
                             const float* __restrict__ intr,
                             const int*   __restrict__ time_ids,
                             int T)
{
    int n = threadIdx.x;
    if (n < TVC) {
        double a[4][8];
        for (int r = 0; r < 4; r++)
            for (int c = 0; c < 4; c++) {
                a[r][c]   = (double)poses[n*16 + r*4 + c];
                a[r][4+c] = (r == c) ? 1.0 : 0.0;
            }
        for (int col = 0; col < 4; col++) {
            int piv = col;
            for (int r = col+1; r < 4; r++)
                if (fabs(a[r][col]) > fabs(a[piv][col])) piv = r;
            if (piv != col)
                for (int c = 0; c < 8; c++) { double t = a[col][c]; a[col][c] = a[piv][c]; a[piv][c] = t; }
            double dv = a[col][col];
            for (int c = 0; c < 8; c++) a[col][c] /= dv;
            for (int r = 0; r < 4; r++) if (r != col) {
                double f = a[r][col];
                for (int c = 0; c < 8; c++) a[r][c] -= f * a[col][c];
            }
        }
        double Km[9];
        for (int i = 0; i < 9; i++) Km[i] = (double)intr[n*9 + i];
        for (int r = 0; r < 3; r++)
            for (int c = 0; c < 4; c++) {
                double s = 0.0;
                for (int j = 0; j < 3; j++) s += Km[r*3 + j] * a[j][4 + c];
                g_P[n*12 + r*4 + c] = (float)s;
            }
    }
    if (n == 0) {
        float cx = intr[2], cy = intr[5];
        float W = 2.0f*cx, H = 2.0f*cy;
        g_scal[0] = W; g_scal[1] = H;
        g_scal[2] = (float)WP / fmaxf(1.0f, W);
        g_scal[3] = (float)HP / fmaxf(1.0f, H);
        int tmin = time_ids[0], tmax = time_ids[0];
        for (int t = 1; t < T; t++) {
            int v = time_ids[t];
            if (v < tmin) tmin = v;
            if (v > tmax) tmax = v;
        }
        if (tmax < tmin + 1) tmax = tmin + 1;
        for (int t = 0; t < T; t++) {
            double tn = (double)(time_ids[t] - tmin) / (double)(tmax - tmin);
            for (int i = 0; i < TE/2; i++) {
                double f  = exp(8.0 * (double)i / (double)(TE/2 - 1));
                double ph = tn * f;
                g_temb[t*TE + i]        = (float)sin(ph);
                g_temb[t*TE + TE/2 + i] = (float)cos(ph);
            }
        }
    }
}

// ---------------- single-launch weight convert + transpose ----------------
// Wh = RN(w); Wm4 = RN(h/4 + 8*(w-h))
struct WTab {
    const float* src[10];
    long long    off[10];
    int          kd[10];
    int          nout[10];
};
__global__ __launch_bounds__(256)
void wconv_all(WTab tab, __half* __restrict__ Wh, __half* __restrict__ Wl)
{
    int mi  = blockIdx.y;
    int idx = blockIdx.x * blockDim.x + threadIdx.x;
    int Kd = tab.kd[mi], Nout = tab.nout[mi];
    if (idx >= Kd * Nout) return;
    int n = idx / Kd, k = idx - n*Kd;
    float w = tab.src[mi][(size_t)k*Nout + n];
    __half h = __float2half_rn(w);
    float hf = __half2float(h);
    float l  = w - hf;
    size_t o = (size_t)tab.off[mi] + idx;
    Wh[o] = h;
    Wl[o] = __float2half_rn(hf*0.25f + 8.0f*l);
}

// ---------------- per-point projection + stable top-4 ----------------
__global__ __launch_bounds__(128)
void proj_topk_kernel(const float* __restrict__ xyz, int M)
{
    int m = blockIdx.x * blockDim.x + threadIdx.x;
    if (m >= M) return;
    float X = xyz[3*m+0], Y = xyz[3*m+1], Z = xyz[3*m+2];
    float W = g_scal[0], H = g_scal[1];

    float bs[KSEL] = {-1.f,-1.f,-1.f,-1.f};
    int   bi[KSEL] = {1000,1000,1000,1000};
    float bu[KSEL], bv[KSEL], bz[KSEL];
    #pragma unroll
    for (int q = 0; q < KSEL; q++) { bu[q]=0; bv[q]=0; bz[q]=0; }

    for (int cam = 0; cam < TVC; cam++) {
        const float* P = g_P + cam*12;
        float uw = P[0]*X + P[1]*Y + P[2] *Z + P[3];
        float vw = P[4]*X + P[5]*Y + P[6] *Z + P[7];
        float z  = P[8]*X + P[9]*Y + P[10]*Z + P[11];
        float wd = fmaxf(z, 1e-6f);
        float u = uw / wd, v = vw / wd;
        bool vis = (z > 1e-4f) && (u >= 0.f) && (u < W) && (v >= 0.f) && (v < H);
        float score = vis ? (1.0f / (fmaxf(z, 0.1f) + 1e-6f)) : 0.0f;
        #pragma unroll
        for (int slot = 0; slot < KSEL; slot++) {
            bool better = (score > bs[slot]) || (score == bs[slot] && cam < bi[slot]);
            if (better) {
                for (int q = KSEL-1; q > slot; q--) {
                    bs[q]=bs[q-1]; bi[q]=bi[q-1]; bu[q]=bu[q-1]; bv[q]=bv[q-1]; bz[q]=bz[q-1];
                }
                bs[slot]=score; bi[slot]=cam; bu[slot]=u; bv[slot]=v; bz[slot]=z;
                break;
            }
        }
    }
    #pragma unroll
    for (int q = 0; q < KSEL; q++) {
        int t = m*KSEL + q;
        g_selcam[t] = bi[q];
        g_selu[t] = bu[q]; g_selv[t] = bv[q]; g_selz[t] = bz[q];
    }
}

// Activation split: h = RN(v), m8 = RN(h/8 + 4*(v-h))
__device__ __forceinline__ void split_store(__half* hp, __half* mp, size_t idx, float v) {
    __half h = __float2half_rn(v);
    float hf = __half2float(h);
    float l  = v - hf;
    hp[idx] = h;
    mp[idx] = __float2half_rn(hf*0.125f + 4.0f*l);
}

// ---------------- bilinear gather + pos feats -> xin h/m8 [Ntok,96] ----------------
__global__ __launch_bounds__(256)
void gather_kernel(const float* __restrict__ feat,
                   const float* __restrict__ view_emb,
                   const float* __restrict__ pos_w,
                   const float* __restrict__ pos_b,
                   int Ntok)
{
    int wid  = (blockIdx.x * blockDim.x + threadIdx.x) >> 5;
    int lane = threadIdx.x & 31;
    if (wid >= Ntok) return;

    int   cam = g_selcam[wid];
    float u = g_selu[wid], v = g_selv[wid], z = g_selz[wid];
    float uf = u * g_scal[2], vf = v * g_scal[3];
    float x0f = floorf(uf), y0f = floorf(vf);
    float fx = uf - x0f, fy = vf - y0f;
    int x0 = (int)x0f, y0 = (int)y0f;
    float w00 = (1.f-fx)*(1.f-fy);
    float w01 = fx*(1.f-fy);
    float w10 = (1.f-fx)*fy;
    float w11 = fx*fy;
    float zm  = (z > 1e-4f) ? 1.0f : 0.0f;

    float s0 = 0.f, s1 = 0.f;
    #pragma unroll
    for (int dy = 0; dy < 2; dy++) {
        #pragma unroll
        for (int dx = 0; dx < 2; dx++) {
            int xi = x0 + dx, yi = y0 + dy;
            bool val = (xi >= 0) && (xi < WP) && (yi >= 0) && (yi < HP);
            int xc = min(max(xi, 0), WP-1);
            int yc = min(max(yi, 0), HP-1);
            size_t base = (((size_t)cam*HP + yc)*WP + xc) * C_;
            float w = dy ? (dx ? w11 : w10) : (dx ? w01 : w00);
            float f0 = feat[base + lane];
            float f1 = feat[base + lane + 32];
            if (!val) { f0 = 0.f; f1 = 0.f; }
            s0 += w * f0;
            s1 += w * f1;
        }
    }
    size_t xb = (size_t)wid * 96;
    split_store(g_xh, g_xl, xb + lane,      s0 * zm);
    split_store(g_xh, g_xl, xb + 32 + lane, s1 * zm);

    int tdx = cam / V_;
    int vdx = cam % V_;
    int vmin = min(vdx, 63);
    float acc = pos_b[lane];
    #pragma unroll
    for (int i = 0; i < TE; i++)
        acc += g_temb[tdx*TE + i] * pos_w[i*32 + lane];
    #pragma unroll
    for (int i = 0; i < VE; i++)
        acc += view_emb[vmin*VE + i] * pos_w[(TE + i)*32 + lane];
    split_store(g_xh, g_xl, xb + 64 + lane, acc);
}

// ---------------- shared helpers ----------------
__device__ __forceinline__ void mma16816(float* c, const uint32_t* a, uint32_t b0, uint32_t b1) {
    asm volatile(
        "mma.sync.aligned.m16n8k16.row.col.f32.f16.f16.f32 "
        "{%0,%1,%2,%3}, {%4,%5,%6,%7}, {%8,%9}, {%0,%1,%2,%3};\n"
        : "+f"(c[0]), "+f"(c[1]), "+f"(c[2]), "+f"(c[3])
        : "r"(a[0]), "r"(a[1]), "r"(a[2]), "r"(a[3]), "r"(b0), "r"(b1));
}
__device__ __forceinline__ void ldsm4(uint32_t* r, uint32_t addr) {
    asm volatile("ldmatrix.sync.aligned.m8n8.x4.shared.b16 {%0,%1,%2,%3}, [%4];"
        : "=r"(r[0]), "=r"(r[1]), "=r"(r[2]), "=r"(r[3]) : "r"(addr));
}
__device__ __forceinline__ void cpa16(uint32_t dst, const void* src, int sz) {
    asm volatile("cp.async.cg.shared.global [%0], [%1], 16, %2;\n" :: "r"(dst), "l"(src), "r"(sz));
}
__device__ __forceinline__ void cp_commit() { asm volatile("cp.async.commit_group;\n"); }
__device__ __forceinline__ void cp_wait0()  { asm volatile("cp.async.wait_group 0;\n"); }

extern __shared__ __half s_dyn[];

// ---- 2-MMA compensated GEMM, BK=64, unified h/m loop ----
// D = (31/32)*sum(Ah*Bh) + sum(Am8*Bm4). mode: 1=relu, 2=fp32 out, 4=half out.
#define SKB 72                              // halves per smem row (144 B)
#define A2_B (128*SKB*2)                    // 18432 per array
#define ST2_B (2*A2_B)                      // 36864 per stage (A+B)

__global__ __launch_bounds__(256, 2)
void gemm_tc2(const __half* __restrict__ Ah, const __half* __restrict__ Am,
              const __half* __restrict__ Bh, const __half* __restrict__ Bm,
              const float* __restrict__ bias, float* __restrict__ C,
              __half* __restrict__ Ch, __half* __restrict__ Cm,
              int N, int Kd, int Nout, int mode)
{
    int bm = blockIdx.y * 128;
    int bn = blockIdx.x * 128;
    int tid = threadIdx.x;
    int wid = tid >> 5, lane = tid & 31;
    int g = lane >> 2, tc = lane & 3;
    int wm = (wid >> 2) * 64;
    int wn = (wid & 3) * 32;
    uint32_t sb = (uint32_t)__cvta_generic_to_shared(s_dyn);

    uint32_t a_off[4];
    #pragma unroll
    for (int i = 0; i < 4; i++)
        a_off[i] = (uint32_t)(((wm + i*16 + (lane & 15)) * SKB + ((lane >> 4) << 3)) * 2);
    uint32_t b_off[2];
    #pragma unroll
    for (int jp = 0; jp < 2; jp++)
        b_off[jp] = (uint32_t)(((wn + jp*16 + (lane & 7) + ((lane >> 4) << 3)) * SKB
                                + (((lane >> 3) & 1) << 3)) * 2);

    float acc[4][4][4];
    #pragma unroll
    for (int i = 0; i < 4; i++)
        #pragma unroll
        for (int j = 0; j < 4; j++)
            #pragma unroll
            for (int r = 0; r < 4; r++) acc[i][j][r] = 0.f;

    const int NTt = (Kd + 63) >> 6;

    auto load_stage = [&](int st, int k0, const __half* Ap, const __half* Bp) {
        // A: 128 rows x 8 segs = 1024 slots
        #pragma unroll
        for (int r = 0; r < 4; r++) {
            int id  = tid + r*256;
            int row = id >> 3, seg = id & 7;
            uint32_t d = sb + st*ST2_B + row*(SKB*2) + seg*16;
            int gr = bm + row;
            int kk = k0 + seg*8;
            bool ok = (gr < N) && (kk + 8 <= Kd);
            cpa16(d, Ap + (size_t)(ok ? gr : 0) * Kd + (ok ? kk : 0), ok ? 16 : 0);
        }
        // B: 128 rows x 8 segs = 1024 slots
        #pragma unroll
        for (int r = 0; r < 4; r++) {
            int id  = tid + r*256;
            int row = id >> 3, seg = id & 7;
            uint32_t d = sb + st*ST2_B + A2_B + row*(SKB*2) + seg*16;
            int gn = bn + row;
            int kk = k0 + seg*8;
            bool ok = (gn < Nout) && (kk + 8 <= Kd);
            cpa16(d, Bp + (size_t)(ok ? gn : 0) * Kd + (ok ? kk : 0), ok ? 16 : 0);
        }
        cp_commit();
    };

    load_stage(0, 0, Ah, Bh);

    const int NT2 = 2 * NTt;
    for (int t = 0; t < NT2; t++) {
        cp_wait0();
        __syncthreads();
        int tn = t + 1;
        if (tn < NT2) {
            bool m2 = tn >= NTt;
            load_stage(tn & 1, (m2 ? tn - NTt : tn) * 64, m2 ? Am : Ah, m2 ? Bm : Bh);
        }
        if (t == NTt) {
            #pragma unroll
            for (int i = 0; i < 4; i++)
                #pragma unroll
                for (int j = 0; j < 4; j++)
                    #pragma unroll
                    for (int r = 0; r < 4; r++) acc[i][j][r] *= (31.0f/32.0f);
        }

        uint32_t sa  = sb + (t & 1)*ST2_B;
        uint32_t sbb = sa + A2_B;

        #pragma unroll
        for (int kb = 0; kb < 64; kb += 16) {
            uint32_t kbB = kb * 2;
            uint32_t ah[4][4];
            #pragma unroll
            for (int i = 0; i < 4; i++)
                ldsm4(ah[i], sa + a_off[i] + kbB);
            #pragma unroll
            for (int jp = 0; jp < 2; jp++) {
                uint32_t bh[4];
                ldsm4(bh, sbb + b_off[jp] + kbB);
                #pragma unroll
                for (int jj = 0; jj < 2; jj++) {
                    int j = jp*2 + jj;
                    #pragma unroll
                    for (int i = 0; i < 4; i++)
                        mma16816(acc[i][j], ah[i], bh[jj*2], bh[jj*2+1]);
                }
            }
        }
        __syncthreads();
    }

    bool relu  = mode & 1;
    bool wfp   = mode & 2;
    bool whalf = mode & 4;
    #pragma unroll
    for (int j = 0; j < 4; j++) {
        int col = bn + wn + j*8 + tc*2;
        if (col >= Nout) continue;
        float bx = bias[col], by = bias[col+1];
        #pragma unroll
        for (int i = 0; i < 4; i++) {
            int r0 = bm + wm + i*16 + g;
            int r1 = r0 + 8;
            float v0 = acc[i][j][0] + bx;
            float v1 = acc[i][j][1] + by;
            float v2 = acc[i][j][2] + bx;
            float v3 = acc[i][j][3] + by;
            if (relu) {
                v0 = fmaxf(v0, 0.f); v1 = fmaxf(v1, 0.f);
                v2 = fmaxf(v2, 0.f); v3 = fmaxf(v3, 0.f);
            }
            if (r0 < N) {
                size_t o = (size_t)r0*Nout + col;
                if (wfp) { C[o] = v0; C[o+1] = v1; }
                if (whalf) {
                    __half h0 = __float2half_rn(v0), h1 = __float2half_rn(v1);
                    float f0 = __half2float(h0), f1 = __half2float(h1);
                    *(__half2*)(Ch + o) = __halves2half2(h0, h1);
                    *(__half2*)(Cm + o) = __halves2half2(
                        __float2half_rn(f0*0.125f + 4.0f*(v0 - f0)),
                        __float2half_rn(f1*0.125f + 4.0f*(v1 - f1)));
                }
            }
            if (r1 < N) {
                size_t o = (size_t)r1*Nout + col;
                if (wfp) { C[o] = v2; C[o+1] = v3; }
                if (whalf) {
                    __half h2 = __float2half_rn(v2), h3 = __float2half_rn(v3);
                    float f2 = __half2float(h2), f3 = __half2float(h3);
                    *(__half2*)(Ch + o) = __halves2half2(h2, h3);
                    *(__half2*)(Cm + o) = __halves2half2(
                        __float2half_rn(f2*0.125f + 4.0f*(v2 - f2)),
                        __float2half_rn(f3*0.125f + 4.0f*(v3 - f3)));
                }
            }
        }
    }
}

// ---------------- fused GEMM + residual + LayerNorm (Nout=256), BK=64, unified loop ----------------
#define FA2_B (64*SKB*2)                    // 9216
#define FB2_B (256*SKB*2)                   // 36864
#define FST2  (FA2_B + FB2_B)               // 46080 per stage
#define FRED2 (2*FST2)                      // 92160
#define FTOT2 (FRED2 + 64*4*8)              // 94208

__global__ __launch_bounds__(256, 2)
void gemm_ln(const __half* __restrict__ Ah, const __half* __restrict__ Am,
             const __half* __restrict__ Bh, const __half* __restrict__ Bm,
             const float* __restrict__ bias,
             const float* __restrict__ lns, const float* __restrict__ lnb,
             float* __restrict__ Hres, __half* __restrict__ Ch, __half* __restrict__ Cm,
             int N, int Kd)
{
    int bm = blockIdx.x * 64;
    int tid = threadIdx.x;
    int wid = tid >> 5, lane = tid & 31;
    int g = lane >> 2, tc = lane & 3;
    int wr = wid >> 2;
    int wc = wid & 3;
    uint32_t sb = (uint32_t)__cvta_generic_to_shared(s_dyn);
    float2* red = (float2*)((char*)s_dyn + FRED2);

    uint32_t a_off[2];
    #pragma unroll
    for (int i = 0; i < 2; i++)
        a_off[i] = (uint32_t)(((wr*32 + i*16 + (lane & 15)) * SKB + ((lane >> 4) << 3)) * 2);
    uint32_t b_off[4];
    #pragma unroll
    for (int jp = 0; jp < 4; jp++)
        b_off[jp] = (uint32_t)(((wc*64 + jp*16 + (lane & 7) + ((lane >> 4) << 3)) * SKB
                                + (((lane >> 3) & 1) << 3)) * 2);

    float acc[2][8][4];
    #pragma unroll
    for (int i = 0; i < 2; i++)
        #pragma unroll
        for (int j = 0; j < 8; j++)
            #pragma unroll
            for (int r = 0; r < 4; r++) acc[i][j][r] = 0.f;

    const int NTt = (Kd + 63) >> 6;

    auto load_stage = [&](int st, int k0, const __half* Ap, const __half* Bp) {
        // A: 64 rows x 8 segs = 512 slots
        #pragma unroll
        for (int r = 0; r < 2; r++) {
            int id  = tid + r*256;
            int row = id >> 3, seg = id & 7;
            uint32_t d = sb + st*FST2 + row*(SKB*2) + seg*16;
            int gr = bm + row;
            int kk = k0 + seg*8;
            bool ok = (gr < N) && (kk + 8 <= Kd);
            cpa16(d, Ap + (size_t)(ok ? gr : 0) * Kd + (ok ? kk : 0), ok ? 16 : 0);
        }
        // B: 256 rows x 8 segs = 2048 slots
        #pragma unroll
        for (int r = 0; r < 8; r++) {
            int id  = tid + r*256;
            int row = id >> 3, seg = id & 7;
            uint32_t d = sb + st*FST2 + FA2_B + row*(SKB*2) + seg*16;
            int kk = k0 + seg*8;
            bool ok = (kk + 8 <= Kd);
            cpa16(d, Bp + (size_t)row * Kd + (ok ? kk : 0), ok ? 16 : 0);
        }
        cp_commit();
    };

    load_stage(0, 0, Ah, Bh);

    const int NT2 = 2 * NTt;
    for (int t = 0; t < NT2; t++) {
        cp_wait0();
        __syncthreads();
        int tn = t + 1;
        if (tn < NT2) {
            bool m2 = tn >= NTt;
            load_stage(tn & 1, (m2 ? tn - NTt : tn) * 64, m2 ? Am : Ah, m2 ? Bm : Bh);
        }
        if (t == NTt) {
            #pragma unroll
            for (int i = 0; i < 2; i++)
                #pragma unroll
                for (int j = 0; j < 8; j++)
                    #pragma unroll
                    for (int r = 0; r < 4; r++) acc[i][j][r] *= (31.0f/32.0f);
        }

        uint32_t sa  = sb + (t & 1)*FST2;
        uint32_t sbb = sa + FA2_B;

        #pragma unroll
        for (int kb = 0; kb < 64; kb += 16) {
            uint32_t kbB = kb * 2;
            uint32_t ah[2][4];
            #pragma unroll
            for (int i = 0; i < 2; i++)
                ldsm4(ah[i], sa + a_off[i] + kbB);
            #pragma unroll
            for (int jp = 0; jp < 4; jp++) {
                uint32_t bh[4];
                ldsm4(bh, sbb + b_off[jp] + kbB);
                #pragma unroll
                for (int jj = 0; jj < 2; jj++) {
                    int j = jp*2 + jj;
                    #pragma unroll
                    for (int i = 0; i < 2; i++)
                        mma16816(acc[i][j], ah[i], bh[jj*2], bh[jj*2+1]);
                }
            }
        }
        __syncthreads();
    }

    // ---- epilogue: x = h_old + (acc + bias); per-row LN over 256 cols ----
    int colw = wc*64;
    #pragma unroll
    for (int i = 0; i < 2; i++) {
        int rbase = wr*32 + i*16 + g;
        #pragma unroll
        for (int hhf = 0; hhf < 2; hhf++) {
            int rl = rbase + hhf*8;
            int grow = bm + rl;
            bool rv = grow < N;
            const float* hrow = Hres + (size_t)grow*256;
            float s1 = 0.f, s2 = 0.f;
            #pragma unroll
            for (int j = 0; j < 8; j++) {
                int col = colw + j*8 + tc*2;
                float2 hv = rv ? *(const float2*)(hrow + col) : make_float2(0.f, 0.f);
                float x0 = acc[i][j][hhf*2+0] + bias[col]   + hv.x;
                float x1 = acc[i][j][hhf*2+1] + bias[col+1] + hv.y;
                acc[i][j][hhf*2+0] = x0;
                acc[i][j][hhf*2+1] = x1;
                s1 += x0 + x1;
                s2 += x0*x0 + x1*x1;
            }
            s1 += __shfl_xor_sync(0xFFFFFFFFu, s1, 1);
            s1 += __shfl_xor_sync(0xFFFFFFFFu, s1, 2);
            s2 += __shfl_xor_sync(0xFFFFFFFFu, s2, 1);
            s2 += __shfl_xor_sync(0xFFFFFFFFu, s2, 2);
            if (tc == 0) red[(rl << 2) + wc] = make_float2(s1, s2);
        }
    }
    __syncthreads();
    #pragma unroll
    for (int i = 0; i < 2; i++) {
        int rbase = wr*32 + i*16 + g;
        #pragma unroll
        for (int hhf = 0; hhf < 2; hhf++) {
            int rl = rbase + hhf*8;
            int grow = bm + rl;
            if (grow >= N) continue;
            float2 t0 = red[(rl<<2)+0], t1 = red[(rl<<2)+1];
            float2 t2 = red[(rl<<2)+2], t3 = red[(rl<<2)+3];
            float tS  = t0.x + t1.x + t2.x + t3.x;
            float tS2 = t0.y + t1.y + t2.y + t3.y;
            float mu  = tS * (1.0f/256.0f);
            float var = tS2 * (1.0f/256.0f) - mu*mu;
            float rinv = rsqrtf(var + 1e-5f);
            float* hrow = Hres + (size_t)grow*256;
            size_t ob = (size_t)grow*256;
            #pragma unroll
            for (int j = 0; j < 8; j++) {
                int col = colw + j*8 + tc*2;
                float y0 = (acc[i][j][hhf*2+0] - mu)*rinv*lns[col]   + lnb[col];
                float y1 = (acc[i][j][hhf*2+1] - mu)*rinv*lns[col+1] + lnb[col+1];
                *(float2*)(hrow + col) = make_float2(y0, y1);
                __half h0 = __float2half_rn(y0), h1 = __float2half_rn(y1);
                float f0 = __half2float(h0), f1 = __half2float(h1);
                *(__half2*)(Ch + ob + col) = __halves2half2(h0, h1);
                *(__half2*)(Cm + ob + col) = __halves2half2(
                    __float2half_rn(f0*0.125f + 4.0f*(y0 - f0)),
                    __float2half_rn(f1*0.125f + 4.0f*(y1 - f1)));
            }
        }
    }
}

// ---------------- attention over 4 tokens, 8 heads, Dh=32 -> o h/m8 ----------------
__global__ __launch_bounds__(256)
void attn_kernel(int M)
{
    int m = blockIdx.x;
    if (m >= M) return;
    int h = threadIdx.x >> 5;
    int lane = threadIdx.x & 31;
    const float* qkv = g_qkv + (size_t)m * KSEL * 768;

    float q[4], k[4], v[4];
    #pragma unroll
    for (int j = 0; j < 4; j++) {
        q[j] = qkv[(size_t)j*768 +        h*32 + lane];
        k[j] = qkv[(size_t)j*768 + 256  + h*32 + lane];
        v[j] = qkv[(size_t)j*768 + 512  + h*32 + lane];
    }
    float s[16];
    #pragma unroll
    for (int i = 0; i < 4; i++)
        #pragma unroll
        for (int j = 0; j < 4; j++)
            s[i*4+j] = q[i] * k[j];
    #pragma unroll
    for (int off = 16; off > 0; off >>= 1)
        #pragma unroll
        for (int x = 0; x < 16; x++)
            s[x] += __shfl_xor_sync(0xFFFFFFFFu, s[x], off);

    const float scale = 0.17677669529663687f;
    float a[16];
    #pragma unroll
    for (int i = 0; i < 4; i++) {
        float s0 = s[i*4+0]*scale, s1 = s[i*4+1]*scale;
        float s2 = s[i*4+2]*scale, s3 = s[i*4+3]*scale;
        float mx = fmaxf(fmaxf(s0, s1), fmaxf(s2, s3));
        float e0 = expf(s0-mx), e1 = expf(s1-mx), e2 = expf(s2-mx), e3 = expf(s3-mx);
        float r = 1.0f / (e0+e1+e2+e3);
        a[i*4+0] = e0*r; a[i*4+1] = e1*r; a[i*4+2] = e2*r; a[i*4+3] = e3*r;
    }
    size_t ob = (size_t)m * KSEL * 256;
    #pragma unroll
    for (int i = 0; i < 4; i++) {
        float oi = a[i*4+0]*v[0] + a[i*4+1]*v[1] + a[i*4+2]*v[2] + a[i*4+3]*v[3];
        split_store(g_oh, g_ol, ob + (size_t)i*256 + h*32 + lane, oi);
    }
}

// ---------------- mean over the 4 tokens -> h/m8 ----------------
__global__ __launch_bounds__(256)
void mean_kernel(int M)
{
    int idx = blockIdx.x * blockDim.x + threadIdx.x;
    if (idx >= M*256) return;
    int m = idx >> 8, c = idx & 255;
    const float* hp = g_h + (size_t)m*4*256 + c;
    split_store(g_mh, g_ml, idx, 0.25f * (hp[0] + hp[256] + hp[512] + hp[768]));
}

// ---------------- host launch ----------------
extern "C" void kernel_launch(void* const* d_in, const int* in_sizes, int n_in,
                              void* d_out, int out_size)
{
    const float* xyz      = (const float*)d_in[0];
    const float* feat     = (const float*)d_in[1];
    const float* poses    = (const float*)d_in[2];
    const float* intr     = (const float*)d_in[3];
    const int*   time_ids = (const int*)  d_in[4];
    const float* view_emb = (const float*)d_in[5];
    const float* pos_w    = (const float*)d_in[6];
    const float* pos_b    = (const float*)d_in[7];
    const float* fp_w     = (const float*)d_in[8];
    const float* fp_b     = (const float*)d_in[9];
    const float* qkv_w    = (const float*)d_in[10];
    const float* qkv_b    = (const float*)d_in[11];
    const float* ao_w     = (const float*)d_in[12];
    const float* ao_b     = (const float*)d_in[13];
    const float* ln1_s    = (const float*)d_in[14];
    const float* ln1_b    = (const float*)d_in[15];
    const float* ff1_w    = (const float*)d_in[16];
    const float* ff1_b    = (const float*)d_in[17];
    const float* ff2_w    = (const float*)d_in[18];
    const float* ff2_b    = (const float*)d_in[19];
    const float* ln2_s    = (const float*)d_in[20];
    const float* ln2_b    = (const float*)d_in[21];
    const float* out_w    = (const float*)d_in[22];
    const float* out_b    = (const float*)d_in[23];

    int M    = in_sizes[0] / 3;
    int Ntok = M * KSEL;
    int T    = in_sizes[4];

    float *ph, *pqkv;
    __half *pxh,*pxl,*phh,*phl,*poh,*pol,*pfh,*pfl,*pmh,*pml,*pwh,*pwl;
    cudaGetSymbolAddress((void**)&ph,    g_h);
    cudaGetSymbolAddress((void**)&pqkv,  g_qkv);
    cudaGetSymbolAddress((void**)&pxh, g_xh); cudaGetSymbolAddress((void**)&pxl, g_xl);
    cudaGetSymbolAddress((void**)&phh, g_hh); cudaGetSymbolAddress((void**)&phl, g_hl);
    cudaGetSymbolAddress((void**)&poh, g_oh); cudaGetSymbolAddress((void**)&pol, g_ol);
    cudaGetSymbolAddress((void**)&pfh, g_fh); cudaGetSymbolAddress((void**)&pfl, g_fl);
    cudaGetSymbolAddress((void**)&pmh, g_mh); cudaGetSymbolAddress((void**)&pml, g_ml);
    cudaGetSymbolAddress((void**)&pwh, g_wh); cudaGetSymbolAddress((void**)&pwl, g_wl);

    cudaFuncSetAttribute(gemm_tc2, cudaFuncAttributeMaxDynamicSharedMemorySize, 2*ST2_B);
    cudaFuncSetAttribute(gemm_ln,  cudaFuncAttributeMaxDynamicSharedMemorySize, FTOT2);

    const long long off_fp   = 0;
    const long long off_qkv0 = off_fp   + 24576;
    const long long off_qkv1 = off_qkv0 + 196608;
    const long long off_ao0  = off_qkv1 + 196608;
    const long long off_ao1  = off_ao0  + 65536;
    const long long off_ff10 = off_ao1  + 65536;
    const long long off_ff11 = off_ff10 + 131072;
    const long long off_ff20 = off_ff11 + 131072;
    const long long off_ff21 = off_ff20 + 131072;
    const long long off_out  = off_ff21 + 131072;

    WTab tab;
    tab.src[0]=fp_w;            tab.off[0]=off_fp;   tab.kd[0]=96;  tab.nout[0]=256;
    tab.src[1]=qkv_w;           tab.off[1]=off_qkv0; tab.kd[1]=256; tab.nout[1]=768;
    tab.src[2]=qkv_w+256*768;   tab.off[2]=off_qkv1; tab.kd[2]=256; tab.nout[2]=768;
    tab.src[3]=ao_w;            tab.off[3]=off_ao0;  tab.kd[3]=256; tab.nout[3]=256;
    tab.src[4]=ao_w+256*256;    tab.off[4]=off_ao1;  tab.kd[4]=256; tab.nout[4]=256;
    tab.src[5]=ff1_w;           tab.off[5]=off_ff10; tab.kd[5]=256; tab.nout[5]=512;
    tab.src[6]=ff1_w+256*512;   tab.off[6]=off_ff11; tab.kd[6]=256; tab.nout[6]=512;
    tab.src[7]=ff2_w;           tab.off[7]=off_ff20; tab.kd[7]=512; tab.nout[7]=256;
    tab.src[8]=ff2_w+512*256;   tab.off[8]=off_ff21; tab.kd[8]=512; tab.nout[8]=256;
    tab.src[9]=out_w;           tab.off[9]=off_out;  tab.kd[9]=256; tab.nout[9]=64;
    wconv_all<<<dim3(768, 10), 256>>>(tab, pwh, pwl);

    setup_kernel<<<1, 32>>>(poses, intr, time_ids, T);
    proj_topk_kernel<<<(M + 127)/128, 128>>>(xyz, M);
    gather_kernel<<<(Ntok*32 + 255)/256, 256>>>(feat, view_emb, pos_w, pos_b, Ntok);

    auto gemm = [&](const __half* Ahp, const __half* Amp, long long woff,
                    const float* bias, float* C, __half* Ch, __half* Cm,
                    int N, int Kd, int Nout, int mode) {
        dim3 grid((Nout + 127)/128, (N + 127)/128);
        gemm_tc2<<<grid, 256, 2*ST2_B>>>(Ahp, Amp, pwh + woff, pwl + woff,
                                         bias, C, Ch, Cm, N, Kd, Nout, mode);
    };

    // fp: xin -> h (fp32 + halves)
    gemm(pxh, pxl, off_fp, fp_b, ph, phh, phl, Ntok, 96, 256, 2|4);

    const long long qoff[2]  = {off_qkv0, off_qkv1};
    const long long aoff[2]  = {off_ao0,  off_ao1};
    const long long f1off[2] = {off_ff10, off_ff11};
    const long long f2off[2] = {off_ff20, off_ff21};
    int gln = (Ntok + 63)/64;
    for (int l = 0; l < 2; l++) {
        gemm(phh, phl, qoff[l], qkv_b + l*768, pqkv, nullptr, nullptr, Ntok, 256, 768, 2);
        attn_kernel<<<M, 256>>>(M);
        gemm_ln<<<gln, 256, FTOT2>>>(poh, pol, pwh + aoff[l], pwl + aoff[l],
                                     ao_b + l*256, ln1_s + l*256, ln1_b + l*256,
                                     ph, phh, phl, Ntok, 256);
        gemm(phh, phl, f1off[l], ff1_b + l*512, nullptr, pfh, pfl, Ntok, 256, 512, 4|1);
        gemm_ln<<<gln, 256, FTOT2>>>(pfh, pfl, pwh + f2off[l], pwl + f2off[l],
                                     ff2_b + l*256, ln2_s + l*256, ln2_b + l*256,
                                     ph, phh, phl, Ntok, 512);
    }

    mean_kernel<<<(M*256 + 255)/256, 256>>>(M);
    gemm(pmh, pml, off_out, out_b, (float*)d_out, nullptr, nullptr, M, 256, 64, 2);
}